// round 4
// baseline (speedup 1.0000x reference)
#include <cuda_runtime.h>
#include <math.h>
#include <stdint.h>

// Problem constants
#define NB    2
#define NT    2048
#define ND    768
#define NH    12
#define NHS   64
#define NFF   3072
#define NHALF 1536
#define NBT   (NB*NT)   // 4096

// ---------------- scratch (device globals; no allocation) ----------------
__device__ float g_h   [NBT * ND];
__device__ float g_qkv [NBT * 3 * ND];
__device__ float g_attn[NBT * ND];
__device__ float g_x1  [NBT * ND];
__device__ float g_u   [NBT * NFF];
__device__ float g_gl  [NBT * NHALF];
__device__ float g_wqkv[ND * 3 * ND];

// ---------------- async copy helpers ----------------
__device__ __forceinline__ void cp_async16(void* smem_dst, const void* gmem_src)
{
    uint32_t d = (uint32_t)__cvta_generic_to_shared(smem_dst);
    asm volatile("cp.async.cg.shared.global [%0], [%1], 16;\n" :: "r"(d), "l"(gmem_src));
}
#define CP_COMMIT() asm volatile("cp.async.commit_group;\n" ::: "memory")
#define CP_WAIT1()  asm volatile("cp.async.wait_group 1;\n" ::: "memory")
#define CP_WAIT0()  asm volatile("cp.async.wait_group 0;\n" ::: "memory")

// ---------------- pack Wq/Wk/Wv (H,D,HS) -> B[768][2304] ----------------
__global__ void pack_wqkv_kernel(const float* __restrict__ Wq,
                                 const float* __restrict__ Wk,
                                 const float* __restrict__ Wv)
{
    int idx = blockIdx.x * blockDim.x + threadIdx.x;
    const int total = ND * 3 * ND;
    if (idx >= total) return;
    int d = idx / (3 * ND);
    int n = idx % (3 * ND);
    int m = n / ND;
    int r = n % ND;
    int h = r / NHS;
    int k = r % NHS;
    const float* W = (m == 0) ? Wq : ((m == 1) ? Wk : Wv);
    g_wqkv[idx] = W[h * ND * NHS + d * NHS + k];
}

// ---------------- RMSNorm ----------------
__device__ __forceinline__ void rms_body(const float* __restrict__ in,
                                         float* __restrict__ out,
                                         const float* __restrict__ g)
{
    int tid = threadIdx.x;
    float v0 = in[tid], v1 = in[tid + 256], v2 = in[tid + 512];
    float ss = v0*v0 + v1*v1 + v2*v2;
    #pragma unroll
    for (int o = 16; o; o >>= 1) ss += __shfl_xor_sync(0xffffffffu, ss, o);
    __shared__ float ws[8];
    __shared__ float s_inv;
    if ((tid & 31) == 0) ws[tid >> 5] = ss;
    __syncthreads();
    if (tid == 0) {
        float t = 0.f;
        #pragma unroll
        for (int i = 0; i < 8; i++) t += ws[i];
        float rms = sqrtf(t * (1.0f / (float)ND));
        s_inv = 1.0f / (rms + 1e-8f);
    }
    __syncthreads();
    float inv = s_inv;
    out[tid]       = g[tid]       * v0 * inv;
    out[tid + 256] = g[tid + 256] * v1 * inv;
    out[tid + 512] = g[tid + 512] * v2 * inv;
}

__global__ __launch_bounds__(256) void rmsnorm1_kernel(const float* __restrict__ x,
                                                       const float* __restrict__ g)
{
    int row = blockIdx.x;
    rms_body(x + (size_t)row * ND, g_h + (size_t)row * ND, g);
}

__global__ __launch_bounds__(256) void rmsnorm2_kernel(const float* __restrict__ g)
{
    int row = blockIdx.x;
    rms_body(g_x1 + (size_t)row * ND, g_h + (size_t)row * ND, g);
}

// ---------------- TF32 helpers ----------------
__device__ __forceinline__ float tf32r(float x)
{
    uint32_t r;
    asm("cvt.rna.tf32.f32 %0, %1;" : "=r"(r) : "f"(x));
    return __uint_as_float(r);
}

__device__ __forceinline__ uint32_t tf32u(float x)
{
    uint32_t r;
    asm("cvt.rna.tf32.f32 %0, %1;" : "=r"(r) : "f"(x));
    return r;
}

__device__ __forceinline__ void mma_tf32(float* c, const uint32_t* a, const uint32_t* b)
{
    asm volatile(
        "mma.sync.aligned.m16n8k8.row.col.f32.tf32.tf32.f32 "
        "{%0,%1,%2,%3}, {%4,%5,%6,%7}, {%8,%9}, {%0,%1,%2,%3};\n"
        : "+f"(c[0]), "+f"(c[1]), "+f"(c[2]), "+f"(c[3])
        : "r"(a[0]), "r"(a[1]), "r"(a[2]), "r"(a[3]), "r"(b[0]), "r"(b[1]));
}

// ---------------- TF32 GEMM: 128x128x32, 2-stage cp.async pipeline -------
// Dynamic smem: As[2][128][36] + Bs[2][32][136] = 71680 bytes.
#define AS_STR 36
#define BS_STR 136
#define AS_STAGE (128 * AS_STR)
#define BS_STAGE (32 * BS_STR)
#define GEMM_SMEM ((2 * AS_STAGE + 2 * BS_STAGE) * (int)sizeof(float))

template<int N, int K, bool BIAS, bool RES>
__device__ __forceinline__ void mma_gemm_body(const float* __restrict__ A,
                                              const float* __restrict__ Bm,
                                              float* __restrict__ C,
                                              const float* __restrict__ bias,
                                              const float* __restrict__ res)
{
    extern __shared__ float smg[];
    float* As = smg;                    // [2][128][36]
    float* Bs = smg + 2 * AS_STAGE;     // [2][32][136]

    const int tid  = threadIdx.x;
    const int warp = tid >> 5, lane = tid & 31;
    const int wm = (warp >> 1) * 32;
    const int wn = (warp & 1) * 64;
    const int bm = blockIdx.y * 128;
    const int bn = blockIdx.x * 128;

    const int lrow = tid >> 3;          // 0..31
    const int lcol = (tid & 7) * 4;     // 0..28

    float acc[2][8][4];
    #pragma unroll
    for (int i = 0; i < 2; i++)
        #pragma unroll
        for (int j = 0; j < 8; j++)
            #pragma unroll
            for (int t = 0; t < 4; t++) acc[i][j][t] = 0.f;

    const int NCH = K / 32;

    // issue stage 0
    {
        float* as = As;
        float* bs = Bs;
        #pragma unroll
        for (int r = 0; r < 4; r++) {
            int row = lrow + 32 * r;
            cp_async16(&as[row * AS_STR + lcol], A + (size_t)(bm + row) * K + lcol);
        }
        #pragma unroll
        for (int c = 0; c < 4; c++) {
            int col = lcol + 32 * c;
            cp_async16(&bs[lrow * BS_STR + col], Bm + (size_t)lrow * N + bn + col);
        }
        CP_COMMIT();
    }

    #pragma unroll 1
    for (int chunk = 0; chunk < NCH; chunk++) {
        const int cur = chunk & 1;
        if (chunk + 1 < NCH) {
            const int nxt = cur ^ 1;
            const int k0 = (chunk + 1) * 32;
            float* as = As + nxt * AS_STAGE;
            float* bs = Bs + nxt * BS_STAGE;
            #pragma unroll
            for (int r = 0; r < 4; r++) {
                int row = lrow + 32 * r;
                cp_async16(&as[row * AS_STR + lcol], A + (size_t)(bm + row) * K + k0 + lcol);
            }
            #pragma unroll
            for (int c = 0; c < 4; c++) {
                int col = lcol + 32 * c;
                cp_async16(&bs[lrow * BS_STR + col], Bm + (size_t)(k0 + lrow) * N + bn + col);
            }
            CP_COMMIT();
            CP_WAIT1();
        } else {
            CP_WAIT0();
        }
        __syncthreads();

        const float* as = As + cur * AS_STAGE;
        const float* bs = Bs + cur * BS_STAGE;

        #pragma unroll
        for (int kk = 0; kk < 32; kk += 8) {
            uint32_t aF[2][4], bF[8][2];
            #pragma unroll
            for (int mt = 0; mt < 2; mt++) {
                int r = wm + mt * 16 + (lane >> 2);
                int c = kk + (lane & 3);
                aF[mt][0] = tf32u(as[r * AS_STR + c]);
                aF[mt][1] = tf32u(as[(r + 8) * AS_STR + c]);
                aF[mt][2] = tf32u(as[r * AS_STR + c + 4]);
                aF[mt][3] = tf32u(as[(r + 8) * AS_STR + c + 4]);
            }
            #pragma unroll
            for (int nt = 0; nt < 8; nt++) {
                int rr = kk + (lane & 3);
                int cc = wn + nt * 8 + (lane >> 2);
                bF[nt][0] = tf32u(bs[rr * BS_STR + cc]);
                bF[nt][1] = tf32u(bs[(rr + 4) * BS_STR + cc]);
            }
            #pragma unroll
            for (int mt = 0; mt < 2; mt++)
                #pragma unroll
                for (int nt = 0; nt < 8; nt++)
                    mma_tf32(acc[mt][nt], aF[mt], bF[nt]);
        }
        __syncthreads();
    }

    #pragma unroll
    for (int mt = 0; mt < 2; mt++) {
        #pragma unroll
        for (int nt = 0; nt < 8; nt++) {
            int row0 = bm + wm + mt * 16 + (lane >> 2);
            int col  = bn + wn + nt * 8 + (lane & 3) * 2;
            float2 v0 = make_float2(acc[mt][nt][0], acc[mt][nt][1]);
            float2 v1 = make_float2(acc[mt][nt][2], acc[mt][nt][3]);
            if constexpr (BIAS) {
                float2 bb = *(const float2*)(bias + col);
                v0.x += bb.x; v0.y += bb.y;
                v1.x += bb.x; v1.y += bb.y;
            }
            if constexpr (RES) {
                float2 r0 = *(const float2*)(res + (size_t)row0 * N + col);
                float2 r1 = *(const float2*)(res + (size_t)(row0 + 8) * N + col);
                v0.x += r0.x; v0.y += r0.y;
                v1.x += r1.x; v1.y += r1.y;
            }
            *(float2*)(C + (size_t)row0 * N + col)       = v0;
            *(float2*)(C + (size_t)(row0 + 8) * N + col) = v1;
        }
    }
}

__global__ __launch_bounds__(256) void gemm_qkv_kernel()
{
    mma_gemm_body<3 * ND, ND, false, false>(g_h, g_wqkv, g_qkv, nullptr, nullptr);
}
__global__ __launch_bounds__(256) void gemm_o_kernel(const float* __restrict__ Wo,
                                                     const float* __restrict__ bo,
                                                     const float* __restrict__ x)
{
    mma_gemm_body<ND, ND, true, true>(g_attn, Wo, g_x1, bo, x);
}
__global__ __launch_bounds__(256) void gemm_ffn1_kernel(const float* __restrict__ W1,
                                                        const float* __restrict__ b1)
{
    mma_gemm_body<NFF, ND, true, false>(g_h, W1, g_u, b1, nullptr);
}
__global__ __launch_bounds__(256) void gemm_ffn2_kernel(const float* __restrict__ W2,
                                                        const float* __restrict__ b2,
                                                        float* __restrict__ out)
{
    mma_gemm_body<ND, NHALF, true, true>(g_gl, W2, out, b2, g_x1);
}

// ---------------- Flash attention with tf32 MMA + register prefetch -------
#define QS_STR 68
#define KS_STR 68
#define VS_STR 72
#define PS_STR 68

__global__ __launch_bounds__(256) void attn_mma_kernel()
{
    extern __shared__ float sm[];
    float* Qs = sm;                      // [128][68]
    float* Ks = Qs + 128 * QS_STR;       // [64][68]
    float* Vs = Ks + 64 * KS_STR;        // [64][72]
    float* Ps = Vs + 64 * VS_STR;        // [128][68]

    const int tid  = threadIdx.x;
    const int warp = tid >> 5, lane = tid & 31;
    const int qb = (int)gridDim.x - 1 - (int)blockIdx.x;   // heavy blocks first
    const int h  = blockIdx.y;
    const int b  = blockIdx.z;
    const int row0 = qb * 128;
    const int wrow = warp * 16;

    const int lr = tid >> 4;            // 0..15
    const int lc = (tid & 15) * 4;      // 0..60

    // Load Q tile: 128 rows x 64 cols (tf32-rounded)
    #pragma unroll
    for (int r = 0; r < 8; r++) {
        int row = lr + 16 * r;
        float4 v = *(const float4*)&g_qkv[(size_t)(b * NT + row0 + row) * (3 * ND)
                                          + h * NHS + lc];
        float4 t = make_float4(tf32r(v.x), tf32r(v.y), tf32r(v.z), tf32r(v.w));
        *(float4*)&Qs[row * QS_STR + lc] = t;
    }

    float oacc[8][4];
    #pragma unroll
    for (int nt = 0; nt < 8; nt++)
        #pragma unroll
        for (int t = 0; t < 4; t++) oacc[nt][t] = 0.f;

    float m0 = -1e30f, m1 = -1e30f, l0 = 0.f, l1 = 0.f;
    const float scale = 0.03608439182435161f;   // 768^-0.5

    const int grow0 = row0 + wrow + (lane >> 2);
    const int grow1 = grow0 + 8;
    const int jb_max = 2 * qb + 1;

    // Prefetch K/V tile 0 into registers
    float4 kpre[4], vpre[4];
    #pragma unroll
    for (int r = 0; r < 4; r++) {
        int row = lr + 16 * r;
        size_t base = (size_t)(b * NT + row) * (3 * ND) + h * NHS + lc;
        kpre[r] = *(const float4*)&g_qkv[ND + base];
        vpre[r] = *(const float4*)&g_qkv[2 * ND + base];
    }

    for (int jb = 0; jb <= jb_max; jb++) {
        __syncthreads();   // all warps done reading previous K/V
        // Commit prefetched tile to smem (tf32-rounded)
        #pragma unroll
        for (int r = 0; r < 4; r++) {
            int row = lr + 16 * r;
            float4 kt = make_float4(tf32r(kpre[r].x), tf32r(kpre[r].y),
                                    tf32r(kpre[r].z), tf32r(kpre[r].w));
            float4 vt = make_float4(tf32r(vpre[r].x), tf32r(vpre[r].y),
                                    tf32r(vpre[r].z), tf32r(vpre[r].w));
            *(float4*)&Ks[row * KS_STR + lc] = kt;
            *(float4*)&Vs[row * VS_STR + lc] = vt;
        }
        __syncthreads();

        // Issue prefetch for next tile (overlaps with MMA + softmax below)
        if (jb < jb_max) {
            #pragma unroll
            for (int r = 0; r < 4; r++) {
                int row = lr + 16 * r;
                size_t base = (size_t)(b * NT + (jb + 1) * 64 + row) * (3 * ND)
                              + h * NHS + lc;
                kpre[r] = *(const float4*)&g_qkv[ND + base];
                vpre[r] = *(const float4*)&g_qkv[2 * ND + base];
            }
        }

        // S = Q K^T (16x64 per warp, in C fragments)
        float sacc[8][4];
        #pragma unroll
        for (int nt = 0; nt < 8; nt++)
            #pragma unroll
            for (int t = 0; t < 4; t++) sacc[nt][t] = 0.f;

        #pragma unroll
        for (int kk = 0; kk < 64; kk += 8) {
            uint32_t aF[4];
            {
                int r = wrow + (lane >> 2);
                int c = kk + (lane & 3);
                aF[0] = __float_as_uint(Qs[r * QS_STR + c]);
                aF[1] = __float_as_uint(Qs[(r + 8) * QS_STR + c]);
                aF[2] = __float_as_uint(Qs[r * QS_STR + c + 4]);
                aF[3] = __float_as_uint(Qs[(r + 8) * QS_STR + c + 4]);
            }
            #pragma unroll
            for (int nt = 0; nt < 8; nt++) {
                uint32_t bF[2];
                int n = nt * 8 + (lane >> 2);
                int c = kk + (lane & 3);
                bF[0] = __float_as_uint(Ks[n * KS_STR + c]);
                bF[1] = __float_as_uint(Ks[n * KS_STR + c + 4]);
                mma_tf32(sacc[nt], aF, bF);
            }
        }

        // Scale + causal mask
        #pragma unroll
        for (int nt = 0; nt < 8; nt++) {
            int gcol = jb * 64 + nt * 8 + (lane & 3) * 2;
            float v0 = sacc[nt][0] * scale;
            float v1 = sacc[nt][1] * scale;
            float v2 = sacc[nt][2] * scale;
            float v3 = sacc[nt][3] * scale;
            if (gcol     > grow0) v0 = -1e30f;
            if (gcol + 1 > grow0) v1 = -1e30f;
            if (gcol     > grow1) v2 = -1e30f;
            if (gcol + 1 > grow1) v3 = -1e30f;
            sacc[nt][0] = v0; sacc[nt][1] = v1;
            sacc[nt][2] = v2; sacc[nt][3] = v3;
        }

        // Row max (quad reduce)
        float mx0 = -1e30f, mx1 = -1e30f;
        #pragma unroll
        for (int nt = 0; nt < 8; nt++) {
            mx0 = fmaxf(mx0, fmaxf(sacc[nt][0], sacc[nt][1]));
            mx1 = fmaxf(mx1, fmaxf(sacc[nt][2], sacc[nt][3]));
        }
        mx0 = fmaxf(mx0, __shfl_xor_sync(0xffffffffu, mx0, 1));
        mx0 = fmaxf(mx0, __shfl_xor_sync(0xffffffffu, mx0, 2));
        mx1 = fmaxf(mx1, __shfl_xor_sync(0xffffffffu, mx1, 1));
        mx1 = fmaxf(mx1, __shfl_xor_sync(0xffffffffu, mx1, 2));

        float mn0 = fmaxf(m0, mx0);
        float mn1 = fmaxf(m1, mx1);

        // Exponentiate + row sum
        float s0 = 0.f, s1 = 0.f;
        #pragma unroll
        for (int nt = 0; nt < 8; nt++) {
            float p0 = __expf(sacc[nt][0] - mn0);
            float p1 = __expf(sacc[nt][1] - mn0);
            float p2 = __expf(sacc[nt][2] - mn1);
            float p3 = __expf(sacc[nt][3] - mn1);
            sacc[nt][0] = p0; sacc[nt][1] = p1;
            sacc[nt][2] = p2; sacc[nt][3] = p3;
            s0 += p0 + p1;
            s1 += p2 + p3;
        }
        s0 += __shfl_xor_sync(0xffffffffu, s0, 1);
        s0 += __shfl_xor_sync(0xffffffffu, s0, 2);
        s1 += __shfl_xor_sync(0xffffffffu, s1, 1);
        s1 += __shfl_xor_sync(0xffffffffu, s1, 2);

        float al0 = __expf(m0 - mn0);
        float al1 = __expf(m1 - mn1);
        l0 = l0 * al0 + s0;
        l1 = l1 * al1 + s1;
        m0 = mn0; m1 = mn1;

        // Rescale O
        #pragma unroll
        for (int nt = 0; nt < 8; nt++) {
            oacc[nt][0] *= al0; oacc[nt][1] *= al0;
            oacc[nt][2] *= al1; oacc[nt][3] *= al1;
        }

        // Write P to smem (warp-local round trip)
        {
            int r = wrow + (lane >> 2);
            #pragma unroll
            for (int nt = 0; nt < 8; nt++) {
                int c = nt * 8 + (lane & 3) * 2;
                *(float2*)&Ps[r * PS_STR + c]       = make_float2(sacc[nt][0], sacc[nt][1]);
                *(float2*)&Ps[(r + 8) * PS_STR + c] = make_float2(sacc[nt][2], sacc[nt][3]);
            }
        }
        __syncwarp();

        // O += P @ V
        #pragma unroll
        for (int kk = 0; kk < 64; kk += 8) {
            uint32_t aF[4];
            {
                int r = wrow + (lane >> 2);
                int c = kk + (lane & 3);
                aF[0] = __float_as_uint(Ps[r * PS_STR + c]);
                aF[1] = __float_as_uint(Ps[(r + 8) * PS_STR + c]);
                aF[2] = __float_as_uint(Ps[r * PS_STR + c + 4]);
                aF[3] = __float_as_uint(Ps[(r + 8) * PS_STR + c + 4]);
            }
            #pragma unroll
            for (int nt = 0; nt < 8; nt++) {
                uint32_t bF[2];
                int s = kk + (lane & 3);
                int n = nt * 8 + (lane >> 2);
                bF[0] = __float_as_uint(Vs[s * VS_STR + n]);
                bF[1] = __float_as_uint(Vs[(s + 4) * VS_STR + n]);
                mma_tf32(oacc[nt], aF, bF);
            }
        }
    }

    // Normalize and store
    float li0 = 1.0f / l0, li1 = 1.0f / l1;
    {
        int r_g0 = b * NT + grow0;
        int r_g1 = b * NT + grow1;
        #pragma unroll
        for (int nt = 0; nt < 8; nt++) {
            int c = h * NHS + nt * 8 + (lane & 3) * 2;
            *(float2*)&g_attn[(size_t)r_g0 * ND + c] =
                make_float2(oacc[nt][0] * li0, oacc[nt][1] * li0);
            *(float2*)&g_attn[(size_t)r_g1 * ND + c] =
                make_float2(oacc[nt][2] * li1, oacc[nt][3] * li1);
        }
    }
}

// ---------------- SwiGLU elementwise ----------------
__global__ void swiglu_kernel()
{
    int idx = blockIdx.x * blockDim.x + threadIdx.x;
    if (idx >= NBT * NHALF) return;
    int row = idx / NHALF;
    int c   = idx % NHALF;
    float a = g_u[(size_t)row * NFF + c];
    float z = g_u[(size_t)row * NFF + NHALF + c];
    float sg = z / (1.0f + __expf(-z));
    g_gl[idx] = sg * a;
}

// ---------------- launch ----------------
extern "C" void kernel_launch(void* const* d_in, const int* in_sizes, int n_in,
                              void* d_out, int out_size)
{
    const float* x  = (const float*)d_in[0];
    const float* Wq = (const float*)d_in[1];
    const float* Wk = (const float*)d_in[2];
    const float* Wv = (const float*)d_in[3];
    const float* Wo = (const float*)d_in[4];
    const float* bo = (const float*)d_in[5];
    const float* W1 = (const float*)d_in[6];
    const float* b1 = (const float*)d_in[7];
    const float* W2 = (const float*)d_in[8];
    const float* b2 = (const float*)d_in[9];
    const float* g1 = (const float*)d_in[10];
    const float* g2 = (const float*)d_in[11];
    float* out = (float*)d_out;

    const int ASMEM = (128 * QS_STR + 64 * KS_STR + 64 * VS_STR + 128 * PS_STR)
                      * (int)sizeof(float);   // 105472 B
    cudaFuncSetAttribute(attn_mma_kernel, cudaFuncAttributeMaxDynamicSharedMemorySize, ASMEM);
    cudaFuncSetAttribute(gemm_qkv_kernel,  cudaFuncAttributeMaxDynamicSharedMemorySize, GEMM_SMEM);
    cudaFuncSetAttribute(gemm_o_kernel,    cudaFuncAttributeMaxDynamicSharedMemorySize, GEMM_SMEM);
    cudaFuncSetAttribute(gemm_ffn1_kernel, cudaFuncAttributeMaxDynamicSharedMemorySize, GEMM_SMEM);
    cudaFuncSetAttribute(gemm_ffn2_kernel, cudaFuncAttributeMaxDynamicSharedMemorySize, GEMM_SMEM);

    pack_wqkv_kernel<<<(ND * 3 * ND + 255) / 256, 256>>>(Wq, Wk, Wv);
    rmsnorm1_kernel<<<NBT, 256>>>(x, g1);
    gemm_qkv_kernel<<<dim3(3 * ND / 128, NBT / 128), 256, GEMM_SMEM>>>();
    attn_mma_kernel<<<dim3(NT / 128, NH, NB), 256, ASMEM>>>();
    gemm_o_kernel<<<dim3(ND / 128, NBT / 128), 256, GEMM_SMEM>>>(Wo, bo, x);
    rmsnorm2_kernel<<<NBT, 256>>>(g2);
    gemm_ffn1_kernel<<<dim3(NFF / 128, NBT / 128), 256, GEMM_SMEM>>>(W1, b1);
    swiglu_kernel<<<(NBT * NHALF + 255) / 256, 256>>>();
    gemm_ffn2_kernel<<<dim3(ND / 128, NBT / 128), 256, GEMM_SMEM>>>(W2, b2, out);
}

// round 5
// speedup vs baseline: 1.0735x; 1.0735x over previous
#include <cuda_runtime.h>
#include <math.h>
#include <stdint.h>

// Problem constants
#define NB    2
#define NT    2048
#define ND    768
#define NH    12
#define NHS   64
#define NFF   3072
#define NHALF 1536
#define NBT   (NB*NT)   // 4096

// ---------------- scratch (device globals; no allocation) ----------------
__device__ float g_h   [NBT * ND];
__device__ float g_qkv [NBT * 3 * ND];
__device__ float g_attn[NBT * ND];
__device__ float g_x1  [NBT * ND];
__device__ float g_u   [NBT * NFF];
__device__ float g_gl  [NBT * NHALF];
__device__ float g_wqkv[ND * 3 * ND];
__device__ float g_wo_r[ND * ND];
__device__ float g_w1_r[ND * NFF];
__device__ float g_w2_r[NHALF * ND];

// ---------------- async copy helpers ----------------
__device__ __forceinline__ void cp_async16(void* smem_dst, const void* gmem_src)
{
    uint32_t d = (uint32_t)__cvta_generic_to_shared(smem_dst);
    asm volatile("cp.async.cg.shared.global [%0], [%1], 16;\n" :: "r"(d), "l"(gmem_src));
}
#define CP_COMMIT() asm volatile("cp.async.commit_group;\n" ::: "memory")
#define CP_WAIT1()  asm volatile("cp.async.wait_group 1;\n" ::: "memory")
#define CP_WAIT0()  asm volatile("cp.async.wait_group 0;\n" ::: "memory")

// ---------------- TF32 helpers ----------------
__device__ __forceinline__ float tf32r(float x)
{
    uint32_t r;
    asm("cvt.rna.tf32.f32 %0, %1;" : "=r"(r) : "f"(x));
    return __uint_as_float(r);
}

__device__ __forceinline__ void mma_tf32(float* c, const uint32_t* a, const uint32_t* b)
{
    asm volatile(
        "mma.sync.aligned.m16n8k8.row.col.f32.tf32.tf32.f32 "
        "{%0,%1,%2,%3}, {%4,%5,%6,%7}, {%8,%9}, {%0,%1,%2,%3};\n"
        : "+f"(c[0]), "+f"(c[1]), "+f"(c[2]), "+f"(c[3])
        : "r"(a[0]), "r"(a[1]), "r"(a[2]), "r"(a[3]), "r"(b[0]), "r"(b[1]));
}

// ---------------- pack Wq/Wk/Wv (H,D,HS) -> B[768][2304], tf32-rounded ----
__global__ void pack_wqkv_kernel(const float* __restrict__ Wq,
                                 const float* __restrict__ Wk,
                                 const float* __restrict__ Wv)
{
    int idx = blockIdx.x * blockDim.x + threadIdx.x;
    const int total = ND * 3 * ND;
    if (idx >= total) return;
    int d = idx / (3 * ND);
    int n = idx % (3 * ND);
    int m = n / ND;
    int r = n % ND;
    int h = r / NHS;
    int k = r % NHS;
    const float* W = (m == 0) ? Wq : ((m == 1) ? Wk : Wv);
    g_wqkv[idx] = tf32r(W[h * ND * NHS + d * NHS + k]);
}

// ---------------- round Wo/W1/W2 into tf32 copies ----------------
#define WO_N (ND * ND)
#define W1_N (ND * NFF)
#define W2_N (NHALF * ND)
__global__ void round_weights_kernel(const float* __restrict__ Wo,
                                     const float* __restrict__ W1,
                                     const float* __restrict__ W2)
{
    int idx = blockIdx.x * blockDim.x + threadIdx.x;
    if (idx < WO_N) g_wo_r[idx] = tf32r(Wo[idx]);
    if (idx < W1_N) g_w1_r[idx] = tf32r(W1[idx]);
    if (idx < W2_N) g_w2_r[idx] = tf32r(W2[idx]);
}

// ---------------- RMSNorm (tf32-rounded output) ----------------
__device__ __forceinline__ void rms_body(const float* __restrict__ in,
                                         float* __restrict__ out,
                                         const float* __restrict__ g)
{
    int tid = threadIdx.x;
    float v0 = in[tid], v1 = in[tid + 256], v2 = in[tid + 512];
    float ss = v0*v0 + v1*v1 + v2*v2;
    #pragma unroll
    for (int o = 16; o; o >>= 1) ss += __shfl_xor_sync(0xffffffffu, ss, o);
    __shared__ float ws[8];
    __shared__ float s_inv;
    if ((tid & 31) == 0) ws[tid >> 5] = ss;
    __syncthreads();
    if (tid == 0) {
        float t = 0.f;
        #pragma unroll
        for (int i = 0; i < 8; i++) t += ws[i];
        float rms = sqrtf(t * (1.0f / (float)ND));
        s_inv = 1.0f / (rms + 1e-8f);
    }
    __syncthreads();
    float inv = s_inv;
    out[tid]       = tf32r(g[tid]       * v0 * inv);
    out[tid + 256] = tf32r(g[tid + 256] * v1 * inv);
    out[tid + 512] = tf32r(g[tid + 512] * v2 * inv);
}

__global__ __launch_bounds__(256) void rmsnorm1_kernel(const float* __restrict__ x,
                                                       const float* __restrict__ g)
{
    int row = blockIdx.x;
    rms_body(x + (size_t)row * ND, g_h + (size_t)row * ND, g);
}

__global__ __launch_bounds__(256) void rmsnorm2_kernel(const float* __restrict__ g)
{
    int row = blockIdx.x;
    rms_body(g_x1 + (size_t)row * ND, g_h + (size_t)row * ND, g);
}

// ---------------- TF32 GEMM: 128x128x32, 2-stage cp.async pipeline -------
// Operands are pre-rounded to tf32 by their producers: mainloop = LDS + HMMA only.
#define AS_STR 36
#define BS_STR 136
#define AS_STAGE (128 * AS_STR)
#define BS_STAGE (32 * BS_STR)
#define GEMM_SMEM ((2 * AS_STAGE + 2 * BS_STAGE) * (int)sizeof(float))

template<int N, int K, bool BIAS, bool RES, bool ROUND>
__device__ __forceinline__ void mma_gemm_body(const float* __restrict__ A,
                                              const float* __restrict__ Bm,
                                              float* __restrict__ C,
                                              const float* __restrict__ bias,
                                              const float* __restrict__ res)
{
    extern __shared__ float smg[];
    float* As = smg;                    // [2][128][36]
    float* Bs = smg + 2 * AS_STAGE;     // [2][32][136]

    const int tid  = threadIdx.x;
    const int warp = tid >> 5, lane = tid & 31;
    const int wm = (warp >> 1) * 32;
    const int wn = (warp & 1) * 64;
    const int bm = blockIdx.y * 128;
    const int bn = blockIdx.x * 128;

    const int lrow = tid >> 3;          // 0..31
    const int lcol = (tid & 7) * 4;     // 0..28

    float acc[2][8][4];
    #pragma unroll
    for (int i = 0; i < 2; i++)
        #pragma unroll
        for (int j = 0; j < 8; j++)
            #pragma unroll
            for (int t = 0; t < 4; t++) acc[i][j][t] = 0.f;

    const int NCH = K / 32;

    // issue stage 0
    {
        float* as = As;
        float* bs = Bs;
        #pragma unroll
        for (int r = 0; r < 4; r++) {
            int row = lrow + 32 * r;
            cp_async16(&as[row * AS_STR + lcol], A + (size_t)(bm + row) * K + lcol);
        }
        #pragma unroll
        for (int c = 0; c < 4; c++) {
            int col = lcol + 32 * c;
            cp_async16(&bs[lrow * BS_STR + col], Bm + (size_t)lrow * N + bn + col);
        }
        CP_COMMIT();
    }

    #pragma unroll 1
    for (int chunk = 0; chunk < NCH; chunk++) {
        const int cur = chunk & 1;
        if (chunk + 1 < NCH) {
            const int nxt = cur ^ 1;
            const int k0 = (chunk + 1) * 32;
            float* as = As + nxt * AS_STAGE;
            float* bs = Bs + nxt * BS_STAGE;
            #pragma unroll
            for (int r = 0; r < 4; r++) {
                int row = lrow + 32 * r;
                cp_async16(&as[row * AS_STR + lcol], A + (size_t)(bm + row) * K + k0 + lcol);
            }
            #pragma unroll
            for (int c = 0; c < 4; c++) {
                int col = lcol + 32 * c;
                cp_async16(&bs[lrow * BS_STR + col], Bm + (size_t)(k0 + lrow) * N + bn + col);
            }
            CP_COMMIT();
            CP_WAIT1();
        } else {
            CP_WAIT0();
        }
        __syncthreads();

        const float* as = As + cur * AS_STAGE;
        const float* bs = Bs + cur * BS_STAGE;

        #pragma unroll
        for (int kk = 0; kk < 32; kk += 8) {
            uint32_t aF[2][4], bF[8][2];
            #pragma unroll
            for (int mt = 0; mt < 2; mt++) {
                int r = wm + mt * 16 + (lane >> 2);
                int c = kk + (lane & 3);
                aF[mt][0] = __float_as_uint(as[r * AS_STR + c]);
                aF[mt][1] = __float_as_uint(as[(r + 8) * AS_STR + c]);
                aF[mt][2] = __float_as_uint(as[r * AS_STR + c + 4]);
                aF[mt][3] = __float_as_uint(as[(r + 8) * AS_STR + c + 4]);
            }
            #pragma unroll
            for (int nt = 0; nt < 8; nt++) {
                int rr = kk + (lane & 3);
                int cc = wn + nt * 8 + (lane >> 2);
                bF[nt][0] = __float_as_uint(bs[rr * BS_STR + cc]);
                bF[nt][1] = __float_as_uint(bs[(rr + 4) * BS_STR + cc]);
            }
            #pragma unroll
            for (int mt = 0; mt < 2; mt++)
                #pragma unroll
                for (int nt = 0; nt < 8; nt++)
                    mma_tf32(acc[mt][nt], aF[mt], bF[nt]);
        }
        __syncthreads();
    }

    #pragma unroll
    for (int mt = 0; mt < 2; mt++) {
        #pragma unroll
        for (int nt = 0; nt < 8; nt++) {
            int row0 = bm + wm + mt * 16 + (lane >> 2);
            int col  = bn + wn + nt * 8 + (lane & 3) * 2;
            float2 v0 = make_float2(acc[mt][nt][0], acc[mt][nt][1]);
            float2 v1 = make_float2(acc[mt][nt][2], acc[mt][nt][3]);
            if constexpr (BIAS) {
                float2 bb = *(const float2*)(bias + col);
                v0.x += bb.x; v0.y += bb.y;
                v1.x += bb.x; v1.y += bb.y;
            }
            if constexpr (RES) {
                float2 r0 = *(const float2*)(res + (size_t)row0 * N + col);
                float2 r1 = *(const float2*)(res + (size_t)(row0 + 8) * N + col);
                v0.x += r0.x; v0.y += r0.y;
                v1.x += r1.x; v1.y += r1.y;
            }
            if constexpr (ROUND) {
                v0.x = tf32r(v0.x); v0.y = tf32r(v0.y);
                v1.x = tf32r(v1.x); v1.y = tf32r(v1.y);
            }
            *(float2*)(C + (size_t)row0 * N + col)       = v0;
            *(float2*)(C + (size_t)(row0 + 8) * N + col) = v1;
        }
    }
}

__global__ __launch_bounds__(256) void gemm_qkv_kernel()
{
    // output rounded: feeds attention MMAs directly
    mma_gemm_body<3 * ND, ND, false, false, true>(g_h, g_wqkv, g_qkv, nullptr, nullptr);
}
__global__ __launch_bounds__(256) void gemm_o_kernel(const float* __restrict__ bo,
                                                     const float* __restrict__ x)
{
    mma_gemm_body<ND, ND, true, true, false>(g_attn, g_wo_r, g_x1, bo, x);
}
__global__ __launch_bounds__(256) void gemm_ffn1_kernel(const float* __restrict__ b1)
{
    mma_gemm_body<NFF, ND, true, false, false>(g_h, g_w1_r, g_u, b1, nullptr);
}
__global__ __launch_bounds__(256) void gemm_ffn2_kernel(const float* __restrict__ b2,
                                                        float* __restrict__ out)
{
    mma_gemm_body<ND, NHALF, true, true, false>(g_gl, g_w2_r, out, b2, g_x1);
}

// ---------------- Flash attention with tf32 MMA + register prefetch -------
// g_qkv is pre-rounded to tf32 by gemm_qkv -> no conversions here.
#define QS_STR 68
#define KS_STR 68
#define VS_STR 72
#define PS_STR 68

__global__ __launch_bounds__(256) void attn_mma_kernel()
{
    extern __shared__ float sm[];
    float* Qs = sm;                      // [128][68]
    float* Ks = Qs + 128 * QS_STR;       // [64][68]
    float* Vs = Ks + 64 * KS_STR;        // [64][72]
    float* Ps = Vs + 64 * VS_STR;        // [128][68]

    const int tid  = threadIdx.x;
    const int warp = tid >> 5, lane = tid & 31;
    const int qb = (int)gridDim.x - 1 - (int)blockIdx.x;   // heavy blocks first
    const int h  = blockIdx.y;
    const int b  = blockIdx.z;
    const int row0 = qb * 128;
    const int wrow = warp * 16;

    const int lr = tid >> 4;            // 0..15
    const int lc = (tid & 15) * 4;      // 0..60

    // Load Q tile: 128 rows x 64 cols (already tf32)
    #pragma unroll
    for (int r = 0; r < 8; r++) {
        int row = lr + 16 * r;
        float4 v = *(const float4*)&g_qkv[(size_t)(b * NT + row0 + row) * (3 * ND)
                                          + h * NHS + lc];
        *(float4*)&Qs[row * QS_STR + lc] = v;
    }

    float oacc[8][4];
    #pragma unroll
    for (int nt = 0; nt < 8; nt++)
        #pragma unroll
        for (int t = 0; t < 4; t++) oacc[nt][t] = 0.f;

    float m0 = -1e30f, m1 = -1e30f, l0 = 0.f, l1 = 0.f;
    const float scale = 0.03608439182435161f;   // 768^-0.5

    const int grow0 = row0 + wrow + (lane >> 2);
    const int grow1 = grow0 + 8;
    const int jb_max = 2 * qb + 1;

    // Prefetch K/V tile 0 into registers
    float4 kpre[4], vpre[4];
    #pragma unroll
    for (int r = 0; r < 4; r++) {
        int row = lr + 16 * r;
        size_t base = (size_t)(b * NT + row) * (3 * ND) + h * NHS + lc;
        kpre[r] = *(const float4*)&g_qkv[ND + base];
        vpre[r] = *(const float4*)&g_qkv[2 * ND + base];
    }

    for (int jb = 0; jb <= jb_max; jb++) {
        __syncthreads();   // all warps done reading previous K/V
        #pragma unroll
        for (int r = 0; r < 4; r++) {
            int row = lr + 16 * r;
            *(float4*)&Ks[row * KS_STR + lc] = kpre[r];
            *(float4*)&Vs[row * VS_STR + lc] = vpre[r];
        }
        __syncthreads();

        // Issue prefetch for next tile (overlaps with MMA + softmax below)
        if (jb < jb_max) {
            #pragma unroll
            for (int r = 0; r < 4; r++) {
                int row = lr + 16 * r;
                size_t base = (size_t)(b * NT + (jb + 1) * 64 + row) * (3 * ND)
                              + h * NHS + lc;
                kpre[r] = *(const float4*)&g_qkv[ND + base];
                vpre[r] = *(const float4*)&g_qkv[2 * ND + base];
            }
        }

        // S = Q K^T (16x64 per warp, in C fragments)
        float sacc[8][4];
        #pragma unroll
        for (int nt = 0; nt < 8; nt++)
            #pragma unroll
            for (int t = 0; t < 4; t++) sacc[nt][t] = 0.f;

        #pragma unroll
        for (int kk = 0; kk < 64; kk += 8) {
            uint32_t aF[4];
            {
                int r = wrow + (lane >> 2);
                int c = kk + (lane & 3);
                aF[0] = __float_as_uint(Qs[r * QS_STR + c]);
                aF[1] = __float_as_uint(Qs[(r + 8) * QS_STR + c]);
                aF[2] = __float_as_uint(Qs[r * QS_STR + c + 4]);
                aF[3] = __float_as_uint(Qs[(r + 8) * QS_STR + c + 4]);
            }
            #pragma unroll
            for (int nt = 0; nt < 8; nt++) {
                uint32_t bF[2];
                int n = nt * 8 + (lane >> 2);
                int c = kk + (lane & 3);
                bF[0] = __float_as_uint(Ks[n * KS_STR + c]);
                bF[1] = __float_as_uint(Ks[n * KS_STR + c + 4]);
                mma_tf32(sacc[nt], aF, bF);
            }
        }

        // Scale + causal mask
        #pragma unroll
        for (int nt = 0; nt < 8; nt++) {
            int gcol = jb * 64 + nt * 8 + (lane & 3) * 2;
            float v0 = sacc[nt][0] * scale;
            float v1 = sacc[nt][1] * scale;
            float v2 = sacc[nt][2] * scale;
            float v3 = sacc[nt][3] * scale;
            if (gcol     > grow0) v0 = -1e30f;
            if (gcol + 1 > grow0) v1 = -1e30f;
            if (gcol     > grow1) v2 = -1e30f;
            if (gcol + 1 > grow1) v3 = -1e30f;
            sacc[nt][0] = v0; sacc[nt][1] = v1;
            sacc[nt][2] = v2; sacc[nt][3] = v3;
        }

        // Row max (quad reduce)
        float mx0 = -1e30f, mx1 = -1e30f;
        #pragma unroll
        for (int nt = 0; nt < 8; nt++) {
            mx0 = fmaxf(mx0, fmaxf(sacc[nt][0], sacc[nt][1]));
            mx1 = fmaxf(mx1, fmaxf(sacc[nt][2], sacc[nt][3]));
        }
        mx0 = fmaxf(mx0, __shfl_xor_sync(0xffffffffu, mx0, 1));
        mx0 = fmaxf(mx0, __shfl_xor_sync(0xffffffffu, mx0, 2));
        mx1 = fmaxf(mx1, __shfl_xor_sync(0xffffffffu, mx1, 1));
        mx1 = fmaxf(mx1, __shfl_xor_sync(0xffffffffu, mx1, 2));

        float mn0 = fmaxf(m0, mx0);
        float mn1 = fmaxf(m1, mx1);

        // Exponentiate + row sum
        float s0 = 0.f, s1 = 0.f;
        #pragma unroll
        for (int nt = 0; nt < 8; nt++) {
            float p0 = __expf(sacc[nt][0] - mn0);
            float p1 = __expf(sacc[nt][1] - mn0);
            float p2 = __expf(sacc[nt][2] - mn1);
            float p3 = __expf(sacc[nt][3] - mn1);
            sacc[nt][0] = p0; sacc[nt][1] = p1;
            sacc[nt][2] = p2; sacc[nt][3] = p3;
            s0 += p0 + p1;
            s1 += p2 + p3;
        }
        s0 += __shfl_xor_sync(0xffffffffu, s0, 1);
        s0 += __shfl_xor_sync(0xffffffffu, s0, 2);
        s1 += __shfl_xor_sync(0xffffffffu, s1, 1);
        s1 += __shfl_xor_sync(0xffffffffu, s1, 2);

        float al0 = __expf(m0 - mn0);
        float al1 = __expf(m1 - mn1);
        l0 = l0 * al0 + s0;
        l1 = l1 * al1 + s1;
        m0 = mn0; m1 = mn1;

        // Rescale O
        #pragma unroll
        for (int nt = 0; nt < 8; nt++) {
            oacc[nt][0] *= al0; oacc[nt][1] *= al0;
            oacc[nt][2] *= al1; oacc[nt][3] *= al1;
        }

        // Write P to smem (warp-local round trip)
        {
            int r = wrow + (lane >> 2);
            #pragma unroll
            for (int nt = 0; nt < 8; nt++) {
                int c = nt * 8 + (lane & 3) * 2;
                *(float2*)&Ps[r * PS_STR + c]       = make_float2(sacc[nt][0], sacc[nt][1]);
                *(float2*)&Ps[(r + 8) * PS_STR + c] = make_float2(sacc[nt][2], sacc[nt][3]);
            }
        }
        __syncwarp();

        // O += P @ V
        #pragma unroll
        for (int kk = 0; kk < 64; kk += 8) {
            uint32_t aF[4];
            {
                int r = wrow + (lane >> 2);
                int c = kk + (lane & 3);
                aF[0] = __float_as_uint(Ps[r * PS_STR + c]);
                aF[1] = __float_as_uint(Ps[(r + 8) * PS_STR + c]);
                aF[2] = __float_as_uint(Ps[r * PS_STR + c + 4]);
                aF[3] = __float_as_uint(Ps[(r + 8) * PS_STR + c + 4]);
            }
            #pragma unroll
            for (int nt = 0; nt < 8; nt++) {
                uint32_t bF[2];
                int s = kk + (lane & 3);
                int n = nt * 8 + (lane >> 2);
                bF[0] = __float_as_uint(Vs[s * VS_STR + n]);
                bF[1] = __float_as_uint(Vs[(s + 4) * VS_STR + n]);
                mma_tf32(oacc[nt], aF, bF);
            }
        }
    }

    // Normalize and store (tf32-rounded: feeds gemm_o as MMA operand)
    float li0 = 1.0f / l0, li1 = 1.0f / l1;
    {
        int r_g0 = b * NT + grow0;
        int r_g1 = b * NT + grow1;
        #pragma unroll
        for (int nt = 0; nt < 8; nt++) {
            int c = h * NHS + nt * 8 + (lane & 3) * 2;
            *(float2*)&g_attn[(size_t)r_g0 * ND + c] =
                make_float2(tf32r(oacc[nt][0] * li0), tf32r(oacc[nt][1] * li0));
            *(float2*)&g_attn[(size_t)r_g1 * ND + c] =
                make_float2(tf32r(oacc[nt][2] * li1), tf32r(oacc[nt][3] * li1));
        }
    }
}

// ---------------- SwiGLU elementwise (tf32-rounded output) ----------------
__global__ void swiglu_kernel()
{
    int idx = blockIdx.x * blockDim.x + threadIdx.x;
    if (idx >= NBT * NHALF) return;
    int row = idx / NHALF;
    int c   = idx % NHALF;
    float a = g_u[(size_t)row * NFF + c];
    float z = g_u[(size_t)row * NFF + NHALF + c];
    float sg = z / (1.0f + __expf(-z));
    g_gl[idx] = tf32r(sg * a);
}

// ---------------- launch ----------------
extern "C" void kernel_launch(void* const* d_in, const int* in_sizes, int n_in,
                              void* d_out, int out_size)
{
    const float* x  = (const float*)d_in[0];
    const float* Wq = (const float*)d_in[1];
    const float* Wk = (const float*)d_in[2];
    const float* Wv = (const float*)d_in[3];
    const float* Wo = (const float*)d_in[4];
    const float* bo = (const float*)d_in[5];
    const float* W1 = (const float*)d_in[6];
    const float* b1 = (const float*)d_in[7];
    const float* W2 = (const float*)d_in[8];
    const float* b2 = (const float*)d_in[9];
    const float* g1 = (const float*)d_in[10];
    const float* g2 = (const float*)d_in[11];
    float* out = (float*)d_out;

    const int ASMEM = (128 * QS_STR + 64 * KS_STR + 64 * VS_STR + 128 * PS_STR)
                      * (int)sizeof(float);   // 105472 B
    cudaFuncSetAttribute(attn_mma_kernel, cudaFuncAttributeMaxDynamicSharedMemorySize, ASMEM);
    cudaFuncSetAttribute(gemm_qkv_kernel,  cudaFuncAttributeMaxDynamicSharedMemorySize, GEMM_SMEM);
    cudaFuncSetAttribute(gemm_o_kernel,    cudaFuncAttributeMaxDynamicSharedMemorySize, GEMM_SMEM);
    cudaFuncSetAttribute(gemm_ffn1_kernel, cudaFuncAttributeMaxDynamicSharedMemorySize, GEMM_SMEM);
    cudaFuncSetAttribute(gemm_ffn2_kernel, cudaFuncAttributeMaxDynamicSharedMemorySize, GEMM_SMEM);

    pack_wqkv_kernel<<<(ND * 3 * ND + 255) / 256, 256>>>(Wq, Wk, Wv);
    round_weights_kernel<<<(W1_N + 255) / 256, 256>>>(Wo, W1, W2);
    rmsnorm1_kernel<<<NBT, 256>>>(x, g1);
    gemm_qkv_kernel<<<dim3(3 * ND / 128, NBT / 128), 256, GEMM_SMEM>>>();
    attn_mma_kernel<<<dim3(NT / 128, NH, NB), 256, ASMEM>>>();
    gemm_o_kernel<<<dim3(ND / 128, NBT / 128), 256, GEMM_SMEM>>>(bo, x);
    rmsnorm2_kernel<<<NBT, 256>>>(g2);
    gemm_ffn1_kernel<<<dim3(NFF / 128, NBT / 128), 256, GEMM_SMEM>>>(b1);
    swiglu_kernel<<<(NBT * NHALF + 255) / 256, 256>>>();
    gemm_ffn2_kernel<<<dim3(ND / 128, NBT / 128), 256, GEMM_SMEM>>>(b2, out);
}

// round 6
// speedup vs baseline: 1.2187x; 1.1353x over previous
#include <cuda_runtime.h>
#include <cuda_bf16.h>
#include <math.h>
#include <stdint.h>

// Problem constants
#define NB    2
#define NT    2048
#define ND    768
#define NH    12
#define NHS   64
#define NFF   3072
#define NHALF 1536
#define NBT   (NB*NT)   // 4096

// ---------------- scratch (device globals; no allocation) ----------------
__device__ __nv_bfloat16 g_h   [NBT * ND];        // rmsnorm output (bf16 GEMM A)
__device__ float         g_qkv [NBT * 3 * ND];    // fused qkv (tf32-rounded fp32)
__device__ __nv_bfloat16 g_attn[NBT * ND];        // attention output (bf16 GEMM A)
__device__ float         g_x1  [NBT * ND];        // residual after attention
__device__ float         g_u   [NBT * NFF];       // FFN1 output
__device__ __nv_bfloat16 g_gl  [NBT * NHALF];     // silu(gate)*a (bf16 GEMM A)
__device__ __nv_bfloat16 g_wqkv_t[3 * ND * ND];   // [2304 n][768 k]
__device__ __nv_bfloat16 g_wo_t  [ND * ND];       // [768 n][768 k]
__device__ __nv_bfloat16 g_w1_t  [NFF * ND];      // [3072 n][768 k]
__device__ __nv_bfloat16 g_w2_t  [ND * NHALF];    // [768 n][1536 k]

// ---------------- async copy helpers ----------------
__device__ __forceinline__ void cp_async16(void* smem_dst, const void* gmem_src)
{
    uint32_t d = (uint32_t)__cvta_generic_to_shared(smem_dst);
    asm volatile("cp.async.cg.shared.global [%0], [%1], 16;\n" :: "r"(d), "l"(gmem_src));
}
#define CP_COMMIT() asm volatile("cp.async.commit_group;\n" ::: "memory")
#define CP_WAIT1()  asm volatile("cp.async.wait_group 1;\n" ::: "memory")
#define CP_WAIT0()  asm volatile("cp.async.wait_group 0;\n" ::: "memory")

// ---------------- TF32 helpers (attention path) ----------------
__device__ __forceinline__ float tf32r(float x)
{
    uint32_t r;
    asm("cvt.rna.tf32.f32 %0, %1;" : "=r"(r) : "f"(x));
    return __uint_as_float(r);
}

__device__ __forceinline__ void mma_tf32(float* c, const uint32_t* a, const uint32_t* b)
{
    asm volatile(
        "mma.sync.aligned.m16n8k8.row.col.f32.tf32.tf32.f32 "
        "{%0,%1,%2,%3}, {%4,%5,%6,%7}, {%8,%9}, {%0,%1,%2,%3};\n"
        : "+f"(c[0]), "+f"(c[1]), "+f"(c[2]), "+f"(c[3])
        : "r"(a[0]), "r"(a[1]), "r"(a[2]), "r"(a[3]), "r"(b[0]), "r"(b[1]));
}

// ---------------- BF16 MMA ----------------
__device__ __forceinline__ void mma_bf16(float* c, const uint32_t* a, const uint32_t* b)
{
    asm volatile(
        "mma.sync.aligned.m16n8k16.row.col.f32.bf16.bf16.f32 "
        "{%0,%1,%2,%3}, {%4,%5,%6,%7}, {%8,%9}, {%0,%1,%2,%3};\n"
        : "+f"(c[0]), "+f"(c[1]), "+f"(c[2]), "+f"(c[3])
        : "r"(a[0]), "r"(a[1]), "r"(a[2]), "r"(a[3]), "r"(b[0]), "r"(b[1]));
}

// ---------------- pack Wq/Wk/Wv -> [2304 n][768 k] bf16 ----------------
__global__ void pack_wqkv_kernel(const float* __restrict__ Wq,
                                 const float* __restrict__ Wk,
                                 const float* __restrict__ Wv)
{
    int idx = blockIdx.x * blockDim.x + threadIdx.x;
    const int total = 3 * ND * ND;
    if (idx >= total) return;
    int n = idx / ND;           // output column 0..2303
    int d = idx % ND;           // k
    int m = n / ND;
    int r = n % ND;
    int h = r / NHS;
    int k = r % NHS;
    const float* W = (m == 0) ? Wq : ((m == 1) ? Wk : Wv);
    g_wqkv_t[idx] = __float2bfloat16(W[h * ND * NHS + d * NHS + k]);
}

// ---------------- transpose + bf16 Wo/W1/W2 ----------------
#define WO_N (ND * ND)
#define W1_N (ND * NFF)
#define W2_N (NHALF * ND)
__global__ void round_weights_kernel(const float* __restrict__ Wo,
                                     const float* __restrict__ W1,
                                     const float* __restrict__ W2)
{
    int idx = blockIdx.x * blockDim.x + threadIdx.x;
    if (idx < WO_N) {
        int n = idx / ND, k = idx % ND;
        g_wo_t[idx] = __float2bfloat16(Wo[k * ND + n]);
    }
    if (idx < W1_N) {
        int n = idx / ND, k = idx % ND;
        g_w1_t[idx] = __float2bfloat16(W1[k * NFF + n]);
    }
    if (idx < W2_N) {
        int n = idx / NHALF, k = idx % NHALF;
        g_w2_t[idx] = __float2bfloat16(W2[k * ND + n]);
    }
}

// ---------------- RMSNorm (bf16 output) ----------------
__device__ __forceinline__ void rms_body(const float* __restrict__ in,
                                         __nv_bfloat16* __restrict__ out,
                                         const float* __restrict__ g)
{
    int tid = threadIdx.x;
    float v0 = in[tid], v1 = in[tid + 256], v2 = in[tid + 512];
    float ss = v0*v0 + v1*v1 + v2*v2;
    #pragma unroll
    for (int o = 16; o; o >>= 1) ss += __shfl_xor_sync(0xffffffffu, ss, o);
    __shared__ float ws[8];
    __shared__ float s_inv;
    if ((tid & 31) == 0) ws[tid >> 5] = ss;
    __syncthreads();
    if (tid == 0) {
        float t = 0.f;
        #pragma unroll
        for (int i = 0; i < 8; i++) t += ws[i];
        float rms = sqrtf(t * (1.0f / (float)ND));
        s_inv = 1.0f / (rms + 1e-8f);
    }
    __syncthreads();
    float inv = s_inv;
    out[tid]       = __float2bfloat16(g[tid]       * v0 * inv);
    out[tid + 256] = __float2bfloat16(g[tid + 256] * v1 * inv);
    out[tid + 512] = __float2bfloat16(g[tid + 512] * v2 * inv);
}

__global__ __launch_bounds__(256) void rmsnorm1_kernel(const float* __restrict__ x,
                                                       const float* __restrict__ g)
{
    int row = blockIdx.x;
    rms_body(x + (size_t)row * ND, g_h + (size_t)row * ND, g);
}

__global__ __launch_bounds__(256) void rmsnorm2_kernel(const float* __restrict__ g)
{
    int row = blockIdx.x;
    rms_body(g_x1 + (size_t)row * ND, g_h + (size_t)row * ND, g);
}

// ---------------- BF16 GEMM: 128x128x64, 2-stage cp.async pipeline -------
// A [M][K] bf16 row-major; B stored transposed [N][K] bf16.
// Smem rows padded to 72 bf16 (36 b32): conflict-free scalar fragment LDS.
#define KC 64
#define STR32 36
#define STAGE32 (128 * STR32)
#define GEMM_SMEM (4 * STAGE32 * 4)   // 2 ops * 2 stages * STAGE32 b32 = 73728 B

template<int N, int K, bool BIAS, bool RES, bool ROUND>
__device__ __forceinline__ void bf16_gemm_body(const __nv_bfloat16* __restrict__ A,
                                               const __nv_bfloat16* __restrict__ Bt,
                                               float* __restrict__ C,
                                               const float* __restrict__ bias,
                                               const float* __restrict__ res)
{
    extern __shared__ __align__(16) uint32_t smu[];
    uint32_t* As = smu;                 // [2][128][36] b32
    uint32_t* Bs = smu + 2 * STAGE32;   // [2][128][36] b32

    const int tid  = threadIdx.x;
    const int warp = tid >> 5, lane = tid & 31;
    const int wm = (warp >> 1) * 32;
    const int wn = (warp & 1) * 64;
    const int bm = blockIdx.y * 128;
    const int bn = blockIdx.x * 128;

    const int lrow = tid >> 1;          // 0..127
    const int lch  = (tid & 1) * 4;     // 16B-chunk base (0 or 4); 8 chunks/row

    float acc[2][8][4];
    #pragma unroll
    for (int i = 0; i < 2; i++)
        #pragma unroll
        for (int j = 0; j < 8; j++)
            #pragma unroll
            for (int t = 0; t < 4; t++) acc[i][j][t] = 0.f;

    const int NCH = K / KC;

    // issue stage 0
    {
        uint32_t* as = As;
        uint32_t* bs = Bs;
        #pragma unroll
        for (int i = 0; i < 4; i++) {
            int ch = lch + i;
            cp_async16(&as[lrow * STR32 + ch * 4], A  + (size_t)(bm + lrow) * K + ch * 8);
            cp_async16(&bs[lrow * STR32 + ch * 4], Bt + (size_t)(bn + lrow) * K + ch * 8);
        }
        CP_COMMIT();
    }

    #pragma unroll 1
    for (int chunk = 0; chunk < NCH; chunk++) {
        const int cur = chunk & 1;
        if (chunk + 1 < NCH) {
            const int nxt = cur ^ 1;
            const int k0 = (chunk + 1) * KC;
            uint32_t* as = As + nxt * STAGE32;
            uint32_t* bs = Bs + nxt * STAGE32;
            #pragma unroll
            for (int i = 0; i < 4; i++) {
                int ch = lch + i;
                cp_async16(&as[lrow * STR32 + ch * 4],
                           A  + (size_t)(bm + lrow) * K + k0 + ch * 8);
                cp_async16(&bs[lrow * STR32 + ch * 4],
                           Bt + (size_t)(bn + lrow) * K + k0 + ch * 8);
            }
            CP_COMMIT();
            CP_WAIT1();
        } else {
            CP_WAIT0();
        }
        __syncthreads();

        const uint32_t* as = As + cur * STAGE32;
        const uint32_t* bs = Bs + cur * STAGE32;

        #pragma unroll
        for (int kk = 0; kk < KC; kk += 16) {
            const int kq = kk >> 1;    // b32 offset
            uint32_t aF[2][4], bF[8][2];
            #pragma unroll
            for (int mt = 0; mt < 2; mt++) {
                int r = wm + mt * 16 + (lane >> 2);
                int c = kq + (lane & 3);
                aF[mt][0] = as[r * STR32 + c];
                aF[mt][1] = as[(r + 8) * STR32 + c];
                aF[mt][2] = as[r * STR32 + c + 4];
                aF[mt][3] = as[(r + 8) * STR32 + c + 4];
            }
            #pragma unroll
            for (int nt = 0; nt < 8; nt++) {
                int n = wn + nt * 8 + (lane >> 2);
                int c = kq + (lane & 3);
                bF[nt][0] = bs[n * STR32 + c];
                bF[nt][1] = bs[n * STR32 + c + 4];
            }
            #pragma unroll
            for (int mt = 0; mt < 2; mt++)
                #pragma unroll
                for (int nt = 0; nt < 8; nt++)
                    mma_bf16(acc[mt][nt], aF[mt], bF[nt]);
        }
        __syncthreads();
    }

    #pragma unroll
    for (int mt = 0; mt < 2; mt++) {
        #pragma unroll
        for (int nt = 0; nt < 8; nt++) {
            int row0 = bm + wm + mt * 16 + (lane >> 2);
            int col  = bn + wn + nt * 8 + (lane & 3) * 2;
            float2 v0 = make_float2(acc[mt][nt][0], acc[mt][nt][1]);
            float2 v1 = make_float2(acc[mt][nt][2], acc[mt][nt][3]);
            if constexpr (BIAS) {
                float2 bb = *(const float2*)(bias + col);
                v0.x += bb.x; v0.y += bb.y;
                v1.x += bb.x; v1.y += bb.y;
            }
            if constexpr (RES) {
                float2 r0 = *(const float2*)(res + (size_t)row0 * N + col);
                float2 r1 = *(const float2*)(res + (size_t)(row0 + 8) * N + col);
                v0.x += r0.x; v0.y += r0.y;
                v1.x += r1.x; v1.y += r1.y;
            }
            if constexpr (ROUND) {
                v0.x = tf32r(v0.x); v0.y = tf32r(v0.y);
                v1.x = tf32r(v1.x); v1.y = tf32r(v1.y);
            }
            *(float2*)(C + (size_t)row0 * N + col)       = v0;
            *(float2*)(C + (size_t)(row0 + 8) * N + col) = v1;
        }
    }
}

__global__ __launch_bounds__(256) void gemm_qkv_kernel()
{
    // output tf32-rounded fp32: feeds attention tf32 MMAs directly
    bf16_gemm_body<3 * ND, ND, false, false, true>(g_h, g_wqkv_t, g_qkv, nullptr, nullptr);
}
__global__ __launch_bounds__(256) void gemm_o_kernel(const float* __restrict__ bo,
                                                     const float* __restrict__ x)
{
    bf16_gemm_body<ND, ND, true, true, false>(g_attn, g_wo_t, g_x1, bo, x);
}
__global__ __launch_bounds__(256) void gemm_ffn1_kernel(const float* __restrict__ b1)
{
    bf16_gemm_body<NFF, ND, true, false, false>(g_h, g_w1_t, g_u, b1, nullptr);
}
__global__ __launch_bounds__(256) void gemm_ffn2_kernel(const float* __restrict__ b2,
                                                        float* __restrict__ out)
{
    bf16_gemm_body<ND, NHALF, true, true, false>(g_gl, g_w2_t, out, b2, g_x1);
}

// ---------------- Flash attention with tf32 MMA + register prefetch -------
// g_qkv is pre-rounded to tf32 by gemm_qkv. Output stored bf16 for gemm_o.
#define QS_STR 68
#define KS_STR 68
#define VS_STR 72
#define PS_STR 68

__global__ __launch_bounds__(256) void attn_mma_kernel()
{
    extern __shared__ float sm[];
    float* Qs = sm;                      // [128][68]
    float* Ks = Qs + 128 * QS_STR;       // [64][68]
    float* Vs = Ks + 64 * KS_STR;        // [64][72]
    float* Ps = Vs + 64 * VS_STR;        // [128][68]

    const int tid  = threadIdx.x;
    const int warp = tid >> 5, lane = tid & 31;
    const int qb = (int)gridDim.x - 1 - (int)blockIdx.x;   // heavy blocks first
    const int h  = blockIdx.y;
    const int b  = blockIdx.z;
    const int row0 = qb * 128;
    const int wrow = warp * 16;

    const int lr = tid >> 4;            // 0..15
    const int lc = (tid & 15) * 4;      // 0..60

    // Load Q tile: 128 rows x 64 cols (already tf32)
    #pragma unroll
    for (int r = 0; r < 8; r++) {
        int row = lr + 16 * r;
        float4 v = *(const float4*)&g_qkv[(size_t)(b * NT + row0 + row) * (3 * ND)
                                          + h * NHS + lc];
        *(float4*)&Qs[row * QS_STR + lc] = v;
    }

    float oacc[8][4];
    #pragma unroll
    for (int nt = 0; nt < 8; nt++)
        #pragma unroll
        for (int t = 0; t < 4; t++) oacc[nt][t] = 0.f;

    float m0 = -1e30f, m1 = -1e30f, l0 = 0.f, l1 = 0.f;
    const float scale = 0.03608439182435161f;   // 768^-0.5

    const int grow0 = row0 + wrow + (lane >> 2);
    const int grow1 = grow0 + 8;
    const int jb_max = 2 * qb + 1;

    // Prefetch K/V tile 0 into registers
    float4 kpre[4], vpre[4];
    #pragma unroll
    for (int r = 0; r < 4; r++) {
        int row = lr + 16 * r;
        size_t base = (size_t)(b * NT + row) * (3 * ND) + h * NHS + lc;
        kpre[r] = *(const float4*)&g_qkv[ND + base];
        vpre[r] = *(const float4*)&g_qkv[2 * ND + base];
    }

    for (int jb = 0; jb <= jb_max; jb++) {
        __syncthreads();   // all warps done reading previous K/V
        #pragma unroll
        for (int r = 0; r < 4; r++) {
            int row = lr + 16 * r;
            *(float4*)&Ks[row * KS_STR + lc] = kpre[r];
            *(float4*)&Vs[row * VS_STR + lc] = vpre[r];
        }
        __syncthreads();

        // Issue prefetch for next tile (overlaps with MMA + softmax below)
        if (jb < jb_max) {
            #pragma unroll
            for (int r = 0; r < 4; r++) {
                int row = lr + 16 * r;
                size_t base = (size_t)(b * NT + (jb + 1) * 64 + row) * (3 * ND)
                              + h * NHS + lc;
                kpre[r] = *(const float4*)&g_qkv[ND + base];
                vpre[r] = *(const float4*)&g_qkv[2 * ND + base];
            }
        }

        // S = Q K^T (16x64 per warp, in C fragments)
        float sacc[8][4];
        #pragma unroll
        for (int nt = 0; nt < 8; nt++)
            #pragma unroll
            for (int t = 0; t < 4; t++) sacc[nt][t] = 0.f;

        #pragma unroll
        for (int kk = 0; kk < 64; kk += 8) {
            uint32_t aF[4];
            {
                int r = wrow + (lane >> 2);
                int c = kk + (lane & 3);
                aF[0] = __float_as_uint(Qs[r * QS_STR + c]);
                aF[1] = __float_as_uint(Qs[(r + 8) * QS_STR + c]);
                aF[2] = __float_as_uint(Qs[r * QS_STR + c + 4]);
                aF[3] = __float_as_uint(Qs[(r + 8) * QS_STR + c + 4]);
            }
            #pragma unroll
            for (int nt = 0; nt < 8; nt++) {
                uint32_t bF[2];
                int n = nt * 8 + (lane >> 2);
                int c = kk + (lane & 3);
                bF[0] = __float_as_uint(Ks[n * KS_STR + c]);
                bF[1] = __float_as_uint(Ks[n * KS_STR + c + 4]);
                mma_tf32(sacc[nt], aF, bF);
            }
        }

        // Scale + causal mask
        #pragma unroll
        for (int nt = 0; nt < 8; nt++) {
            int gcol = jb * 64 + nt * 8 + (lane & 3) * 2;
            float v0 = sacc[nt][0] * scale;
            float v1 = sacc[nt][1] * scale;
            float v2 = sacc[nt][2] * scale;
            float v3 = sacc[nt][3] * scale;
            if (gcol     > grow0) v0 = -1e30f;
            if (gcol + 1 > grow0) v1 = -1e30f;
            if (gcol     > grow1) v2 = -1e30f;
            if (gcol + 1 > grow1) v3 = -1e30f;
            sacc[nt][0] = v0; sacc[nt][1] = v1;
            sacc[nt][2] = v2; sacc[nt][3] = v3;
        }

        // Row max (quad reduce)
        float mx0 = -1e30f, mx1 = -1e30f;
        #pragma unroll
        for (int nt = 0; nt < 8; nt++) {
            mx0 = fmaxf(mx0, fmaxf(sacc[nt][0], sacc[nt][1]));
            mx1 = fmaxf(mx1, fmaxf(sacc[nt][2], sacc[nt][3]));
        }
        mx0 = fmaxf(mx0, __shfl_xor_sync(0xffffffffu, mx0, 1));
        mx0 = fmaxf(mx0, __shfl_xor_sync(0xffffffffu, mx0, 2));
        mx1 = fmaxf(mx1, __shfl_xor_sync(0xffffffffu, mx1, 1));
        mx1 = fmaxf(mx1, __shfl_xor_sync(0xffffffffu, mx1, 2));

        float mn0 = fmaxf(m0, mx0);
        float mn1 = fmaxf(m1, mx1);

        // Exponentiate + row sum
        float s0 = 0.f, s1 = 0.f;
        #pragma unroll
        for (int nt = 0; nt < 8; nt++) {
            float p0 = __expf(sacc[nt][0] - mn0);
            float p1 = __expf(sacc[nt][1] - mn0);
            float p2 = __expf(sacc[nt][2] - mn1);
            float p3 = __expf(sacc[nt][3] - mn1);
            sacc[nt][0] = p0; sacc[nt][1] = p1;
            sacc[nt][2] = p2; sacc[nt][3] = p3;
            s0 += p0 + p1;
            s1 += p2 + p3;
        }
        s0 += __shfl_xor_sync(0xffffffffu, s0, 1);
        s0 += __shfl_xor_sync(0xffffffffu, s0, 2);
        s1 += __shfl_xor_sync(0xffffffffu, s1, 1);
        s1 += __shfl_xor_sync(0xffffffffu, s1, 2);

        float al0 = __expf(m0 - mn0);
        float al1 = __expf(m1 - mn1);
        l0 = l0 * al0 + s0;
        l1 = l1 * al1 + s1;
        m0 = mn0; m1 = mn1;

        // Rescale O
        #pragma unroll
        for (int nt = 0; nt < 8; nt++) {
            oacc[nt][0] *= al0; oacc[nt][1] *= al0;
            oacc[nt][2] *= al1; oacc[nt][3] *= al1;
        }

        // Write P to smem (warp-local round trip)
        {
            int r = wrow + (lane >> 2);
            #pragma unroll
            for (int nt = 0; nt < 8; nt++) {
                int c = nt * 8 + (lane & 3) * 2;
                *(float2*)&Ps[r * PS_STR + c]       = make_float2(sacc[nt][0], sacc[nt][1]);
                *(float2*)&Ps[(r + 8) * PS_STR + c] = make_float2(sacc[nt][2], sacc[nt][3]);
            }
        }
        __syncwarp();

        // O += P @ V
        #pragma unroll
        for (int kk = 0; kk < 64; kk += 8) {
            uint32_t aF[4];
            {
                int r = wrow + (lane >> 2);
                int c = kk + (lane & 3);
                aF[0] = __float_as_uint(Ps[r * PS_STR + c]);
                aF[1] = __float_as_uint(Ps[(r + 8) * PS_STR + c]);
                aF[2] = __float_as_uint(Ps[r * PS_STR + c + 4]);
                aF[3] = __float_as_uint(Ps[(r + 8) * PS_STR + c + 4]);
            }
            #pragma unroll
            for (int nt = 0; nt < 8; nt++) {
                uint32_t bF[2];
                int s = kk + (lane & 3);
                int n = nt * 8 + (lane >> 2);
                bF[0] = __float_as_uint(Vs[s * VS_STR + n]);
                bF[1] = __float_as_uint(Vs[(s + 4) * VS_STR + n]);
                mma_tf32(oacc[nt], aF, bF);
            }
        }
    }

    // Normalize and store as bf16 (feeds gemm_o's A operand)
    float li0 = 1.0f / l0, li1 = 1.0f / l1;
    {
        int r_g0 = b * NT + grow0;
        int r_g1 = b * NT + grow1;
        #pragma unroll
        for (int nt = 0; nt < 8; nt++) {
            int c = h * NHS + nt * 8 + (lane & 3) * 2;
            __nv_bfloat162 p0 = __floats2bfloat162_rn(oacc[nt][0] * li0, oacc[nt][1] * li0);
            __nv_bfloat162 p1 = __floats2bfloat162_rn(oacc[nt][2] * li1, oacc[nt][3] * li1);
            *(__nv_bfloat162*)&g_attn[(size_t)r_g0 * ND + c] = p0;
            *(__nv_bfloat162*)&g_attn[(size_t)r_g1 * ND + c] = p1;
        }
    }
}

// ---------------- SwiGLU elementwise (bf16 output) ----------------
__global__ void swiglu_kernel()
{
    int idx = blockIdx.x * blockDim.x + threadIdx.x;
    if (idx >= NBT * NHALF) return;
    int row = idx / NHALF;
    int c   = idx % NHALF;
    float a = g_u[(size_t)row * NFF + c];
    float z = g_u[(size_t)row * NFF + NHALF + c];
    float sg = z / (1.0f + __expf(-z));
    g_gl[idx] = __float2bfloat16(sg * a);
}

// ---------------- launch ----------------
extern "C" void kernel_launch(void* const* d_in, const int* in_sizes, int n_in,
                              void* d_out, int out_size)
{
    const float* x  = (const float*)d_in[0];
    const float* Wq = (const float*)d_in[1];
    const float* Wk = (const float*)d_in[2];
    const float* Wv = (const float*)d_in[3];
    const float* Wo = (const float*)d_in[4];
    const float* bo = (const float*)d_in[5];
    const float* W1 = (const float*)d_in[6];
    const float* b1 = (const float*)d_in[7];
    const float* W2 = (const float*)d_in[8];
    const float* b2 = (const float*)d_in[9];
    const float* g1 = (const float*)d_in[10];
    const float* g2 = (const float*)d_in[11];
    float* out = (float*)d_out;

    const int ASMEM = (128 * QS_STR + 64 * KS_STR + 64 * VS_STR + 128 * PS_STR)
                      * (int)sizeof(float);   // 105472 B
    cudaFuncSetAttribute(attn_mma_kernel, cudaFuncAttributeMaxDynamicSharedMemorySize, ASMEM);
    cudaFuncSetAttribute(gemm_qkv_kernel,  cudaFuncAttributeMaxDynamicSharedMemorySize, GEMM_SMEM);
    cudaFuncSetAttribute(gemm_o_kernel,    cudaFuncAttributeMaxDynamicSharedMemorySize, GEMM_SMEM);
    cudaFuncSetAttribute(gemm_ffn1_kernel, cudaFuncAttributeMaxDynamicSharedMemorySize, GEMM_SMEM);
    cudaFuncSetAttribute(gemm_ffn2_kernel, cudaFuncAttributeMaxDynamicSharedMemorySize, GEMM_SMEM);

    pack_wqkv_kernel<<<(3 * ND * ND + 255) / 256, 256>>>(Wq, Wk, Wv);
    round_weights_kernel<<<(W1_N + 255) / 256, 256>>>(Wo, W1, W2);
    rmsnorm1_kernel<<<NBT, 256>>>(x, g1);
    gemm_qkv_kernel<<<dim3(3 * ND / 128, NBT / 128), 256, GEMM_SMEM>>>();
    attn_mma_kernel<<<dim3(NT / 128, NH, NB), 256, ASMEM>>>();
    gemm_o_kernel<<<dim3(ND / 128, NBT / 128), 256, GEMM_SMEM>>>(bo, x);
    rmsnorm2_kernel<<<NBT, 256>>>(g2);
    gemm_ffn1_kernel<<<dim3(NFF / 128, NBT / 128), 256, GEMM_SMEM>>>(b1);
    swiglu_kernel<<<(NBT * NHALF + 255) / 256, 256>>>();
    gemm_ffn2_kernel<<<dim3(ND / 128, NBT / 128), 256, GEMM_SMEM>>>(b2, out);
}

// round 7
// speedup vs baseline: 1.2535x; 1.0286x over previous
#include <cuda_runtime.h>
#include <cuda_bf16.h>
#include <math.h>
#include <stdint.h>

// Problem constants
#define NB    2
#define NT    2048
#define ND    768
#define NH    12
#define NHS   64
#define NFF   3072
#define NHALF 1536
#define NBT   (NB*NT)   // 4096

// ---------------- scratch (device globals; no allocation) ----------------
__device__ __nv_bfloat16 g_h   [NBT * ND];
__device__ float         g_qkv [NBT * 3 * ND];
__device__ __nv_bfloat16 g_attn[NBT * ND];
__device__ float         g_x1  [NBT * ND];
__device__ float         g_u   [NBT * NFF];
__device__ __nv_bfloat16 g_gl  [NBT * NHALF];
__device__ __nv_bfloat16 g_wqkv_t[3 * ND * ND];   // [2304 n][768 k]
__device__ __nv_bfloat16 g_wo_t  [ND * ND];       // [768 n][768 k]
__device__ __nv_bfloat16 g_w1_t  [NFF * ND];      // [3072 n][768 k]
__device__ __nv_bfloat16 g_w2_t  [ND * NHALF];    // [768 n][1536 k]

// ---------------- async copy helpers ----------------
__device__ __forceinline__ void cp_async16(void* smem_dst, const void* gmem_src)
{
    uint32_t d = (uint32_t)__cvta_generic_to_shared(smem_dst);
    asm volatile("cp.async.cg.shared.global [%0], [%1], 16;\n" :: "r"(d), "l"(gmem_src));
}
#define CP_COMMIT() asm volatile("cp.async.commit_group;\n" ::: "memory")
#define CP_WAIT1()  asm volatile("cp.async.wait_group 1;\n" ::: "memory")
#define CP_WAIT0()  asm volatile("cp.async.wait_group 0;\n" ::: "memory")

// ---------------- ldmatrix ----------------
__device__ __forceinline__ void ldsm_x4(uint32_t& r0, uint32_t& r1,
                                        uint32_t& r2, uint32_t& r3, uint32_t addr)
{
    asm volatile("ldmatrix.sync.aligned.m8n8.x4.shared.b16 {%0,%1,%2,%3}, [%4];"
                 : "=r"(r0), "=r"(r1), "=r"(r2), "=r"(r3) : "r"(addr));
}

// ---------------- TF32 helpers (attention path) ----------------
__device__ __forceinline__ float tf32r(float x)
{
    uint32_t r;
    asm("cvt.rna.tf32.f32 %0, %1;" : "=r"(r) : "f"(x));
    return __uint_as_float(r);
}

__device__ __forceinline__ void mma_tf32(float* c, const uint32_t* a, const uint32_t* b)
{
    asm volatile(
        "mma.sync.aligned.m16n8k8.row.col.f32.tf32.tf32.f32 "
        "{%0,%1,%2,%3}, {%4,%5,%6,%7}, {%8,%9}, {%0,%1,%2,%3};\n"
        : "+f"(c[0]), "+f"(c[1]), "+f"(c[2]), "+f"(c[3])
        : "r"(a[0]), "r"(a[1]), "r"(a[2]), "r"(a[3]), "r"(b[0]), "r"(b[1]));
}

// ---------------- BF16 MMA ----------------
__device__ __forceinline__ void mma_bf16(float* c, const uint32_t* a, const uint32_t* b)
{
    asm volatile(
        "mma.sync.aligned.m16n8k16.row.col.f32.bf16.bf16.f32 "
        "{%0,%1,%2,%3}, {%4,%5,%6,%7}, {%8,%9}, {%0,%1,%2,%3};\n"
        : "+f"(c[0]), "+f"(c[1]), "+f"(c[2]), "+f"(c[3])
        : "r"(a[0]), "r"(a[1]), "r"(a[2]), "r"(a[3]), "r"(b[0]), "r"(b[1]));
}

// ---------------- pack Wq/Wk/Wv -> [2304 n][768 k] bf16 ----------------
__global__ void pack_wqkv_kernel(const float* __restrict__ Wq,
                                 const float* __restrict__ Wk,
                                 const float* __restrict__ Wv)
{
    int idx = blockIdx.x * blockDim.x + threadIdx.x;
    const int total = 3 * ND * ND;
    if (idx >= total) return;
    int n = idx / ND;
    int d = idx % ND;
    int m = n / ND;
    int r = n % ND;
    int h = r / NHS;
    int k = r % NHS;
    const float* W = (m == 0) ? Wq : ((m == 1) ? Wk : Wv);
    g_wqkv_t[idx] = __float2bfloat16(W[h * ND * NHS + d * NHS + k]);
}

// ---------------- transpose + bf16 Wo/W1/W2 ----------------
#define WO_N (ND * ND)
#define W1_N (ND * NFF)
#define W2_N (NHALF * ND)
__global__ void round_weights_kernel(const float* __restrict__ Wo,
                                     const float* __restrict__ W1,
                                     const float* __restrict__ W2)
{
    int idx = blockIdx.x * blockDim.x + threadIdx.x;
    if (idx < WO_N) {
        int n = idx / ND, k = idx % ND;
        g_wo_t[idx] = __float2bfloat16(Wo[k * ND + n]);
    }
    if (idx < W1_N) {
        int n = idx / ND, k = idx % ND;
        g_w1_t[idx] = __float2bfloat16(W1[k * NFF + n]);
    }
    if (idx < W2_N) {
        int n = idx / NHALF, k = idx % NHALF;
        g_w2_t[idx] = __float2bfloat16(W2[k * ND + n]);
    }
}

// ---------------- RMSNorm (bf16 output) ----------------
__device__ __forceinline__ void rms_body(const float* __restrict__ in,
                                         __nv_bfloat16* __restrict__ out,
                                         const float* __restrict__ g)
{
    int tid = threadIdx.x;
    float v0 = in[tid], v1 = in[tid + 256], v2 = in[tid + 512];
    float ss = v0*v0 + v1*v1 + v2*v2;
    #pragma unroll
    for (int o = 16; o; o >>= 1) ss += __shfl_xor_sync(0xffffffffu, ss, o);
    __shared__ float ws[8];
    __shared__ float s_inv;
    if ((tid & 31) == 0) ws[tid >> 5] = ss;
    __syncthreads();
    if (tid == 0) {
        float t = 0.f;
        #pragma unroll
        for (int i = 0; i < 8; i++) t += ws[i];
        float rms = sqrtf(t * (1.0f / (float)ND));
        s_inv = 1.0f / (rms + 1e-8f);
    }
    __syncthreads();
    float inv = s_inv;
    out[tid]       = __float2bfloat16(g[tid]       * v0 * inv);
    out[tid + 256] = __float2bfloat16(g[tid + 256] * v1 * inv);
    out[tid + 512] = __float2bfloat16(g[tid + 512] * v2 * inv);
}

__global__ __launch_bounds__(256) void rmsnorm1_kernel(const float* __restrict__ x,
                                                       const float* __restrict__ g)
{
    int row = blockIdx.x;
    rms_body(x + (size_t)row * ND, g_h + (size_t)row * ND, g);
}

__global__ __launch_bounds__(256) void rmsnorm2_kernel(const float* __restrict__ g)
{
    int row = blockIdx.x;
    rms_body(g_x1 + (size_t)row * ND, g_h + (size_t)row * ND, g);
}

// ---------------- BF16 GEMM: 128x128x64, cp.async + ldmatrix -------------
#define KC 64
#define STR32 36
#define STAGE32 (128 * STR32)
#define GEMM_SMEM (4 * STAGE32 * 4)   // 73728 B

template<int N, int K, bool BIAS, bool RES, bool ROUND>
__device__ __forceinline__ void bf16_gemm_body(const __nv_bfloat16* __restrict__ A,
                                               const __nv_bfloat16* __restrict__ Bt,
                                               float* __restrict__ C,
                                               const float* __restrict__ bias,
                                               const float* __restrict__ res)
{
    extern __shared__ __align__(16) uint32_t smu[];
    uint32_t* As = smu;                 // [2][128][36] b32
    uint32_t* Bs = smu + 2 * STAGE32;   // [2][128][36] b32

    const int tid  = threadIdx.x;
    const int warp = tid >> 5, lane = tid & 31;
    const int wm = (warp >> 1) * 32;
    const int wn = (warp & 1) * 64;
    const int bm = blockIdx.y * 128;
    const int bn = blockIdx.x * 128;

    const uint32_t s_smu = (uint32_t)__cvta_generic_to_shared(smu);

    const int lrow = tid >> 1;
    const int lch  = (tid & 1) * 4;

    // ldmatrix per-lane byte offsets (within a stage)
    const uint32_t a_off0 = (uint32_t)(wm + (lane & 15)) * 144u + ((lane >> 4) << 4);
    const uint32_t b_off0 = (uint32_t)(wn + (lane & 7) + ((lane >> 4) << 3)) * 144u
                          + (((lane >> 3) & 1) << 4);

    float acc[2][8][4];
    #pragma unroll
    for (int i = 0; i < 2; i++)
        #pragma unroll
        for (int j = 0; j < 8; j++)
            #pragma unroll
            for (int t = 0; t < 4; t++) acc[i][j][t] = 0.f;

    const int NCH = K / KC;

    {
        uint32_t* as = As;
        uint32_t* bs = Bs;
        #pragma unroll
        for (int i = 0; i < 4; i++) {
            int ch = lch + i;
            cp_async16(&as[lrow * STR32 + ch * 4], A  + (size_t)(bm + lrow) * K + ch * 8);
            cp_async16(&bs[lrow * STR32 + ch * 4], Bt + (size_t)(bn + lrow) * K + ch * 8);
        }
        CP_COMMIT();
    }

    #pragma unroll 1
    for (int chunk = 0; chunk < NCH; chunk++) {
        const int cur = chunk & 1;
        if (chunk + 1 < NCH) {
            const int nxt = cur ^ 1;
            const int k0 = (chunk + 1) * KC;
            uint32_t* as = As + nxt * STAGE32;
            uint32_t* bs = Bs + nxt * STAGE32;
            #pragma unroll
            for (int i = 0; i < 4; i++) {
                int ch = lch + i;
                cp_async16(&as[lrow * STR32 + ch * 4],
                           A  + (size_t)(bm + lrow) * K + k0 + ch * 8);
                cp_async16(&bs[lrow * STR32 + ch * 4],
                           Bt + (size_t)(bn + lrow) * K + k0 + ch * 8);
            }
            CP_COMMIT();
            CP_WAIT1();
        } else {
            CP_WAIT0();
        }
        __syncthreads();

        const uint32_t as_b = s_smu + (uint32_t)(cur * STAGE32 * 4) + a_off0;
        const uint32_t bs_b = s_smu + (uint32_t)((2 + cur) * STAGE32 * 4) + b_off0;

        #pragma unroll
        for (int kk = 0; kk < KC; kk += 16) {
            uint32_t aF[2][4], bF[8][2];
            #pragma unroll
            for (int mt = 0; mt < 2; mt++)
                ldsm_x4(aF[mt][0], aF[mt][1], aF[mt][2], aF[mt][3],
                        as_b + (uint32_t)(mt * 16 * 144) + (uint32_t)(kk * 2));
            #pragma unroll
            for (int p = 0; p < 4; p++)
                ldsm_x4(bF[2*p][0], bF[2*p][1], bF[2*p+1][0], bF[2*p+1][1],
                        bs_b + (uint32_t)(p * 16 * 144) + (uint32_t)(kk * 2));
            #pragma unroll
            for (int mt = 0; mt < 2; mt++)
                #pragma unroll
                for (int nt = 0; nt < 8; nt++)
                    mma_bf16(acc[mt][nt], aF[mt], bF[nt]);
        }
        __syncthreads();
    }

    #pragma unroll
    for (int mt = 0; mt < 2; mt++) {
        #pragma unroll
        for (int nt = 0; nt < 8; nt++) {
            int row0 = bm + wm + mt * 16 + (lane >> 2);
            int col  = bn + wn + nt * 8 + (lane & 3) * 2;
            float2 v0 = make_float2(acc[mt][nt][0], acc[mt][nt][1]);
            float2 v1 = make_float2(acc[mt][nt][2], acc[mt][nt][3]);
            if constexpr (BIAS) {
                float2 bb = *(const float2*)(bias + col);
                v0.x += bb.x; v0.y += bb.y;
                v1.x += bb.x; v1.y += bb.y;
            }
            if constexpr (RES) {
                float2 r0 = *(const float2*)(res + (size_t)row0 * N + col);
                float2 r1 = *(const float2*)(res + (size_t)(row0 + 8) * N + col);
                v0.x += r0.x; v0.y += r0.y;
                v1.x += r1.x; v1.y += r1.y;
            }
            if constexpr (ROUND) {
                v0.x = tf32r(v0.x); v0.y = tf32r(v0.y);
                v1.x = tf32r(v1.x); v1.y = tf32r(v1.y);
            }
            *(float2*)(C + (size_t)row0 * N + col)       = v0;
            *(float2*)(C + (size_t)(row0 + 8) * N + col) = v1;
        }
    }
}

__global__ __launch_bounds__(256) void gemm_qkv_kernel()
{
    bf16_gemm_body<3 * ND, ND, false, false, true>(g_h, g_wqkv_t, g_qkv, nullptr, nullptr);
}
__global__ __launch_bounds__(256) void gemm_o_kernel(const float* __restrict__ bo,
                                                     const float* __restrict__ x)
{
    bf16_gemm_body<ND, ND, true, true, false>(g_attn, g_wo_t, g_x1, bo, x);
}
__global__ __launch_bounds__(256) void gemm_ffn1_kernel(const float* __restrict__ b1)
{
    bf16_gemm_body<NFF, ND, true, false, false>(g_h, g_w1_t, g_u, b1, nullptr);
}
__global__ __launch_bounds__(256) void gemm_ffn2_kernel(const float* __restrict__ b2,
                                                        float* __restrict__ out)
{
    bf16_gemm_body<ND, NHALF, true, true, false>(g_gl, g_w2_t, out, b2, g_x1);
}

// ---------------- Flash attention with tf32 MMA + register prefetch -------
#define QS_STR 68
#define KS_STR 68
#define VS_STR 72
#define PS_STR 68

__global__ __launch_bounds__(256) void attn_mma_kernel()
{
    extern __shared__ float sm[];
    float* Qs = sm;                      // [128][68]
    float* Ks = Qs + 128 * QS_STR;       // [64][68]
    float* Vs = Ks + 64 * KS_STR;        // [64][72]
    float* Ps = Vs + 64 * VS_STR;        // [128][68]

    const int tid  = threadIdx.x;
    const int warp = tid >> 5, lane = tid & 31;
    const int qb = (int)gridDim.x - 1 - (int)blockIdx.x;
    const int h  = blockIdx.y;
    const int b  = blockIdx.z;
    const int row0 = qb * 128;
    const int wrow = warp * 16;

    const int lr = tid >> 4;
    const int lc = (tid & 15) * 4;

    #pragma unroll
    for (int r = 0; r < 8; r++) {
        int row = lr + 16 * r;
        float4 v = *(const float4*)&g_qkv[(size_t)(b * NT + row0 + row) * (3 * ND)
                                          + h * NHS + lc];
        *(float4*)&Qs[row * QS_STR + lc] = v;
    }

    float oacc[8][4];
    #pragma unroll
    for (int nt = 0; nt < 8; nt++)
        #pragma unroll
        for (int t = 0; t < 4; t++) oacc[nt][t] = 0.f;

    float m0 = -1e30f, m1 = -1e30f, l0 = 0.f, l1 = 0.f;
    const float scale = 0.03608439182435161f;   // 768^-0.5

    const int grow0 = row0 + wrow + (lane >> 2);
    const int grow1 = grow0 + 8;
    const int jb_max = 2 * qb + 1;

    float4 kpre[4], vpre[4];
    #pragma unroll
    for (int r = 0; r < 4; r++) {
        int row = lr + 16 * r;
        size_t base = (size_t)(b * NT + row) * (3 * ND) + h * NHS + lc;
        kpre[r] = *(const float4*)&g_qkv[ND + base];
        vpre[r] = *(const float4*)&g_qkv[2 * ND + base];
    }

    for (int jb = 0; jb <= jb_max; jb++) {
        __syncthreads();
        #pragma unroll
        for (int r = 0; r < 4; r++) {
            int row = lr + 16 * r;
            *(float4*)&Ks[row * KS_STR + lc] = kpre[r];
            *(float4*)&Vs[row * VS_STR + lc] = vpre[r];
        }
        __syncthreads();

        if (jb < jb_max) {
            #pragma unroll
            for (int r = 0; r < 4; r++) {
                int row = lr + 16 * r;
                size_t base = (size_t)(b * NT + (jb + 1) * 64 + row) * (3 * ND)
                              + h * NHS + lc;
                kpre[r] = *(const float4*)&g_qkv[ND + base];
                vpre[r] = *(const float4*)&g_qkv[2 * ND + base];
            }
        }

        float sacc[8][4];
        #pragma unroll
        for (int nt = 0; nt < 8; nt++)
            #pragma unroll
            for (int t = 0; t < 4; t++) sacc[nt][t] = 0.f;

        #pragma unroll
        for (int kk = 0; kk < 64; kk += 8) {
            uint32_t aF[4];
            {
                int r = wrow + (lane >> 2);
                int c = kk + (lane & 3);
                aF[0] = __float_as_uint(Qs[r * QS_STR + c]);
                aF[1] = __float_as_uint(Qs[(r + 8) * QS_STR + c]);
                aF[2] = __float_as_uint(Qs[r * QS_STR + c + 4]);
                aF[3] = __float_as_uint(Qs[(r + 8) * QS_STR + c + 4]);
            }
            #pragma unroll
            for (int nt = 0; nt < 8; nt++) {
                uint32_t bF[2];
                int n = nt * 8 + (lane >> 2);
                int c = kk + (lane & 3);
                bF[0] = __float_as_uint(Ks[n * KS_STR + c]);
                bF[1] = __float_as_uint(Ks[n * KS_STR + c + 4]);
                mma_tf32(sacc[nt], aF, bF);
            }
        }

        #pragma unroll
        for (int nt = 0; nt < 8; nt++) {
            int gcol = jb * 64 + nt * 8 + (lane & 3) * 2;
            float v0 = sacc[nt][0] * scale;
            float v1 = sacc[nt][1] * scale;
            float v2 = sacc[nt][2] * scale;
            float v3 = sacc[nt][3] * scale;
            if (gcol     > grow0) v0 = -1e30f;
            if (gcol + 1 > grow0) v1 = -1e30f;
            if (gcol     > grow1) v2 = -1e30f;
            if (gcol + 1 > grow1) v3 = -1e30f;
            sacc[nt][0] = v0; sacc[nt][1] = v1;
            sacc[nt][2] = v2; sacc[nt][3] = v3;
        }

        float mx0 = -1e30f, mx1 = -1e30f;
        #pragma unroll
        for (int nt = 0; nt < 8; nt++) {
            mx0 = fmaxf(mx0, fmaxf(sacc[nt][0], sacc[nt][1]));
            mx1 = fmaxf(mx1, fmaxf(sacc[nt][2], sacc[nt][3]));
        }
        mx0 = fmaxf(mx0, __shfl_xor_sync(0xffffffffu, mx0, 1));
        mx0 = fmaxf(mx0, __shfl_xor_sync(0xffffffffu, mx0, 2));
        mx1 = fmaxf(mx1, __shfl_xor_sync(0xffffffffu, mx1, 1));
        mx1 = fmaxf(mx1, __shfl_xor_sync(0xffffffffu, mx1, 2));

        float mn0 = fmaxf(m0, mx0);
        float mn1 = fmaxf(m1, mx1);

        float s0 = 0.f, s1 = 0.f;
        #pragma unroll
        for (int nt = 0; nt < 8; nt++) {
            float p0 = __expf(sacc[nt][0] - mn0);
            float p1 = __expf(sacc[nt][1] - mn0);
            float p2 = __expf(sacc[nt][2] - mn1);
            float p3 = __expf(sacc[nt][3] - mn1);
            sacc[nt][0] = p0; sacc[nt][1] = p1;
            sacc[nt][2] = p2; sacc[nt][3] = p3;
            s0 += p0 + p1;
            s1 += p2 + p3;
        }
        s0 += __shfl_xor_sync(0xffffffffu, s0, 1);
        s0 += __shfl_xor_sync(0xffffffffu, s0, 2);
        s1 += __shfl_xor_sync(0xffffffffu, s1, 1);
        s1 += __shfl_xor_sync(0xffffffffu, s1, 2);

        float al0 = __expf(m0 - mn0);
        float al1 = __expf(m1 - mn1);
        l0 = l0 * al0 + s0;
        l1 = l1 * al1 + s1;
        m0 = mn0; m1 = mn1;

        #pragma unroll
        for (int nt = 0; nt < 8; nt++) {
            oacc[nt][0] *= al0; oacc[nt][1] *= al0;
            oacc[nt][2] *= al1; oacc[nt][3] *= al1;
        }

        {
            int r = wrow + (lane >> 2);
            #pragma unroll
            for (int nt = 0; nt < 8; nt++) {
                int c = nt * 8 + (lane & 3) * 2;
                *(float2*)&Ps[r * PS_STR + c]       = make_float2(sacc[nt][0], sacc[nt][1]);
                *(float2*)&Ps[(r + 8) * PS_STR + c] = make_float2(sacc[nt][2], sacc[nt][3]);
            }
        }
        __syncwarp();

        #pragma unroll
        for (int kk = 0; kk < 64; kk += 8) {
            uint32_t aF[4];
            {
                int r = wrow + (lane >> 2);
                int c = kk + (lane & 3);
                aF[0] = __float_as_uint(Ps[r * PS_STR + c]);
                aF[1] = __float_as_uint(Ps[(r + 8) * PS_STR + c]);
                aF[2] = __float_as_uint(Ps[r * PS_STR + c + 4]);
                aF[3] = __float_as_uint(Ps[(r + 8) * PS_STR + c + 4]);
            }
            #pragma unroll
            for (int nt = 0; nt < 8; nt++) {
                uint32_t bF[2];
                int s = kk + (lane & 3);
                int n = nt * 8 + (lane >> 2);
                bF[0] = __float_as_uint(Vs[s * VS_STR + n]);
                bF[1] = __float_as_uint(Vs[(s + 4) * VS_STR + n]);
                mma_tf32(oacc[nt], aF, bF);
            }
        }
    }

    float li0 = 1.0f / l0, li1 = 1.0f / l1;
    {
        int r_g0 = b * NT + grow0;
        int r_g1 = b * NT + grow1;
        #pragma unroll
        for (int nt = 0; nt < 8; nt++) {
            int c = h * NHS + nt * 8 + (lane & 3) * 2;
            __nv_bfloat162 p0 = __floats2bfloat162_rn(oacc[nt][0] * li0, oacc[nt][1] * li0);
            __nv_bfloat162 p1 = __floats2bfloat162_rn(oacc[nt][2] * li1, oacc[nt][3] * li1);
            *(__nv_bfloat162*)&g_attn[(size_t)r_g0 * ND + c] = p0;
            *(__nv_bfloat162*)&g_attn[(size_t)r_g1 * ND + c] = p1;
        }
    }
}

// ---------------- SwiGLU elementwise (vectorized, bf16 output) ------------
__global__ void swiglu_kernel()
{
    int idx = blockIdx.x * blockDim.x + threadIdx.x;
    if (idx >= NBT * NHALF / 4) return;
    int row = idx / (NHALF / 4);
    int c4  = (idx % (NHALF / 4)) * 4;
    float4 a = *(const float4*)&g_u[(size_t)row * NFF + c4];
    float4 z = *(const float4*)&g_u[(size_t)row * NFF + NHALF + c4];
    float r0 = a.x * (z.x / (1.0f + __expf(-z.x)));
    float r1 = a.y * (z.y / (1.0f + __expf(-z.y)));
    float r2 = a.z * (z.z / (1.0f + __expf(-z.z)));
    float r3 = a.w * (z.w / (1.0f + __expf(-z.w)));
    __nv_bfloat162 p0 = __floats2bfloat162_rn(r0, r1);
    __nv_bfloat162 p1 = __floats2bfloat162_rn(r2, r3);
    uint2 pk = make_uint2(*(uint32_t*)&p0, *(uint32_t*)&p1);
    *(uint2*)&g_gl[(size_t)row * NHALF + c4] = pk;
}

// ---------------- launch ----------------
extern "C" void kernel_launch(void* const* d_in, const int* in_sizes, int n_in,
                              void* d_out, int out_size)
{
    const float* x  = (const float*)d_in[0];
    const float* Wq = (const float*)d_in[1];
    const float* Wk = (const float*)d_in[2];
    const float* Wv = (const float*)d_in[3];
    const float* Wo = (const float*)d_in[4];
    const float* bo = (const float*)d_in[5];
    const float* W1 = (const float*)d_in[6];
    const float* b1 = (const float*)d_in[7];
    const float* W2 = (const float*)d_in[8];
    const float* b2 = (const float*)d_in[9];
    const float* g1 = (const float*)d_in[10];
    const float* g2 = (const float*)d_in[11];
    float* out = (float*)d_out;

    const int ASMEM = (128 * QS_STR + 64 * KS_STR + 64 * VS_STR + 128 * PS_STR)
                      * (int)sizeof(float);   // 105472 B
    cudaFuncSetAttribute(attn_mma_kernel, cudaFuncAttributeMaxDynamicSharedMemorySize, ASMEM);
    cudaFuncSetAttribute(gemm_qkv_kernel,  cudaFuncAttributeMaxDynamicSharedMemorySize, GEMM_SMEM);
    cudaFuncSetAttribute(gemm_o_kernel,    cudaFuncAttributeMaxDynamicSharedMemorySize, GEMM_SMEM);
    cudaFuncSetAttribute(gemm_ffn1_kernel, cudaFuncAttributeMaxDynamicSharedMemorySize, GEMM_SMEM);
    cudaFuncSetAttribute(gemm_ffn2_kernel, cudaFuncAttributeMaxDynamicSharedMemorySize, GEMM_SMEM);

    pack_wqkv_kernel<<<(3 * ND * ND + 255) / 256, 256>>>(Wq, Wk, Wv);
    round_weights_kernel<<<(W1_N + 255) / 256, 256>>>(Wo, W1, W2);
    rmsnorm1_kernel<<<NBT, 256>>>(x, g1);
    gemm_qkv_kernel<<<dim3(3 * ND / 128, NBT / 128), 256, GEMM_SMEM>>>();
    attn_mma_kernel<<<dim3(NT / 128, NH, NB), 256, ASMEM>>>();
    gemm_o_kernel<<<dim3(ND / 128, NBT / 128), 256, GEMM_SMEM>>>(bo, x);
    rmsnorm2_kernel<<<NBT, 256>>>(g2);
    gemm_ffn1_kernel<<<dim3(NFF / 128, NBT / 128), 256, GEMM_SMEM>>>(b1);
    swiglu_kernel<<<(NBT * NHALF / 4 + 255) / 256, 256>>>();
    gemm_ffn2_kernel<<<dim3(ND / 128, NBT / 128), 256, GEMM_SMEM>>>(b2, out);
}

// round 8
// speedup vs baseline: 1.2642x; 1.0085x over previous
#include <cuda_runtime.h>
#include <cuda_bf16.h>
#include <math.h>
#include <stdint.h>

// Problem constants
#define NB    2
#define NT    2048
#define ND    768
#define NH    12
#define NHS   64
#define NFF   3072
#define NHALF 1536
#define NBT   (NB*NT)   // 4096

// ---------------- scratch (device globals; no allocation) ----------------
__device__ __nv_bfloat16 g_h   [NBT * ND];
__device__ float         g_qkv [NBT * 3 * ND];
__device__ __nv_bfloat16 g_attn[NBT * ND];
__device__ float         g_x1  [NBT * ND];
__device__ float         g_u   [NBT * NFF];
__device__ __nv_bfloat16 g_gl  [NBT * NHALF];
__device__ __nv_bfloat16 g_wqkv_t[3 * ND * ND];   // [2304 n][768 k]
__device__ __nv_bfloat16 g_wo_t  [ND * ND];       // [768 n][768 k]
__device__ __nv_bfloat16 g_w1_t  [NFF * ND];      // [3072 n][768 k]
__device__ __nv_bfloat16 g_w2_t  [ND * NHALF];    // [768 n][1536 k]

// ---------------- async copy helpers ----------------
__device__ __forceinline__ void cp_async16(void* smem_dst, const void* gmem_src)
{
    uint32_t d = (uint32_t)__cvta_generic_to_shared(smem_dst);
    asm volatile("cp.async.cg.shared.global [%0], [%1], 16;\n" :: "r"(d), "l"(gmem_src));
}
#define CP_COMMIT() asm volatile("cp.async.commit_group;\n" ::: "memory")
#define CP_WAIT1()  asm volatile("cp.async.wait_group 1;\n" ::: "memory")
#define CP_WAIT0()  asm volatile("cp.async.wait_group 0;\n" ::: "memory")

// ---------------- ldmatrix ----------------
__device__ __forceinline__ void ldsm_x4(uint32_t& r0, uint32_t& r1,
                                        uint32_t& r2, uint32_t& r3, uint32_t addr)
{
    asm volatile("ldmatrix.sync.aligned.m8n8.x4.shared.b16 {%0,%1,%2,%3}, [%4];"
                 : "=r"(r0), "=r"(r1), "=r"(r2), "=r"(r3) : "r"(addr));
}

// ---------------- TF32 helpers (attention path) ----------------
__device__ __forceinline__ float tf32r(float x)
{
    uint32_t r;
    asm("cvt.rna.tf32.f32 %0, %1;" : "=r"(r) : "f"(x));
    return __uint_as_float(r);
}

__device__ __forceinline__ void mma_tf32(float* c, const uint32_t* a, const uint32_t* b)
{
    asm volatile(
        "mma.sync.aligned.m16n8k8.row.col.f32.tf32.tf32.f32 "
        "{%0,%1,%2,%3}, {%4,%5,%6,%7}, {%8,%9}, {%0,%1,%2,%3};\n"
        : "+f"(c[0]), "+f"(c[1]), "+f"(c[2]), "+f"(c[3])
        : "r"(a[0]), "r"(a[1]), "r"(a[2]), "r"(a[3]), "r"(b[0]), "r"(b[1]));
}

// ---------------- BF16 MMA ----------------
__device__ __forceinline__ void mma_bf16(float* c, const uint32_t* a, const uint32_t* b)
{
    asm volatile(
        "mma.sync.aligned.m16n8k16.row.col.f32.bf16.bf16.f32 "
        "{%0,%1,%2,%3}, {%4,%5,%6,%7}, {%8,%9}, {%0,%1,%2,%3};\n"
        : "+f"(c[0]), "+f"(c[1]), "+f"(c[2]), "+f"(c[3])
        : "r"(a[0]), "r"(a[1]), "r"(a[2]), "r"(a[3]), "r"(b[0]), "r"(b[1]));
}

// ---------------- pack Wq/Wk/Wv -> [2304 n][768 k] bf16 ----------------
__global__ void pack_wqkv_kernel(const float* __restrict__ Wq,
                                 const float* __restrict__ Wk,
                                 const float* __restrict__ Wv)
{
    int idx = blockIdx.x * blockDim.x + threadIdx.x;
    const int total = 3 * ND * ND;
    if (idx >= total) return;
    int n = idx / ND;
    int d = idx % ND;
    int m = n / ND;
    int r = n % ND;
    int h = r / NHS;
    int k = r % NHS;
    const float* W = (m == 0) ? Wq : ((m == 1) ? Wk : Wv);
    g_wqkv_t[idx] = __float2bfloat16(W[h * ND * NHS + d * NHS + k]);
}

// ---------------- transpose + bf16 Wo/W1/W2 ----------------
#define WO_N (ND * ND)
#define W1_N (ND * NFF)
#define W2_N (NHALF * ND)
__global__ void round_weights_kernel(const float* __restrict__ Wo,
                                     const float* __restrict__ W1,
                                     const float* __restrict__ W2)
{
    int idx = blockIdx.x * blockDim.x + threadIdx.x;
    if (idx < WO_N) {
        int n = idx / ND, k = idx % ND;
        g_wo_t[idx] = __float2bfloat16(Wo[k * ND + n]);
    }
    if (idx < W1_N) {
        int n = idx / ND, k = idx % ND;
        g_w1_t[idx] = __float2bfloat16(W1[k * NFF + n]);
    }
    if (idx < W2_N) {
        int n = idx / NHALF, k = idx % NHALF;
        g_w2_t[idx] = __float2bfloat16(W2[k * ND + n]);
    }
}

// ---------------- RMSNorm (bf16 output) ----------------
__device__ __forceinline__ void rms_body(const float* __restrict__ in,
                                         __nv_bfloat16* __restrict__ out,
                                         const float* __restrict__ g)
{
    int tid = threadIdx.x;
    float v0 = in[tid], v1 = in[tid + 256], v2 = in[tid + 512];
    float ss = v0*v0 + v1*v1 + v2*v2;
    #pragma unroll
    for (int o = 16; o; o >>= 1) ss += __shfl_xor_sync(0xffffffffu, ss, o);
    __shared__ float ws[8];
    __shared__ float s_inv;
    if ((tid & 31) == 0) ws[tid >> 5] = ss;
    __syncthreads();
    if (tid == 0) {
        float t = 0.f;
        #pragma unroll
        for (int i = 0; i < 8; i++) t += ws[i];
        float rms = sqrtf(t * (1.0f / (float)ND));
        s_inv = 1.0f / (rms + 1e-8f);
    }
    __syncthreads();
    float inv = s_inv;
    out[tid]       = __float2bfloat16(g[tid]       * v0 * inv);
    out[tid + 256] = __float2bfloat16(g[tid + 256] * v1 * inv);
    out[tid + 512] = __float2bfloat16(g[tid + 512] * v2 * inv);
}

__global__ __launch_bounds__(256) void rmsnorm1_kernel(const float* __restrict__ x,
                                                       const float* __restrict__ g)
{
    int row = blockIdx.x;
    rms_body(x + (size_t)row * ND, g_h + (size_t)row * ND, g);
}

__global__ __launch_bounds__(256) void rmsnorm2_kernel(const float* __restrict__ g)
{
    int row = blockIdx.x;
    rms_body(g_x1 + (size_t)row * ND, g_h + (size_t)row * ND, g);
}

// ---------------- BF16 GEMM: 128x128x64, 3-stage cp.async + ldmatrix ------
// One __syncthreads per chunk: after the sync at iter i, every warp has
// finished computing chunk i-1, so stage (i+2)%3 (== (i-1)%3) is free to fill.
#define KC 64
#define STR32 36
#define STAGE32 (128 * STR32)
#define GEMM_SMEM (6 * STAGE32 * 4)   // 3 stages * (A+B) = 110592 B

template<int N, int K, bool BIAS, bool RES, bool ROUND>
__device__ __forceinline__ void bf16_gemm_body(const __nv_bfloat16* __restrict__ A,
                                               const __nv_bfloat16* __restrict__ Bt,
                                               float* __restrict__ C,
                                               const float* __restrict__ bias,
                                               const float* __restrict__ res)
{
    extern __shared__ __align__(16) uint32_t smu[];
    uint32_t* As = smu;                 // [3][128][36] b32
    uint32_t* Bs = smu + 3 * STAGE32;   // [3][128][36] b32

    const int tid  = threadIdx.x;
    const int warp = tid >> 5, lane = tid & 31;
    const int wm = (warp >> 1) * 32;
    const int wn = (warp & 1) * 64;
    const int bm = blockIdx.y * 128;
    const int bn = blockIdx.x * 128;

    const uint32_t s_smu = (uint32_t)__cvta_generic_to_shared(smu);

    const int lrow = tid >> 1;
    const int lch  = (tid & 1) * 4;

    const uint32_t a_off0 = (uint32_t)(wm + (lane & 15)) * 144u + ((lane >> 4) << 4);
    const uint32_t b_off0 = (uint32_t)(wn + (lane & 7) + ((lane >> 4) << 3)) * 144u
                          + (((lane >> 3) & 1) << 4);

    float acc[2][8][4];
    #pragma unroll
    for (int i = 0; i < 2; i++)
        #pragma unroll
        for (int j = 0; j < 8; j++)
            #pragma unroll
            for (int t = 0; t < 4; t++) acc[i][j][t] = 0.f;

    const int NCH = K / KC;

    // prologue: issue chunks 0 and 1 into stages 0 and 1
    #pragma unroll
    for (int s = 0; s < 2; s++) {
        uint32_t* as = As + s * STAGE32;
        uint32_t* bs = Bs + s * STAGE32;
        const int k0 = s * KC;
        #pragma unroll
        for (int i = 0; i < 4; i++) {
            int ch = lch + i;
            cp_async16(&as[lrow * STR32 + ch * 4],
                       A  + (size_t)(bm + lrow) * K + k0 + ch * 8);
            cp_async16(&bs[lrow * STR32 + ch * 4],
                       Bt + (size_t)(bn + lrow) * K + k0 + ch * 8);
        }
        CP_COMMIT();
    }

    int cur = 0;       // stage of current chunk
    int nst = 2;       // stage for chunk+2
    #pragma unroll 1
    for (int chunk = 0; chunk < NCH; chunk++) {
        // Ensure chunk's group is done. Pending before any commit this iter:
        //   chunk <= NCH-2: {G(chunk), G(chunk+1)} -> wait_group(1)
        //   chunk == NCH-1: {G(chunk)}             -> wait_group(0)
        if (chunk == NCH - 1) { CP_WAIT0(); } else { CP_WAIT1(); }
        __syncthreads();   // all warps done computing chunk-1 -> stage nst free

        if (chunk + 2 < NCH) {
            const int k0 = (chunk + 2) * KC;
            uint32_t* as = As + nst * STAGE32;
            uint32_t* bs = Bs + nst * STAGE32;
            #pragma unroll
            for (int i = 0; i < 4; i++) {
                int ch = lch + i;
                cp_async16(&as[lrow * STR32 + ch * 4],
                           A  + (size_t)(bm + lrow) * K + k0 + ch * 8);
                cp_async16(&bs[lrow * STR32 + ch * 4],
                           Bt + (size_t)(bn + lrow) * K + k0 + ch * 8);
            }
            CP_COMMIT();
        }

        const uint32_t as_b = s_smu + (uint32_t)(cur * STAGE32 * 4) + a_off0;
        const uint32_t bs_b = s_smu + (uint32_t)((3 + cur) * STAGE32 * 4) + b_off0;

        #pragma unroll
        for (int kk = 0; kk < KC; kk += 16) {
            uint32_t aF[2][4], bF[8][2];
            #pragma unroll
            for (int mt = 0; mt < 2; mt++)
                ldsm_x4(aF[mt][0], aF[mt][1], aF[mt][2], aF[mt][3],
                        as_b + (uint32_t)(mt * 16 * 144) + (uint32_t)(kk * 2));
            #pragma unroll
            for (int p = 0; p < 4; p++)
                ldsm_x4(bF[2*p][0], bF[2*p][1], bF[2*p+1][0], bF[2*p+1][1],
                        bs_b + (uint32_t)(p * 16 * 144) + (uint32_t)(kk * 2));
            #pragma unroll
            for (int mt = 0; mt < 2; mt++)
                #pragma unroll
                for (int nt = 0; nt < 8; nt++)
                    mma_bf16(acc[mt][nt], aF[mt], bF[nt]);
        }

        cur = (cur == 2) ? 0 : cur + 1;
        nst = (nst == 2) ? 0 : nst + 1;
    }

    #pragma unroll
    for (int mt = 0; mt < 2; mt++) {
        #pragma unroll
        for (int nt = 0; nt < 8; nt++) {
            int row0 = bm + wm + mt * 16 + (lane >> 2);
            int col  = bn + wn + nt * 8 + (lane & 3) * 2;
            float2 v0 = make_float2(acc[mt][nt][0], acc[mt][nt][1]);
            float2 v1 = make_float2(acc[mt][nt][2], acc[mt][nt][3]);
            if constexpr (BIAS) {
                float2 bb = *(const float2*)(bias + col);
                v0.x += bb.x; v0.y += bb.y;
                v1.x += bb.x; v1.y += bb.y;
            }
            if constexpr (RES) {
                float2 r0 = *(const float2*)(res + (size_t)row0 * N + col);
                float2 r1 = *(const float2*)(res + (size_t)(row0 + 8) * N + col);
                v0.x += r0.x; v0.y += r0.y;
                v1.x += r1.x; v1.y += r1.y;
            }
            if constexpr (ROUND) {
                v0.x = tf32r(v0.x); v0.y = tf32r(v0.y);
                v1.x = tf32r(v1.x); v1.y = tf32r(v1.y);
            }
            *(float2*)(C + (size_t)row0 * N + col)       = v0;
            *(float2*)(C + (size_t)(row0 + 8) * N + col) = v1;
        }
    }
}

__global__ __launch_bounds__(256) void gemm_qkv_kernel()
{
    bf16_gemm_body<3 * ND, ND, false, false, true>(g_h, g_wqkv_t, g_qkv, nullptr, nullptr);
}
__global__ __launch_bounds__(256) void gemm_o_kernel(const float* __restrict__ bo,
                                                     const float* __restrict__ x)
{
    bf16_gemm_body<ND, ND, true, true, false>(g_attn, g_wo_t, g_x1, bo, x);
}
__global__ __launch_bounds__(256) void gemm_ffn1_kernel(const float* __restrict__ b1)
{
    bf16_gemm_body<NFF, ND, true, false, false>(g_h, g_w1_t, g_u, b1, nullptr);
}
__global__ __launch_bounds__(256) void gemm_ffn2_kernel(const float* __restrict__ b2,
                                                        float* __restrict__ out)
{
    bf16_gemm_body<ND, NHALF, true, true, false>(g_gl, g_w2_t, out, b2, g_x1);
}

// ---------------- Flash attention with tf32 MMA + register prefetch -------
#define QS_STR 68
#define KS_STR 68
#define VS_STR 72
#define PS_STR 68

__global__ __launch_bounds__(256) void attn_mma_kernel()
{
    extern __shared__ float sm[];
    float* Qs = sm;                      // [128][68]
    float* Ks = Qs + 128 * QS_STR;       // [64][68]
    float* Vs = Ks + 64 * KS_STR;        // [64][72]
    float* Ps = Vs + 64 * VS_STR;        // [128][68]

    const int tid  = threadIdx.x;
    const int warp = tid >> 5, lane = tid & 31;
    const int qb = (int)gridDim.x - 1 - (int)blockIdx.x;
    const int h  = blockIdx.y;
    const int b  = blockIdx.z;
    const int row0 = qb * 128;
    const int wrow = warp * 16;

    const int lr = tid >> 4;
    const int lc = (tid & 15) * 4;

    #pragma unroll
    for (int r = 0; r < 8; r++) {
        int row = lr + 16 * r;
        float4 v = *(const float4*)&g_qkv[(size_t)(b * NT + row0 + row) * (3 * ND)
                                          + h * NHS + lc];
        *(float4*)&Qs[row * QS_STR + lc] = v;
    }

    float oacc[8][4];
    #pragma unroll
    for (int nt = 0; nt < 8; nt++)
        #pragma unroll
        for (int t = 0; t < 4; t++) oacc[nt][t] = 0.f;

    float m0 = -1e30f, m1 = -1e30f, l0 = 0.f, l1 = 0.f;
    const float scale = 0.03608439182435161f;   // 768^-0.5

    const int grow0 = row0 + wrow + (lane >> 2);
    const int grow1 = grow0 + 8;
    const int jb_max = 2 * qb + 1;

    float4 kpre[4], vpre[4];
    #pragma unroll
    for (int r = 0; r < 4; r++) {
        int row = lr + 16 * r;
        size_t base = (size_t)(b * NT + row) * (3 * ND) + h * NHS + lc;
        kpre[r] = *(const float4*)&g_qkv[ND + base];
        vpre[r] = *(const float4*)&g_qkv[2 * ND + base];
    }

    for (int jb = 0; jb <= jb_max; jb++) {
        __syncthreads();
        #pragma unroll
        for (int r = 0; r < 4; r++) {
            int row = lr + 16 * r;
            *(float4*)&Ks[row * KS_STR + lc] = kpre[r];
            *(float4*)&Vs[row * VS_STR + lc] = vpre[r];
        }
        __syncthreads();

        if (jb < jb_max) {
            #pragma unroll
            for (int r = 0; r < 4; r++) {
                int row = lr + 16 * r;
                size_t base = (size_t)(b * NT + (jb + 1) * 64 + row) * (3 * ND)
                              + h * NHS + lc;
                kpre[r] = *(const float4*)&g_qkv[ND + base];
                vpre[r] = *(const float4*)&g_qkv[2 * ND + base];
            }
        }

        float sacc[8][4];
        #pragma unroll
        for (int nt = 0; nt < 8; nt++)
            #pragma unroll
            for (int t = 0; t < 4; t++) sacc[nt][t] = 0.f;

        #pragma unroll
        for (int kk = 0; kk < 64; kk += 8) {
            uint32_t aF[4];
            {
                int r = wrow + (lane >> 2);
                int c = kk + (lane & 3);
                aF[0] = __float_as_uint(Qs[r * QS_STR + c]);
                aF[1] = __float_as_uint(Qs[(r + 8) * QS_STR + c]);
                aF[2] = __float_as_uint(Qs[r * QS_STR + c + 4]);
                aF[3] = __float_as_uint(Qs[(r + 8) * QS_STR + c + 4]);
            }
            #pragma unroll
            for (int nt = 0; nt < 8; nt++) {
                uint32_t bF[2];
                int n = nt * 8 + (lane >> 2);
                int c = kk + (lane & 3);
                bF[0] = __float_as_uint(Ks[n * KS_STR + c]);
                bF[1] = __float_as_uint(Ks[n * KS_STR + c + 4]);
                mma_tf32(sacc[nt], aF, bF);
            }
        }

        #pragma unroll
        for (int nt = 0; nt < 8; nt++) {
            int gcol = jb * 64 + nt * 8 + (lane & 3) * 2;
            float v0 = sacc[nt][0] * scale;
            float v1 = sacc[nt][1] * scale;
            float v2 = sacc[nt][2] * scale;
            float v3 = sacc[nt][3] * scale;
            if (gcol     > grow0) v0 = -1e30f;
            if (gcol + 1 > grow0) v1 = -1e30f;
            if (gcol     > grow1) v2 = -1e30f;
            if (gcol + 1 > grow1) v3 = -1e30f;
            sacc[nt][0] = v0; sacc[nt][1] = v1;
            sacc[nt][2] = v2; sacc[nt][3] = v3;
        }

        float mx0 = -1e30f, mx1 = -1e30f;
        #pragma unroll
        for (int nt = 0; nt < 8; nt++) {
            mx0 = fmaxf(mx0, fmaxf(sacc[nt][0], sacc[nt][1]));
            mx1 = fmaxf(mx1, fmaxf(sacc[nt][2], sacc[nt][3]));
        }
        mx0 = fmaxf(mx0, __shfl_xor_sync(0xffffffffu, mx0, 1));
        mx0 = fmaxf(mx0, __shfl_xor_sync(0xffffffffu, mx0, 2));
        mx1 = fmaxf(mx1, __shfl_xor_sync(0xffffffffu, mx1, 1));
        mx1 = fmaxf(mx1, __shfl_xor_sync(0xffffffffu, mx1, 2));

        float mn0 = fmaxf(m0, mx0);
        float mn1 = fmaxf(m1, mx1);

        float s0 = 0.f, s1 = 0.f;
        #pragma unroll
        for (int nt = 0; nt < 8; nt++) {
            float p0 = __expf(sacc[nt][0] - mn0);
            float p1 = __expf(sacc[nt][1] - mn0);
            float p2 = __expf(sacc[nt][2] - mn1);
            float p3 = __expf(sacc[nt][3] - mn1);
            sacc[nt][0] = p0; sacc[nt][1] = p1;
            sacc[nt][2] = p2; sacc[nt][3] = p3;
            s0 += p0 + p1;
            s1 += p2 + p3;
        }
        s0 += __shfl_xor_sync(0xffffffffu, s0, 1);
        s0 += __shfl_xor_sync(0xffffffffu, s0, 2);
        s1 += __shfl_xor_sync(0xffffffffu, s1, 1);
        s1 += __shfl_xor_sync(0xffffffffu, s1, 2);

        float al0 = __expf(m0 - mn0);
        float al1 = __expf(m1 - mn1);
        l0 = l0 * al0 + s0;
        l1 = l1 * al1 + s1;
        m0 = mn0; m1 = mn1;

        #pragma unroll
        for (int nt = 0; nt < 8; nt++) {
            oacc[nt][0] *= al0; oacc[nt][1] *= al0;
            oacc[nt][2] *= al1; oacc[nt][3] *= al1;
        }

        {
            int r = wrow + (lane >> 2);
            #pragma unroll
            for (int nt = 0; nt < 8; nt++) {
                int c = nt * 8 + (lane & 3) * 2;
                *(float2*)&Ps[r * PS_STR + c]       = make_float2(sacc[nt][0], sacc[nt][1]);
                *(float2*)&Ps[(r + 8) * PS_STR + c] = make_float2(sacc[nt][2], sacc[nt][3]);
            }
        }
        __syncwarp();

        #pragma unroll
        for (int kk = 0; kk < 64; kk += 8) {
            uint32_t aF[4];
            {
                int r = wrow + (lane >> 2);
                int c = kk + (lane & 3);
                aF[0] = __float_as_uint(Ps[r * PS_STR + c]);
                aF[1] = __float_as_uint(Ps[(r + 8) * PS_STR + c]);
                aF[2] = __float_as_uint(Ps[r * PS_STR + c + 4]);
                aF[3] = __float_as_uint(Ps[(r + 8) * PS_STR + c + 4]);
            }
            #pragma unroll
            for (int nt = 0; nt < 8; nt++) {
                uint32_t bF[2];
                int s = kk + (lane & 3);
                int n = nt * 8 + (lane >> 2);
                bF[0] = __float_as_uint(Vs[s * VS_STR + n]);
                bF[1] = __float_as_uint(Vs[(s + 4) * VS_STR + n]);
                mma_tf32(oacc[nt], aF, bF);
            }
        }
    }

    float li0 = 1.0f / l0, li1 = 1.0f / l1;
    {
        int r_g0 = b * NT + grow0;
        int r_g1 = b * NT + grow1;
        #pragma unroll
        for (int nt = 0; nt < 8; nt++) {
            int c = h * NHS + nt * 8 + (lane & 3) * 2;
            __nv_bfloat162 p0 = __floats2bfloat162_rn(oacc[nt][0] * li0, oacc[nt][1] * li0);
            __nv_bfloat162 p1 = __floats2bfloat162_rn(oacc[nt][2] * li1, oacc[nt][3] * li1);
            *(__nv_bfloat162*)&g_attn[(size_t)r_g0 * ND + c] = p0;
            *(__nv_bfloat162*)&g_attn[(size_t)r_g1 * ND + c] = p1;
        }
    }
}

// ---------------- SwiGLU elementwise (vectorized, bf16 output) ------------
__global__ void swiglu_kernel()
{
    int idx = blockIdx.x * blockDim.x + threadIdx.x;
    if (idx >= NBT * NHALF / 4) return;
    int row = idx / (NHALF / 4);
    int c4  = (idx % (NHALF / 4)) * 4;
    float4 a = *(const float4*)&g_u[(size_t)row * NFF + c4];
    float4 z = *(const float4*)&g_u[(size_t)row * NFF + NHALF + c4];
    float r0 = a.x * (z.x / (1.0f + __expf(-z.x)));
    float r1 = a.y * (z.y / (1.0f + __expf(-z.y)));
    float r2 = a.z * (z.z / (1.0f + __expf(-z.z)));
    float r3 = a.w * (z.w / (1.0f + __expf(-z.w)));
    __nv_bfloat162 p0 = __floats2bfloat162_rn(r0, r1);
    __nv_bfloat162 p1 = __floats2bfloat162_rn(r2, r3);
    uint2 pk = make_uint2(*(uint32_t*)&p0, *(uint32_t*)&p1);
    *(uint2*)&g_gl[(size_t)row * NHALF + c4] = pk;
}

// ---------------- launch ----------------
extern "C" void kernel_launch(void* const* d_in, const int* in_sizes, int n_in,
                              void* d_out, int out_size)
{
    const float* x  = (const float*)d_in[0];
    const float* Wq = (const float*)d_in[1];
    const float* Wk = (const float*)d_in[2];
    const float* Wv = (const float*)d_in[3];
    const float* Wo = (const float*)d_in[4];
    const float* bo = (const float*)d_in[5];
    const float* W1 = (const float*)d_in[6];
    const float* b1 = (const float*)d_in[7];
    const float* W2 = (const float*)d_in[8];
    const float* b2 = (const float*)d_in[9];
    const float* g1 = (const float*)d_in[10];
    const float* g2 = (const float*)d_in[11];
    float* out = (float*)d_out;

    const int ASMEM = (128 * QS_STR + 64 * KS_STR + 64 * VS_STR + 128 * PS_STR)
                      * (int)sizeof(float);   // 105472 B
    cudaFuncSetAttribute(attn_mma_kernel, cudaFuncAttributeMaxDynamicSharedMemorySize, ASMEM);
    cudaFuncSetAttribute(gemm_qkv_kernel,  cudaFuncAttributeMaxDynamicSharedMemorySize, GEMM_SMEM);
    cudaFuncSetAttribute(gemm_o_kernel,    cudaFuncAttributeMaxDynamicSharedMemorySize, GEMM_SMEM);
    cudaFuncSetAttribute(gemm_ffn1_kernel, cudaFuncAttributeMaxDynamicSharedMemorySize, GEMM_SMEM);
    cudaFuncSetAttribute(gemm_ffn2_kernel, cudaFuncAttributeMaxDynamicSharedMemorySize, GEMM_SMEM);

    pack_wqkv_kernel<<<(3 * ND * ND + 255) / 256, 256>>>(Wq, Wk, Wv);
    round_weights_kernel<<<(W1_N + 255) / 256, 256>>>(Wo, W1, W2);
    rmsnorm1_kernel<<<NBT, 256>>>(x, g1);
    gemm_qkv_kernel<<<dim3(3 * ND / 128, NBT / 128), 256, GEMM_SMEM>>>();
    attn_mma_kernel<<<dim3(NT / 128, NH, NB), 256, ASMEM>>>();
    gemm_o_kernel<<<dim3(ND / 128, NBT / 128), 256, GEMM_SMEM>>>(bo, x);
    rmsnorm2_kernel<<<NBT, 256>>>(g2);
    gemm_ffn1_kernel<<<dim3(NFF / 128, NBT / 128), 256, GEMM_SMEM>>>(b1);
    swiglu_kernel<<<(NBT * NHALF / 4 + 255) / 256, 256>>>();
    gemm_ffn2_kernel<<<dim3(ND / 128, NBT / 128), 256, GEMM_SMEM>>>(b2, out);
}

// round 10
// speedup vs baseline: 1.5695x; 1.2415x over previous
#include <cuda_runtime.h>
#include <cuda_bf16.h>
#include <math.h>
#include <stdint.h>

// Problem constants
#define NB    2
#define NT    2048
#define ND    768
#define NH    12
#define NHS   64
#define NFF   3072
#define NHALF 1536
#define NBT   (NB*NT)   // 4096

// ---------------- scratch (device globals; no allocation) ----------------
__device__ __nv_bfloat16 g_h   [NBT * ND];
__device__ __nv_bfloat16 g_qkv [NBT * 3 * ND];    // bf16 now
__device__ __nv_bfloat16 g_attn[NBT * ND];
__device__ float         g_x1  [NBT * ND];
__device__ float         g_u   [NBT * NFF];
__device__ __nv_bfloat16 g_gl  [NBT * NHALF];
__device__ __nv_bfloat16 g_wqkv_t[3 * ND * ND];   // [2304 n][768 k]
__device__ __nv_bfloat16 g_wo_t  [ND * ND];       // [768 n][768 k]
__device__ __nv_bfloat16 g_w1_t  [NFF * ND];      // [3072 n][768 k]
__device__ __nv_bfloat16 g_w2_t  [ND * NHALF];    // [768 n][1536 k]

// ---------------- async copy helpers ----------------
__device__ __forceinline__ void cp_async16(void* smem_dst, const void* gmem_src)
{
    uint32_t d = (uint32_t)__cvta_generic_to_shared(smem_dst);
    asm volatile("cp.async.cg.shared.global [%0], [%1], 16;\n" :: "r"(d), "l"(gmem_src));
}
#define CP_COMMIT() asm volatile("cp.async.commit_group;\n" ::: "memory")
#define CP_WAIT1()  asm volatile("cp.async.wait_group 1;\n" ::: "memory")
#define CP_WAIT0()  asm volatile("cp.async.wait_group 0;\n" ::: "memory")

// ---------------- ldmatrix ----------------
__device__ __forceinline__ void ldsm_x4(uint32_t& r0, uint32_t& r1,
                                        uint32_t& r2, uint32_t& r3, uint32_t addr)
{
    asm volatile("ldmatrix.sync.aligned.m8n8.x4.shared.b16 {%0,%1,%2,%3}, [%4];"
                 : "=r"(r0), "=r"(r1), "=r"(r2), "=r"(r3) : "r"(addr));
}
__device__ __forceinline__ void ldsm_x4_t(uint32_t& r0, uint32_t& r1,
                                          uint32_t& r2, uint32_t& r3, uint32_t addr)
{
    asm volatile("ldmatrix.sync.aligned.m8n8.x4.trans.shared.b16 {%0,%1,%2,%3}, [%4];"
                 : "=r"(r0), "=r"(r1), "=r"(r2), "=r"(r3) : "r"(addr));
}

// ---------------- BF16 MMA ----------------
__device__ __forceinline__ void mma_bf16(float* c, const uint32_t* a, const uint32_t* b)
{
    asm volatile(
        "mma.sync.aligned.m16n8k16.row.col.f32.bf16.bf16.f32 "
        "{%0,%1,%2,%3}, {%4,%5,%6,%7}, {%8,%9}, {%0,%1,%2,%3};\n"
        : "+f"(c[0]), "+f"(c[1]), "+f"(c[2]), "+f"(c[3])
        : "r"(a[0]), "r"(a[1]), "r"(a[2]), "r"(a[3]), "r"(b[0]), "r"(b[1]));
}

__device__ __forceinline__ uint32_t packbf(float lo, float hi)
{
    __nv_bfloat162 p = __floats2bfloat162_rn(lo, hi);
    return *(uint32_t*)&p;
}

// ---------------- pack Wq/Wk/Wv -> [2304 n][768 k] bf16 ----------------
__global__ void pack_wqkv_kernel(const float* __restrict__ Wq,
                                 const float* __restrict__ Wk,
                                 const float* __restrict__ Wv)
{
    int idx = blockIdx.x * blockDim.x + threadIdx.x;
    const int total = 3 * ND * ND;
    if (idx >= total) return;
    int n = idx / ND;
    int d = idx % ND;
    int m = n / ND;
    int r = n % ND;
    int h = r / NHS;
    int k = r % NHS;
    const float* W = (m == 0) ? Wq : ((m == 1) ? Wk : Wv);
    g_wqkv_t[idx] = __float2bfloat16(W[h * ND * NHS + d * NHS + k]);
}

// ---------------- transpose + bf16 Wo/W1/W2 ----------------
#define WO_N (ND * ND)
#define W1_N (ND * NFF)
#define W2_N (NHALF * ND)
__global__ void round_weights_kernel(const float* __restrict__ Wo,
                                     const float* __restrict__ W1,
                                     const float* __restrict__ W2)
{
    int idx = blockIdx.x * blockDim.x + threadIdx.x;
    if (idx < WO_N) {
        int n = idx / ND, k = idx % ND;
        g_wo_t[idx] = __float2bfloat16(Wo[k * ND + n]);
    }
    if (idx < W1_N) {
        int n = idx / ND, k = idx % ND;
        g_w1_t[idx] = __float2bfloat16(W1[k * NFF + n]);
    }
    if (idx < W2_N) {
        int n = idx / NHALF, k = idx % NHALF;
        g_w2_t[idx] = __float2bfloat16(W2[k * ND + n]);
    }
}

// ---------------- RMSNorm (bf16 output) ----------------
__device__ __forceinline__ void rms_body(const float* __restrict__ in,
                                         __nv_bfloat16* __restrict__ out,
                                         const float* __restrict__ g)
{
    int tid = threadIdx.x;
    float v0 = in[tid], v1 = in[tid + 256], v2 = in[tid + 512];
    float ss = v0*v0 + v1*v1 + v2*v2;
    #pragma unroll
    for (int o = 16; o; o >>= 1) ss += __shfl_xor_sync(0xffffffffu, ss, o);
    __shared__ float ws[8];
    __shared__ float s_inv;
    if ((tid & 31) == 0) ws[tid >> 5] = ss;
    __syncthreads();
    if (tid == 0) {
        float t = 0.f;
        #pragma unroll
        for (int i = 0; i < 8; i++) t += ws[i];
        float rms = sqrtf(t * (1.0f / (float)ND));
        s_inv = 1.0f / (rms + 1e-8f);
    }
    __syncthreads();
    float inv = s_inv;
    out[tid]       = __float2bfloat16(g[tid]       * v0 * inv);
    out[tid + 256] = __float2bfloat16(g[tid + 256] * v1 * inv);
    out[tid + 512] = __float2bfloat16(g[tid + 512] * v2 * inv);
}

__global__ __launch_bounds__(256) void rmsnorm1_kernel(const float* __restrict__ x,
                                                       const float* __restrict__ g)
{
    int row = blockIdx.x;
    rms_body(x + (size_t)row * ND, g_h + (size_t)row * ND, g);
}

__global__ __launch_bounds__(256) void rmsnorm2_kernel(const float* __restrict__ g)
{
    int row = blockIdx.x;
    rms_body(g_x1 + (size_t)row * ND, g_h + (size_t)row * ND, g);
}

// ---------------- BF16 GEMM: 128x128x64, 3-stage cp.async + ldmatrix ------
// (R8 body, proven at 507.8us; output type templated: float or bf16)
#define KC 64
#define STR32 36
#define STAGE32 (128 * STR32)
#define GEMM_SMEM (6 * STAGE32 * 4)   // 110592 B

template<int N, int K, bool BIAS, bool RES, typename OutT>
__device__ __forceinline__ void bf16_gemm_body(const __nv_bfloat16* __restrict__ A,
                                               const __nv_bfloat16* __restrict__ Bt,
                                               OutT* __restrict__ C,
                                               const float* __restrict__ bias,
                                               const float* __restrict__ res)
{
    extern __shared__ __align__(16) uint32_t smu[];
    uint32_t* As = smu;                 // [3][128][36] b32
    uint32_t* Bs = smu + 3 * STAGE32;   // [3][128][36] b32

    const int tid  = threadIdx.x;
    const int warp = tid >> 5, lane = tid & 31;
    const int wm = (warp >> 1) * 32;
    const int wn = (warp & 1) * 64;
    const int bm = blockIdx.y * 128;
    const int bn = blockIdx.x * 128;

    const uint32_t s_smu = (uint32_t)__cvta_generic_to_shared(smu);

    const int lrow = tid >> 1;
    const int lch  = (tid & 1) * 4;

    const uint32_t a_off0 = (uint32_t)(wm + (lane & 15)) * 144u + ((lane >> 4) << 4);
    const uint32_t b_off0 = (uint32_t)(wn + (lane & 7) + ((lane >> 4) << 3)) * 144u
                          + (((lane >> 3) & 1) << 4);

    float acc[2][8][4];
    #pragma unroll
    for (int i = 0; i < 2; i++)
        #pragma unroll
        for (int j = 0; j < 8; j++)
            #pragma unroll
            for (int t = 0; t < 4; t++) acc[i][j][t] = 0.f;

    const int NCH = K / KC;

    #pragma unroll
    for (int s = 0; s < 2; s++) {
        uint32_t* as = As + s * STAGE32;
        uint32_t* bs = Bs + s * STAGE32;
        const int k0 = s * KC;
        #pragma unroll
        for (int i = 0; i < 4; i++) {
            int ch = lch + i;
            cp_async16(&as[lrow * STR32 + ch * 4],
                       A  + (size_t)(bm + lrow) * K + k0 + ch * 8);
            cp_async16(&bs[lrow * STR32 + ch * 4],
                       Bt + (size_t)(bn + lrow) * K + k0 + ch * 8);
        }
        CP_COMMIT();
    }

    int cur = 0;
    int nst = 2;
    #pragma unroll 1
    for (int chunk = 0; chunk < NCH; chunk++) {
        if (chunk == NCH - 1) { CP_WAIT0(); } else { CP_WAIT1(); }
        __syncthreads();

        if (chunk + 2 < NCH) {
            const int k0 = (chunk + 2) * KC;
            uint32_t* as = As + nst * STAGE32;
            uint32_t* bs = Bs + nst * STAGE32;
            #pragma unroll
            for (int i = 0; i < 4; i++) {
                int ch = lch + i;
                cp_async16(&as[lrow * STR32 + ch * 4],
                           A  + (size_t)(bm + lrow) * K + k0 + ch * 8);
                cp_async16(&bs[lrow * STR32 + ch * 4],
                           Bt + (size_t)(bn + lrow) * K + k0 + ch * 8);
            }
            CP_COMMIT();
        }

        const uint32_t as_b = s_smu + (uint32_t)(cur * STAGE32 * 4) + a_off0;
        const uint32_t bs_b = s_smu + (uint32_t)((3 + cur) * STAGE32 * 4) + b_off0;

        #pragma unroll
        for (int kk = 0; kk < KC; kk += 16) {
            uint32_t aF[2][4], bF[8][2];
            #pragma unroll
            for (int mt = 0; mt < 2; mt++)
                ldsm_x4(aF[mt][0], aF[mt][1], aF[mt][2], aF[mt][3],
                        as_b + (uint32_t)(mt * 16 * 144) + (uint32_t)(kk * 2));
            #pragma unroll
            for (int p = 0; p < 4; p++)
                ldsm_x4(bF[2*p][0], bF[2*p][1], bF[2*p+1][0], bF[2*p+1][1],
                        bs_b + (uint32_t)(p * 16 * 144) + (uint32_t)(kk * 2));
            #pragma unroll
            for (int mt = 0; mt < 2; mt++)
                #pragma unroll
                for (int nt = 0; nt < 8; nt++)
                    mma_bf16(acc[mt][nt], aF[mt], bF[nt]);
        }

        cur = (cur == 2) ? 0 : cur + 1;
        nst = (nst == 2) ? 0 : nst + 1;
    }

    #pragma unroll
    for (int mt = 0; mt < 2; mt++) {
        #pragma unroll
        for (int nt = 0; nt < 8; nt++) {
            int row0 = bm + wm + mt * 16 + (lane >> 2);
            int col  = bn + wn + nt * 8 + (lane & 3) * 2;
            float2 v0 = make_float2(acc[mt][nt][0], acc[mt][nt][1]);
            float2 v1 = make_float2(acc[mt][nt][2], acc[mt][nt][3]);
            if constexpr (BIAS) {
                float2 bb = *(const float2*)(bias + col);
                v0.x += bb.x; v0.y += bb.y;
                v1.x += bb.x; v1.y += bb.y;
            }
            if constexpr (RES) {
                float2 r0 = *(const float2*)(res + (size_t)row0 * N + col);
                float2 r1 = *(const float2*)(res + (size_t)(row0 + 8) * N + col);
                v0.x += r0.x; v0.y += r0.y;
                v1.x += r1.x; v1.y += r1.y;
            }
            if constexpr (sizeof(OutT) == 2) {
                *(uint32_t*)(C + (size_t)row0 * N + col)       = packbf(v0.x, v0.y);
                *(uint32_t*)(C + (size_t)(row0 + 8) * N + col) = packbf(v1.x, v1.y);
            } else {
                *(float2*)(C + (size_t)row0 * N + col)       = v0;
                *(float2*)(C + (size_t)(row0 + 8) * N + col) = v1;
            }
        }
    }
}

__global__ __launch_bounds__(256) void gemm_qkv_kernel()
{
    bf16_gemm_body<3 * ND, ND, false, false, __nv_bfloat16>(g_h, g_wqkv_t, g_qkv,
                                                            nullptr, nullptr);
}
__global__ __launch_bounds__(256) void gemm_o_kernel(const float* __restrict__ bo,
                                                     const float* __restrict__ x)
{
    bf16_gemm_body<ND, ND, true, true, float>(g_attn, g_wo_t, g_x1, bo, x);
}
__global__ __launch_bounds__(256) void gemm_ffn1_kernel(const float* __restrict__ b1)
{
    bf16_gemm_body<NFF, ND, true, false, float>(g_h, g_w1_t, g_u, b1, nullptr);
}
__global__ __launch_bounds__(256) void gemm_ffn2_kernel(const float* __restrict__ b2,
                                                        float* __restrict__ out)
{
    bf16_gemm_body<ND, NHALF, true, true, float>(g_gl, g_w2_t, out, b2, g_x1);
}

// ---------------- Flash attention, full bf16 MMA --------------------------
// 128 q-rows/block, 8 warps * 16 rows. S in C-frags; P packed to A-frags in
// registers (no smem round-trip). Q/K ldmatrix, V ldmatrix.trans.
// Smem rows: 72 bf16 = 144 B (GEMM-proven conflict-free ldmatrix stride).
#define AT_STR 72
#define ATT_SMEM ((128 + 64 + 64) * AT_STR * 2)   // 36864 B

__global__ __launch_bounds__(256) void attn_mma_kernel()
{
    extern __shared__ __align__(16) __nv_bfloat16 smb[];
    __nv_bfloat16* Qs = smb;                     // [128][72]
    __nv_bfloat16* Ks = Qs + 128 * AT_STR;       // [64][72]
    __nv_bfloat16* Vs = Ks + 64 * AT_STR;        // [64][72]

    const int tid  = threadIdx.x;
    const int warp = tid >> 5, lane = tid & 31;
    const int qb = (int)gridDim.x - 1 - (int)blockIdx.x;   // heavy blocks first
    const int h  = blockIdx.y;
    const int b  = blockIdx.z;
    const int row0 = qb * 128;
    const int wrow = warp * 16;

    const uint32_t sQ = (uint32_t)__cvta_generic_to_shared(Qs);
    const uint32_t sK = (uint32_t)__cvta_generic_to_shared(Ks);
    const uint32_t sV = (uint32_t)__cvta_generic_to_shared(Vs);

    // ---- load Q tile: 128 rows x 64 bf16 (row=tid>>1, 4x16B chunks) ----
    {
        int row = tid >> 1;
        int chb = (tid & 1) * 4;
        const __nv_bfloat16* qp = g_qkv + (size_t)(b * NT + row0 + row) * (3 * ND)
                                  + h * NHS;
        #pragma unroll
        for (int i = 0; i < 4; i++) {
            int ch = chb + i;
            *(uint4*)&Qs[row * AT_STR + ch * 8] = *(const uint4*)(qp + ch * 8);
        }
    }

    float oacc[8][4];
    #pragma unroll
    for (int nt = 0; nt < 8; nt++)
        #pragma unroll
        for (int t = 0; t < 4; t++) oacc[nt][t] = 0.f;

    float m0 = -1e30f, m1 = -1e30f, l0 = 0.f, l1 = 0.f;
    const float scale = 0.03608439182435161f;   // 768^-0.5

    const int grow0 = row0 + wrow + (lane >> 2);
    const int grow1 = grow0 + 8;
    const int jb_max = 2 * qb + 1;

    // K/V loader: row = tid>>2 (0..63), 2x16B chunks each
    const int kvrow = tid >> 2;
    const int kvch  = (tid & 3) * 2;

    uint4 kpre[2], vpre[2];
    {
        size_t base = (size_t)(b * NT + kvrow) * (3 * ND) + h * NHS;
        #pragma unroll
        for (int i = 0; i < 2; i++) {
            kpre[i] = *(const uint4*)(g_qkv + base + ND + (kvch + i) * 8);
            vpre[i] = *(const uint4*)(g_qkv + base + 2 * ND + (kvch + i) * 8);
        }
    }

    // ldmatrix base offsets (byte):
    const uint32_t qa_off = (uint32_t)(wrow + (lane & 15)) * 144u + ((lane >> 4) << 4);
    const uint32_t kb_off = (uint32_t)((lane & 7) + ((lane >> 4) << 3)) * 144u
                          + (((lane >> 3) & 1) << 4);
    const uint32_t vb_off = (uint32_t)((lane & 7) + (((lane >> 3) & 1) << 3)) * 144u
                          + ((lane >> 4) << 4);

    for (int jb = 0; jb <= jb_max; jb++) {
        __syncthreads();   // previous tile fully consumed
        #pragma unroll
        for (int i = 0; i < 2; i++) {
            *(uint4*)&Ks[kvrow * AT_STR + (kvch + i) * 8] = kpre[i];
            *(uint4*)&Vs[kvrow * AT_STR + (kvch + i) * 8] = vpre[i];
        }
        __syncthreads();

        // prefetch next tile (overlaps S-MMA + softmax + PV below)
        if (jb < jb_max) {
            size_t base = (size_t)(b * NT + (jb + 1) * 64 + kvrow) * (3 * ND) + h * NHS;
            #pragma unroll
            for (int i = 0; i < 2; i++) {
                kpre[i] = *(const uint4*)(g_qkv + base + ND + (kvch + i) * 8);
                vpre[i] = *(const uint4*)(g_qkv + base + 2 * ND + (kvch + i) * 8);
            }
        }

        // ---- S = Q K^T : 4 k16-steps, 8 ntiles ----
        float sacc[8][4];
        #pragma unroll
        for (int nt = 0; nt < 8; nt++)
            #pragma unroll
            for (int t = 0; t < 4; t++) sacc[nt][t] = 0.f;

        #pragma unroll
        for (int kb = 0; kb < 64; kb += 16) {
            uint32_t aF[4], bF[8][2];
            ldsm_x4(aF[0], aF[1], aF[2], aF[3], sQ + qa_off + kb * 2);
            #pragma unroll
            for (int p = 0; p < 4; p++)
                ldsm_x4(bF[2*p][0], bF[2*p][1], bF[2*p+1][0], bF[2*p+1][1],
                        sK + kb_off + (uint32_t)(p * 16 * 144) + (uint32_t)(kb * 2));
            #pragma unroll
            for (int nt = 0; nt < 8; nt++)
                mma_bf16(sacc[nt], aF, bF[nt]);
        }

        // ---- scale + causal mask ----
        #pragma unroll
        for (int nt = 0; nt < 8; nt++) {
            int gcol = jb * 64 + nt * 8 + (lane & 3) * 2;
            float v0 = sacc[nt][0] * scale;
            float v1 = sacc[nt][1] * scale;
            float v2 = sacc[nt][2] * scale;
            float v3 = sacc[nt][3] * scale;
            if (gcol     > grow0) v0 = -1e30f;
            if (gcol + 1 > grow0) v1 = -1e30f;
            if (gcol     > grow1) v2 = -1e30f;
            if (gcol + 1 > grow1) v3 = -1e30f;
            sacc[nt][0] = v0; sacc[nt][1] = v1;
            sacc[nt][2] = v2; sacc[nt][3] = v3;
        }

        // ---- online softmax (quad reduce) ----
        float mx0 = -1e30f, mx1 = -1e30f;
        #pragma unroll
        for (int nt = 0; nt < 8; nt++) {
            mx0 = fmaxf(mx0, fmaxf(sacc[nt][0], sacc[nt][1]));
            mx1 = fmaxf(mx1, fmaxf(sacc[nt][2], sacc[nt][3]));
        }
        mx0 = fmaxf(mx0, __shfl_xor_sync(0xffffffffu, mx0, 1));
        mx0 = fmaxf(mx0, __shfl_xor_sync(0xffffffffu, mx0, 2));
        mx1 = fmaxf(mx1, __shfl_xor_sync(0xffffffffu, mx1, 1));
        mx1 = fmaxf(mx1, __shfl_xor_sync(0xffffffffu, mx1, 2));

        float mn0 = fmaxf(m0, mx0);
        float mn1 = fmaxf(m1, mx1);

        float s0 = 0.f, s1 = 0.f;
        #pragma unroll
        for (int nt = 0; nt < 8; nt++) {
            float p0 = __expf(sacc[nt][0] - mn0);
            float p1 = __expf(sacc[nt][1] - mn0);
            float p2 = __expf(sacc[nt][2] - mn1);
            float p3 = __expf(sacc[nt][3] - mn1);
            sacc[nt][0] = p0; sacc[nt][1] = p1;
            sacc[nt][2] = p2; sacc[nt][3] = p3;
            s0 += p0 + p1;
            s1 += p2 + p3;
        }
        s0 += __shfl_xor_sync(0xffffffffu, s0, 1);
        s0 += __shfl_xor_sync(0xffffffffu, s0, 2);
        s1 += __shfl_xor_sync(0xffffffffu, s1, 1);
        s1 += __shfl_xor_sync(0xffffffffu, s1, 2);

        float al0 = __expf(m0 - mn0);
        float al1 = __expf(m1 - mn1);
        l0 = l0 * al0 + s0;
        l1 = l1 * al1 + s1;
        m0 = mn0; m1 = mn1;

        #pragma unroll
        for (int nt = 0; nt < 8; nt++) {
            oacc[nt][0] *= al0; oacc[nt][1] *= al0;
            oacc[nt][2] *= al1; oacc[nt][3] *= al1;
        }

        // ---- pack P (C-frags) -> bf16 A-frags, pure registers ----
        uint32_t aP[4][4];
        #pragma unroll
        for (int j = 0; j < 4; j++) {
            aP[j][0] = packbf(sacc[2*j][0],   sacc[2*j][1]);
            aP[j][1] = packbf(sacc[2*j][2],   sacc[2*j][3]);
            aP[j][2] = packbf(sacc[2*j+1][0], sacc[2*j+1][1]);
            aP[j][3] = packbf(sacc[2*j+1][2], sacc[2*j+1][3]);
        }

        // ---- O += P @ V : B-frags via ldmatrix.trans from Vs[s][n] ----
        #pragma unroll
        for (int j = 0; j < 4; j++) {
            uint32_t bV[8][2];
            #pragma unroll
            for (int p = 0; p < 4; p++)
                ldsm_x4_t(bV[2*p][0], bV[2*p][1], bV[2*p+1][0], bV[2*p+1][1],
                          sV + vb_off + (uint32_t)(j * 16 * 144) + (uint32_t)(p * 32));
            #pragma unroll
            for (int nt = 0; nt < 8; nt++)
                mma_bf16(oacc[nt], aP[j], bV[nt]);
        }
    }

    // ---- normalize + store bf16 ----
    float li0 = 1.0f / l0, li1 = 1.0f / l1;
    {
        int r_g0 = b * NT + grow0;
        int r_g1 = b * NT + grow1;
        #pragma unroll
        for (int nt = 0; nt < 8; nt++) {
            int c = h * NHS + nt * 8 + (lane & 3) * 2;
            *(uint32_t*)&g_attn[(size_t)r_g0 * ND + c] =
                packbf(oacc[nt][0] * li0, oacc[nt][1] * li0);
            *(uint32_t*)&g_attn[(size_t)r_g1 * ND + c] =
                packbf(oacc[nt][2] * li1, oacc[nt][3] * li1);
        }
    }
}

// ---------------- SwiGLU elementwise (vectorized, bf16 output) ------------
__global__ void swiglu_kernel()
{
    int idx = blockIdx.x * blockDim.x + threadIdx.x;
    if (idx >= NBT * NHALF / 4) return;
    int row = idx / (NHALF / 4);
    int c4  = (idx % (NHALF / 4)) * 4;
    float4 a = *(const float4*)&g_u[(size_t)row * NFF + c4];
    float4 z = *(const float4*)&g_u[(size_t)row * NFF + NHALF + c4];
    float r0 = a.x * (z.x / (1.0f + __expf(-z.x)));
    float r1 = a.y * (z.y / (1.0f + __expf(-z.y)));
    float r2 = a.z * (z.z / (1.0f + __expf(-z.z)));
    float r3 = a.w * (z.w / (1.0f + __expf(-z.w)));
    uint2 pk = make_uint2(packbf(r0, r1), packbf(r2, r3));
    *(uint2*)&g_gl[(size_t)row * NHALF + c4] = pk;
}

// ---------------- launch ----------------
extern "C" void kernel_launch(void* const* d_in, const int* in_sizes, int n_in,
                              void* d_out, int out_size)
{
    const float* x  = (const float*)d_in[0];
    const float* Wq = (const float*)d_in[1];
    const float* Wk = (const float*)d_in[2];
    const float* Wv = (const float*)d_in[3];
    const float* Wo = (const float*)d_in[4];
    const float* bo = (const float*)d_in[5];
    const float* W1 = (const float*)d_in[6];
    const float* b1 = (const float*)d_in[7];
    const float* W2 = (const float*)d_in[8];
    const float* b2 = (const float*)d_in[9];
    const float* g1 = (const float*)d_in[10];
    const float* g2 = (const float*)d_in[11];
    float* out = (float*)d_out;

    cudaFuncSetAttribute(attn_mma_kernel, cudaFuncAttributeMaxDynamicSharedMemorySize, ATT_SMEM);
    cudaFuncSetAttribute(gemm_qkv_kernel,  cudaFuncAttributeMaxDynamicSharedMemorySize, GEMM_SMEM);
    cudaFuncSetAttribute(gemm_o_kernel,    cudaFuncAttributeMaxDynamicSharedMemorySize, GEMM_SMEM);
    cudaFuncSetAttribute(gemm_ffn1_kernel, cudaFuncAttributeMaxDynamicSharedMemorySize, GEMM_SMEM);
    cudaFuncSetAttribute(gemm_ffn2_kernel, cudaFuncAttributeMaxDynamicSharedMemorySize, GEMM_SMEM);

    pack_wqkv_kernel<<<(3 * ND * ND + 255) / 256, 256>>>(Wq, Wk, Wv);
    round_weights_kernel<<<(W1_N + 255) / 256, 256>>>(Wo, W1, W2);
    rmsnorm1_kernel<<<NBT, 256>>>(x, g1);
    gemm_qkv_kernel<<<dim3(3 * ND / 128, NBT / 128), 256, GEMM_SMEM>>>();
    attn_mma_kernel<<<dim3(NT / 128, NH, NB), 256, ATT_SMEM>>>();
    gemm_o_kernel<<<dim3(ND / 128, NBT / 128), 256, GEMM_SMEM>>>(bo, x);
    rmsnorm2_kernel<<<NBT, 256>>>(g2);
    gemm_ffn1_kernel<<<dim3(NFF / 128, NBT / 128), 256, GEMM_SMEM>>>(b1);
    swiglu_kernel<<<(NBT * NHALF / 4 + 255) / 256, 256>>>();
    gemm_ffn2_kernel<<<dim3(ND / 128, NBT / 128), 256, GEMM_SMEM>>>(b2, out);
}

// round 11
// speedup vs baseline: 1.6222x; 1.0336x over previous
#include <cuda_runtime.h>
#include <cuda_bf16.h>
#include <math.h>
#include <stdint.h>

// Problem constants
#define NB    2
#define NT    2048
#define ND    768
#define NH    12
#define NHS   64
#define NFF   3072
#define NHALF 1536
#define NBT   (NB*NT)   // 4096

// ---------------- scratch (device globals; no allocation) ----------------
__device__ __nv_bfloat16 g_h   [NBT * ND];
__device__ __nv_bfloat16 g_qkv [NBT * 3 * ND];
__device__ __nv_bfloat16 g_attn[NBT * ND];
__device__ float         g_x1  [NBT * ND];
__device__ __nv_bfloat16 g_gl  [NBT * NHALF];
__device__ __nv_bfloat16 g_wqkv_t[3 * ND * ND];   // [2304 n][768 k]
__device__ __nv_bfloat16 g_wo_t  [ND * ND];       // [768 n][768 k]
__device__ __nv_bfloat16 g_w1_t  [NFF * ND];      // [3072 packed n][768 k]
__device__ __nv_bfloat16 g_w2_t  [ND * NHALF];    // [768 n][1536 k]

// ---------------- async copy helpers ----------------
__device__ __forceinline__ void cp_async16(void* smem_dst, const void* gmem_src)
{
    uint32_t d = (uint32_t)__cvta_generic_to_shared(smem_dst);
    asm volatile("cp.async.cg.shared.global [%0], [%1], 16;\n" :: "r"(d), "l"(gmem_src));
}
#define CP_COMMIT() asm volatile("cp.async.commit_group;\n" ::: "memory")
#define CP_WAIT1()  asm volatile("cp.async.wait_group 1;\n" ::: "memory")
#define CP_WAIT0()  asm volatile("cp.async.wait_group 0;\n" ::: "memory")

// ---------------- ldmatrix ----------------
__device__ __forceinline__ void ldsm_x4(uint32_t& r0, uint32_t& r1,
                                        uint32_t& r2, uint32_t& r3, uint32_t addr)
{
    asm volatile("ldmatrix.sync.aligned.m8n8.x4.shared.b16 {%0,%1,%2,%3}, [%4];"
                 : "=r"(r0), "=r"(r1), "=r"(r2), "=r"(r3) : "r"(addr));
}
__device__ __forceinline__ void ldsm_x4_t(uint32_t& r0, uint32_t& r1,
                                          uint32_t& r2, uint32_t& r3, uint32_t addr)
{
    asm volatile("ldmatrix.sync.aligned.m8n8.x4.trans.shared.b16 {%0,%1,%2,%3}, [%4];"
                 : "=r"(r0), "=r"(r1), "=r"(r2), "=r"(r3) : "r"(addr));
}

// ---------------- BF16 MMA ----------------
__device__ __forceinline__ void mma_bf16(float* c, const uint32_t* a, const uint32_t* b)
{
    asm volatile(
        "mma.sync.aligned.m16n8k16.row.col.f32.bf16.bf16.f32 "
        "{%0,%1,%2,%3}, {%4,%5,%6,%7}, {%8,%9}, {%0,%1,%2,%3};\n"
        : "+f"(c[0]), "+f"(c[1]), "+f"(c[2]), "+f"(c[3])
        : "r"(a[0]), "r"(a[1]), "r"(a[2]), "r"(a[3]), "r"(b[0]), "r"(b[1]));
}

__device__ __forceinline__ uint32_t packbf(float lo, float hi)
{
    __nv_bfloat162 p = __floats2bfloat162_rn(lo, hi);
    return *(uint32_t*)&p;
}

__device__ __forceinline__ float siluf(float z)
{
    return z / (1.0f + __expf(-z));
}

// ---------------- pack Wq/Wk/Wv -> [2304 n][768 k] bf16 ----------------
__global__ void pack_wqkv_kernel(const float* __restrict__ Wq,
                                 const float* __restrict__ Wk,
                                 const float* __restrict__ Wv)
{
    int idx = blockIdx.x * blockDim.x + threadIdx.x;
    const int total = 3 * ND * ND;
    if (idx >= total) return;
    int n = idx / ND;
    int d = idx % ND;
    int m = n / ND;
    int r = n % ND;
    int h = r / NHS;
    int k = r % NHS;
    const float* W = (m == 0) ? Wq : ((m == 1) ? Wk : Wv);
    g_wqkv_t[idx] = __float2bfloat16(W[h * ND * NHS + d * NHS + k]);
}

// ---------------- transpose + bf16 Wo/W1(swiglu-packed)/W2 ----------------
#define WO_N (ND * ND)
#define W1_N (ND * NFF)
#define W2_N (NHALF * ND)
__global__ void round_weights_kernel(const float* __restrict__ Wo,
                                     const float* __restrict__ W1,
                                     const float* __restrict__ W2)
{
    int idx = blockIdx.x * blockDim.x + threadIdx.x;
    if (idx < WO_N) {
        int n = idx / ND, k = idx % ND;
        g_wo_t[idx] = __float2bfloat16(Wo[k * ND + n]);
    }
    if (idx < W1_N) {
        // packed layout: tile of 128 packed cols -> 64 output cols, a/gate
        // interleaved at 8-col (n-tile) granularity.
        int p = idx / ND, k = idx % ND;
        int base128 = p & ~127;
        int loc = p & 127;
        int u = loc >> 4;
        int v = loc & 15;
        int fbase = (base128 >> 1) + u * 8;
        int src = (v < 8) ? (fbase + v) : (NHALF + fbase + (v - 8));
        g_w1_t[idx] = __float2bfloat16(W1[k * NFF + src]);
    }
    if (idx < W2_N) {
        int n = idx / NHALF, k = idx % NHALF;
        g_w2_t[idx] = __float2bfloat16(W2[k * ND + n]);
    }
}

// ---------------- RMSNorm (bf16 output) ----------------
__device__ __forceinline__ void rms_body(const float* __restrict__ in,
                                         __nv_bfloat16* __restrict__ out,
                                         const float* __restrict__ g)
{
    int tid = threadIdx.x;
    float v0 = in[tid], v1 = in[tid + 256], v2 = in[tid + 512];
    float ss = v0*v0 + v1*v1 + v2*v2;
    #pragma unroll
    for (int o = 16; o; o >>= 1) ss += __shfl_xor_sync(0xffffffffu, ss, o);
    __shared__ float ws[8];
    __shared__ float s_inv;
    if ((tid & 31) == 0) ws[tid >> 5] = ss;
    __syncthreads();
    if (tid == 0) {
        float t = 0.f;
        #pragma unroll
        for (int i = 0; i < 8; i++) t += ws[i];
        float rms = sqrtf(t * (1.0f / (float)ND));
        s_inv = 1.0f / (rms + 1e-8f);
    }
    __syncthreads();
    float inv = s_inv;
    out[tid]       = __float2bfloat16(g[tid]       * v0 * inv);
    out[tid + 256] = __float2bfloat16(g[tid + 256] * v1 * inv);
    out[tid + 512] = __float2bfloat16(g[tid + 512] * v2 * inv);
}

__global__ __launch_bounds__(256) void rmsnorm1_kernel(const float* __restrict__ x,
                                                       const float* __restrict__ g)
{
    int row = blockIdx.x;
    rms_body(x + (size_t)row * ND, g_h + (size_t)row * ND, g);
}

__global__ __launch_bounds__(256) void rmsnorm2_kernel(const float* __restrict__ g)
{
    int row = blockIdx.x;
    rms_body(g_x1 + (size_t)row * ND, g_h + (size_t)row * ND, g);
}

// ---------------- BF16 GEMM: 128x128x64, 3-stage cp.async + ldmatrix ------
// MODE: 0 = fp32 out (+bias/res), 1 = bf16 out, 2 = fused-swiglu bf16 out
#define KC 64
#define STR32 36
#define STAGE32 (128 * STR32)
#define GEMM_SMEM (6 * STAGE32 * 4)   // 110592 B

template<int N, int K, bool BIAS, bool RES, int MODE, typename OutT>
__device__ __forceinline__ void bf16_gemm_body(const __nv_bfloat16* __restrict__ A,
                                               const __nv_bfloat16* __restrict__ Bt,
                                               OutT* __restrict__ C,
                                               const float* __restrict__ bias,
                                               const float* __restrict__ res)
{
    extern __shared__ __align__(16) uint32_t smu[];
    uint32_t* As = smu;                 // [3][128][36] b32
    uint32_t* Bs = smu + 3 * STAGE32;   // [3][128][36] b32

    const int tid  = threadIdx.x;
    const int warp = tid >> 5, lane = tid & 31;
    const int wm = (warp >> 1) * 32;
    const int wn = (warp & 1) * 64;
    const int bm = blockIdx.y * 128;
    const int bn = blockIdx.x * 128;

    const uint32_t s_smu = (uint32_t)__cvta_generic_to_shared(smu);

    const int lrow = tid >> 1;
    const int lch  = (tid & 1) * 4;

    const uint32_t a_off0 = (uint32_t)(wm + (lane & 15)) * 144u + ((lane >> 4) << 4);
    const uint32_t b_off0 = (uint32_t)(wn + (lane & 7) + ((lane >> 4) << 3)) * 144u
                          + (((lane >> 3) & 1) << 4);

    float acc[2][8][4];
    #pragma unroll
    for (int i = 0; i < 2; i++)
        #pragma unroll
        for (int j = 0; j < 8; j++)
            #pragma unroll
            for (int t = 0; t < 4; t++) acc[i][j][t] = 0.f;

    const int NCH = K / KC;

    #pragma unroll
    for (int s = 0; s < 2; s++) {
        uint32_t* as = As + s * STAGE32;
        uint32_t* bs = Bs + s * STAGE32;
        const int k0 = s * KC;
        #pragma unroll
        for (int i = 0; i < 4; i++) {
            int ch = lch + i;
            cp_async16(&as[lrow * STR32 + ch * 4],
                       A  + (size_t)(bm + lrow) * K + k0 + ch * 8);
            cp_async16(&bs[lrow * STR32 + ch * 4],
                       Bt + (size_t)(bn + lrow) * K + k0 + ch * 8);
        }
        CP_COMMIT();
    }

    int cur = 0;
    int nst = 2;
    #pragma unroll 1
    for (int chunk = 0; chunk < NCH; chunk++) {
        if (chunk == NCH - 1) { CP_WAIT0(); } else { CP_WAIT1(); }
        __syncthreads();

        if (chunk + 2 < NCH) {
            const int k0 = (chunk + 2) * KC;
            uint32_t* as = As + nst * STAGE32;
            uint32_t* bs = Bs + nst * STAGE32;
            #pragma unroll
            for (int i = 0; i < 4; i++) {
                int ch = lch + i;
                cp_async16(&as[lrow * STR32 + ch * 4],
                           A  + (size_t)(bm + lrow) * K + k0 + ch * 8);
                cp_async16(&bs[lrow * STR32 + ch * 4],
                           Bt + (size_t)(bn + lrow) * K + k0 + ch * 8);
            }
            CP_COMMIT();
        }

        const uint32_t as_b = s_smu + (uint32_t)(cur * STAGE32 * 4) + a_off0;
        const uint32_t bs_b = s_smu + (uint32_t)((3 + cur) * STAGE32 * 4) + b_off0;

        #pragma unroll
        for (int kk = 0; kk < KC; kk += 16) {
            uint32_t aF[2][4], bF[8][2];
            #pragma unroll
            for (int mt = 0; mt < 2; mt++)
                ldsm_x4(aF[mt][0], aF[mt][1], aF[mt][2], aF[mt][3],
                        as_b + (uint32_t)(mt * 16 * 144) + (uint32_t)(kk * 2));
            #pragma unroll
            for (int p = 0; p < 4; p++)
                ldsm_x4(bF[2*p][0], bF[2*p][1], bF[2*p+1][0], bF[2*p+1][1],
                        bs_b + (uint32_t)(p * 16 * 144) + (uint32_t)(kk * 2));
            #pragma unroll
            for (int mt = 0; mt < 2; mt++)
                #pragma unroll
                for (int nt = 0; nt < 8; nt++)
                    mma_bf16(acc[mt][nt], aF[mt], bF[nt]);
        }

        cur = (cur == 2) ? 0 : cur + 1;
        nst = (nst == 2) ? 0 : nst + 1;
    }

    if constexpr (MODE == 2) {
        // fused SwiGLU: ntile 2j = a-cols, ntile 2j+1 = gate-cols for the
        // SAME 8 output columns. out = silu(gate+bg)*(a+ba), bf16 to C[NHALF].
        #pragma unroll
        for (int mt = 0; mt < 2; mt++) {
            #pragma unroll
            for (int j = 0; j < 4; j++) {
                int row0 = bm + wm + mt * 16 + (lane >> 2);
                int f    = (bn >> 1) + (wn >> 1) + j * 8 + (lane & 3) * 2;
                float2 ba = *(const float2*)(bias + f);
                float2 bg = *(const float2*)(bias + NHALF + f);
                float a0 = acc[mt][2*j][0] + ba.x;
                float a1 = acc[mt][2*j][1] + ba.y;
                float a2 = acc[mt][2*j][2] + ba.x;
                float a3 = acc[mt][2*j][3] + ba.y;
                float z0 = acc[mt][2*j+1][0] + bg.x;
                float z1 = acc[mt][2*j+1][1] + bg.y;
                float z2 = acc[mt][2*j+1][2] + bg.x;
                float z3 = acc[mt][2*j+1][3] + bg.y;
                *(uint32_t*)((__nv_bfloat16*)C + (size_t)row0 * NHALF + f) =
                    packbf(siluf(z0) * a0, siluf(z1) * a1);
                *(uint32_t*)((__nv_bfloat16*)C + (size_t)(row0 + 8) * NHALF + f) =
                    packbf(siluf(z2) * a2, siluf(z3) * a3);
            }
        }
    } else {
        #pragma unroll
        for (int mt = 0; mt < 2; mt++) {
            #pragma unroll
            for (int nt = 0; nt < 8; nt++) {
                int row0 = bm + wm + mt * 16 + (lane >> 2);
                int col  = bn + wn + nt * 8 + (lane & 3) * 2;
                float2 v0 = make_float2(acc[mt][nt][0], acc[mt][nt][1]);
                float2 v1 = make_float2(acc[mt][nt][2], acc[mt][nt][3]);
                if constexpr (BIAS) {
                    float2 bb = *(const float2*)(bias + col);
                    v0.x += bb.x; v0.y += bb.y;
                    v1.x += bb.x; v1.y += bb.y;
                }
                if constexpr (RES) {
                    float2 r0 = *(const float2*)(res + (size_t)row0 * N + col);
                    float2 r1 = *(const float2*)(res + (size_t)(row0 + 8) * N + col);
                    v0.x += r0.x; v0.y += r0.y;
                    v1.x += r1.x; v1.y += r1.y;
                }
                if constexpr (MODE == 1) {
                    *(uint32_t*)(C + (size_t)row0 * N + col)       = packbf(v0.x, v0.y);
                    *(uint32_t*)(C + (size_t)(row0 + 8) * N + col) = packbf(v1.x, v1.y);
                } else {
                    *(float2*)(C + (size_t)row0 * N + col)       = v0;
                    *(float2*)(C + (size_t)(row0 + 8) * N + col) = v1;
                }
            }
        }
    }
}

__global__ __launch_bounds__(256) void gemm_qkv_kernel()
{
    bf16_gemm_body<3 * ND, ND, false, false, 1, __nv_bfloat16>(g_h, g_wqkv_t, g_qkv,
                                                               nullptr, nullptr);
}
__global__ __launch_bounds__(256) void gemm_o_kernel(const float* __restrict__ bo,
                                                     const float* __restrict__ x)
{
    bf16_gemm_body<ND, ND, true, true, 0, float>(g_attn, g_wo_t, g_x1, bo, x);
}
__global__ __launch_bounds__(256) void gemm_ffn1_kernel(const float* __restrict__ b1)
{
    // fused swiglu epilogue -> g_gl (bf16, 1536 cols)
    bf16_gemm_body<NFF, ND, false, false, 2, __nv_bfloat16>(g_h, g_w1_t, g_gl,
                                                            b1, nullptr);
}
__global__ __launch_bounds__(256) void gemm_ffn2_kernel(const float* __restrict__ b2,
                                                        float* __restrict__ out)
{
    bf16_gemm_body<ND, NHALF, true, true, 0, float>(g_gl, g_w2_t, out, b2, g_x1);
}

// ---------------- Flash attention, full bf16 MMA (R10, passing) -----------
#define AT_STR 72
#define ATT_SMEM ((128 + 64 + 64) * AT_STR * 2)   // 36864 B

__global__ __launch_bounds__(256) void attn_mma_kernel()
{
    extern __shared__ __align__(16) __nv_bfloat16 smb[];
    __nv_bfloat16* Qs = smb;                     // [128][72]
    __nv_bfloat16* Ks = Qs + 128 * AT_STR;       // [64][72]
    __nv_bfloat16* Vs = Ks + 64 * AT_STR;        // [64][72]

    const int tid  = threadIdx.x;
    const int warp = tid >> 5, lane = tid & 31;
    const int qb = (int)gridDim.x - 1 - (int)blockIdx.x;
    const int h  = blockIdx.y;
    const int b  = blockIdx.z;
    const int row0 = qb * 128;
    const int wrow = warp * 16;

    const uint32_t sQ = (uint32_t)__cvta_generic_to_shared(Qs);
    const uint32_t sK = (uint32_t)__cvta_generic_to_shared(Ks);
    const uint32_t sV = (uint32_t)__cvta_generic_to_shared(Vs);

    {
        int row = tid >> 1;
        int chb = (tid & 1) * 4;
        const __nv_bfloat16* qp = g_qkv + (size_t)(b * NT + row0 + row) * (3 * ND)
                                  + h * NHS;
        #pragma unroll
        for (int i = 0; i < 4; i++) {
            int ch = chb + i;
            *(uint4*)&Qs[row * AT_STR + ch * 8] = *(const uint4*)(qp + ch * 8);
        }
    }

    float oacc[8][4];
    #pragma unroll
    for (int nt = 0; nt < 8; nt++)
        #pragma unroll
        for (int t = 0; t < 4; t++) oacc[nt][t] = 0.f;

    float m0 = -1e30f, m1 = -1e30f, l0 = 0.f, l1 = 0.f;
    const float scale = 0.03608439182435161f;   // 768^-0.5

    const int grow0 = row0 + wrow + (lane >> 2);
    const int grow1 = grow0 + 8;
    const int jb_max = 2 * qb + 1;

    const int kvrow = tid >> 2;
    const int kvch  = (tid & 3) * 2;

    uint4 kpre[2], vpre[2];
    {
        size_t base = (size_t)(b * NT + kvrow) * (3 * ND) + h * NHS;
        #pragma unroll
        for (int i = 0; i < 2; i++) {
            kpre[i] = *(const uint4*)(g_qkv + base + ND + (kvch + i) * 8);
            vpre[i] = *(const uint4*)(g_qkv + base + 2 * ND + (kvch + i) * 8);
        }
    }

    const uint32_t qa_off = (uint32_t)(wrow + (lane & 15)) * 144u + ((lane >> 4) << 4);
    const uint32_t kb_off = (uint32_t)((lane & 7) + ((lane >> 4) << 3)) * 144u
                          + (((lane >> 3) & 1) << 4);
    const uint32_t vb_off = (uint32_t)((lane & 7) + (((lane >> 3) & 1) << 3)) * 144u
                          + ((lane >> 4) << 4);

    for (int jb = 0; jb <= jb_max; jb++) {
        __syncthreads();
        #pragma unroll
        for (int i = 0; i < 2; i++) {
            *(uint4*)&Ks[kvrow * AT_STR + (kvch + i) * 8] = kpre[i];
            *(uint4*)&Vs[kvrow * AT_STR + (kvch + i) * 8] = vpre[i];
        }
        __syncthreads();

        if (jb < jb_max) {
            size_t base = (size_t)(b * NT + (jb + 1) * 64 + kvrow) * (3 * ND) + h * NHS;
            #pragma unroll
            for (int i = 0; i < 2; i++) {
                kpre[i] = *(const uint4*)(g_qkv + base + ND + (kvch + i) * 8);
                vpre[i] = *(const uint4*)(g_qkv + base + 2 * ND + (kvch + i) * 8);
            }
        }

        float sacc[8][4];
        #pragma unroll
        for (int nt = 0; nt < 8; nt++)
            #pragma unroll
            for (int t = 0; t < 4; t++) sacc[nt][t] = 0.f;

        #pragma unroll
        for (int kb = 0; kb < 64; kb += 16) {
            uint32_t aF[4], bF[8][2];
            ldsm_x4(aF[0], aF[1], aF[2], aF[3], sQ + qa_off + kb * 2);
            #pragma unroll
            for (int p = 0; p < 4; p++)
                ldsm_x4(bF[2*p][0], bF[2*p][1], bF[2*p+1][0], bF[2*p+1][1],
                        sK + kb_off + (uint32_t)(p * 16 * 144) + (uint32_t)(kb * 2));
            #pragma unroll
            for (int nt = 0; nt < 8; nt++)
                mma_bf16(sacc[nt], aF, bF[nt]);
        }

        #pragma unroll
        for (int nt = 0; nt < 8; nt++) {
            int gcol = jb * 64 + nt * 8 + (lane & 3) * 2;
            float v0 = sacc[nt][0] * scale;
            float v1 = sacc[nt][1] * scale;
            float v2 = sacc[nt][2] * scale;
            float v3 = sacc[nt][3] * scale;
            if (gcol     > grow0) v0 = -1e30f;
            if (gcol + 1 > grow0) v1 = -1e30f;
            if (gcol     > grow1) v2 = -1e30f;
            if (gcol + 1 > grow1) v3 = -1e30f;
            sacc[nt][0] = v0; sacc[nt][1] = v1;
            sacc[nt][2] = v2; sacc[nt][3] = v3;
        }

        float mx0 = -1e30f, mx1 = -1e30f;
        #pragma unroll
        for (int nt = 0; nt < 8; nt++) {
            mx0 = fmaxf(mx0, fmaxf(sacc[nt][0], sacc[nt][1]));
            mx1 = fmaxf(mx1, fmaxf(sacc[nt][2], sacc[nt][3]));
        }
        mx0 = fmaxf(mx0, __shfl_xor_sync(0xffffffffu, mx0, 1));
        mx0 = fmaxf(mx0, __shfl_xor_sync(0xffffffffu, mx0, 2));
        mx1 = fmaxf(mx1, __shfl_xor_sync(0xffffffffu, mx1, 1));
        mx1 = fmaxf(mx1, __shfl_xor_sync(0xffffffffu, mx1, 2));

        float mn0 = fmaxf(m0, mx0);
        float mn1 = fmaxf(m1, mx1);

        float s0 = 0.f, s1 = 0.f;
        #pragma unroll
        for (int nt = 0; nt < 8; nt++) {
            float p0 = __expf(sacc[nt][0] - mn0);
            float p1 = __expf(sacc[nt][1] - mn0);
            float p2 = __expf(sacc[nt][2] - mn1);
            float p3 = __expf(sacc[nt][3] - mn1);
            sacc[nt][0] = p0; sacc[nt][1] = p1;
            sacc[nt][2] = p2; sacc[nt][3] = p3;
            s0 += p0 + p1;
            s1 += p2 + p3;
        }
        s0 += __shfl_xor_sync(0xffffffffu, s0, 1);
        s0 += __shfl_xor_sync(0xffffffffu, s0, 2);
        s1 += __shfl_xor_sync(0xffffffffu, s1, 1);
        s1 += __shfl_xor_sync(0xffffffffu, s1, 2);

        float al0 = __expf(m0 - mn0);
        float al1 = __expf(m1 - mn1);
        l0 = l0 * al0 + s0;
        l1 = l1 * al1 + s1;
        m0 = mn0; m1 = mn1;

        #pragma unroll
        for (int nt = 0; nt < 8; nt++) {
            oacc[nt][0] *= al0; oacc[nt][1] *= al0;
            oacc[nt][2] *= al1; oacc[nt][3] *= al1;
        }

        uint32_t aP[4][4];
        #pragma unroll
        for (int j = 0; j < 4; j++) {
            aP[j][0] = packbf(sacc[2*j][0],   sacc[2*j][1]);
            aP[j][1] = packbf(sacc[2*j][2],   sacc[2*j][3]);
            aP[j][2] = packbf(sacc[2*j+1][0], sacc[2*j+1][1]);
            aP[j][3] = packbf(sacc[2*j+1][2], sacc[2*j+1][3]);
        }

        #pragma unroll
        for (int j = 0; j < 4; j++) {
            uint32_t bV[8][2];
            #pragma unroll
            for (int p = 0; p < 4; p++)
                ldsm_x4_t(bV[2*p][0], bV[2*p][1], bV[2*p+1][0], bV[2*p+1][1],
                          sV + vb_off + (uint32_t)(j * 16 * 144) + (uint32_t)(p * 32));
            #pragma unroll
            for (int nt = 0; nt < 8; nt++)
                mma_bf16(oacc[nt], aP[j], bV[nt]);
        }
    }

    float li0 = 1.0f / l0, li1 = 1.0f / l1;
    {
        int r_g0 = b * NT + grow0;
        int r_g1 = b * NT + grow1;
        #pragma unroll
        for (int nt = 0; nt < 8; nt++) {
            int c = h * NHS + nt * 8 + (lane & 3) * 2;
            *(uint32_t*)&g_attn[(size_t)r_g0 * ND + c] =
                packbf(oacc[nt][0] * li0, oacc[nt][1] * li0);
            *(uint32_t*)&g_attn[(size_t)r_g1 * ND + c] =
                packbf(oacc[nt][2] * li1, oacc[nt][3] * li1);
        }
    }
}

// ---------------- launch ----------------
extern "C" void kernel_launch(void* const* d_in, const int* in_sizes, int n_in,
                              void* d_out, int out_size)
{
    const float* x  = (const float*)d_in[0];
    const float* Wq = (const float*)d_in[1];
    const float* Wk = (const float*)d_in[2];
    const float* Wv = (const float*)d_in[3];
    const float* Wo = (const float*)d_in[4];
    const float* bo = (const float*)d_in[5];
    const float* W1 = (const float*)d_in[6];
    const float* b1 = (const float*)d_in[7];
    const float* W2 = (const float*)d_in[8];
    const float* b2 = (const float*)d_in[9];
    const float* g1 = (const float*)d_in[10];
    const float* g2 = (const float*)d_in[11];
    float* out = (float*)d_out;

    cudaFuncSetAttribute(attn_mma_kernel, cudaFuncAttributeMaxDynamicSharedMemorySize, ATT_SMEM);
    cudaFuncSetAttribute(gemm_qkv_kernel,  cudaFuncAttributeMaxDynamicSharedMemorySize, GEMM_SMEM);
    cudaFuncSetAttribute(gemm_o_kernel,    cudaFuncAttributeMaxDynamicSharedMemorySize, GEMM_SMEM);
    cudaFuncSetAttribute(gemm_ffn1_kernel, cudaFuncAttributeMaxDynamicSharedMemorySize, GEMM_SMEM);
    cudaFuncSetAttribute(gemm_ffn2_kernel, cudaFuncAttributeMaxDynamicSharedMemorySize, GEMM_SMEM);

    pack_wqkv_kernel<<<(3 * ND * ND + 255) / 256, 256>>>(Wq, Wk, Wv);
    round_weights_kernel<<<(W1_N + 255) / 256, 256>>>(Wo, W1, W2);
    rmsnorm1_kernel<<<NBT, 256>>>(x, g1);
    gemm_qkv_kernel<<<dim3(3 * ND / 128, NBT / 128), 256, GEMM_SMEM>>>();
    attn_mma_kernel<<<dim3(NT / 128, NH, NB), 256, ATT_SMEM>>>();
    gemm_o_kernel<<<dim3(ND / 128, NBT / 128), 256, GEMM_SMEM>>>(bo, x);
    rmsnorm2_kernel<<<NBT, 256>>>(g2);
    gemm_ffn1_kernel<<<dim3(NFF / 128, NBT / 128), 256, GEMM_SMEM>>>(b1);
    gemm_ffn2_kernel<<<dim3(ND / 128, NBT / 128), 256, GEMM_SMEM>>>(b2, out);
}

// round 12
// speedup vs baseline: 1.6418x; 1.0121x over previous
#include <cuda_runtime.h>
#include <cuda_bf16.h>
#include <math.h>
#include <stdint.h>

// Problem constants
#define NB    2
#define NT    2048
#define ND    768
#define NH    12
#define NHS   64
#define NFF   3072
#define NHALF 1536
#define NBT   (NB*NT)   // 4096

// ---------------- scratch (device globals; no allocation) ----------------
__device__ __nv_bfloat16 g_h   [NBT * ND];
__device__ __nv_bfloat16 g_qkv [NBT * 3 * ND];
__device__ __nv_bfloat16 g_attn[NBT * ND];
__device__ float         g_x1  [NBT * ND];
__device__ __nv_bfloat16 g_gl  [NBT * NHALF];
__device__ __nv_bfloat16 g_wqkv_t[3 * ND * ND];   // [2304 n][768 k]
__device__ __nv_bfloat16 g_wo_t  [ND * ND];       // [768 n][768 k]
__device__ __nv_bfloat16 g_w1_t  [NFF * ND];      // [3072 packed n][768 k]
__device__ __nv_bfloat16 g_w2_t  [ND * NHALF];    // [768 n][1536 k]

// ---------------- async copy helpers ----------------
__device__ __forceinline__ void cp_async16(void* smem_dst, const void* gmem_src)
{
    uint32_t d = (uint32_t)__cvta_generic_to_shared(smem_dst);
    asm volatile("cp.async.cg.shared.global [%0], [%1], 16;\n" :: "r"(d), "l"(gmem_src));
}
#define CP_COMMIT() asm volatile("cp.async.commit_group;\n" ::: "memory")
#define CP_WAIT1()  asm volatile("cp.async.wait_group 1;\n" ::: "memory")
#define CP_WAIT0()  asm volatile("cp.async.wait_group 0;\n" ::: "memory")

// ---------------- ldmatrix ----------------
__device__ __forceinline__ void ldsm_x4(uint32_t& r0, uint32_t& r1,
                                        uint32_t& r2, uint32_t& r3, uint32_t addr)
{
    asm volatile("ldmatrix.sync.aligned.m8n8.x4.shared.b16 {%0,%1,%2,%3}, [%4];"
                 : "=r"(r0), "=r"(r1), "=r"(r2), "=r"(r3) : "r"(addr));
}
__device__ __forceinline__ void ldsm_x4_t(uint32_t& r0, uint32_t& r1,
                                          uint32_t& r2, uint32_t& r3, uint32_t addr)
{
    asm volatile("ldmatrix.sync.aligned.m8n8.x4.trans.shared.b16 {%0,%1,%2,%3}, [%4];"
                 : "=r"(r0), "=r"(r1), "=r"(r2), "=r"(r3) : "r"(addr));
}

// ---------------- BF16 MMA ----------------
__device__ __forceinline__ void mma_bf16(float* c, const uint32_t* a, const uint32_t* b)
{
    asm volatile(
        "mma.sync.aligned.m16n8k16.row.col.f32.bf16.bf16.f32 "
        "{%0,%1,%2,%3}, {%4,%5,%6,%7}, {%8,%9}, {%0,%1,%2,%3};\n"
        : "+f"(c[0]), "+f"(c[1]), "+f"(c[2]), "+f"(c[3])
        : "r"(a[0]), "r"(a[1]), "r"(a[2]), "r"(a[3]), "r"(b[0]), "r"(b[1]));
}

__device__ __forceinline__ uint32_t packbf(float lo, float hi)
{
    __nv_bfloat162 p = __floats2bfloat162_rn(lo, hi);
    return *(uint32_t*)&p;
}

__device__ __forceinline__ float siluf(float z)
{
    return z / (1.0f + __expf(-z));
}

// ---------------- pack Wq/Wk/Wv -> [2304 n][768 k] bf16 ----------------
__global__ void pack_wqkv_kernel(const float* __restrict__ Wq,
                                 const float* __restrict__ Wk,
                                 const float* __restrict__ Wv)
{
    int idx = blockIdx.x * blockDim.x + threadIdx.x;
    const int total = 3 * ND * ND;
    if (idx >= total) return;
    int n = idx / ND;
    int d = idx % ND;
    int m = n / ND;
    int r = n % ND;
    int h = r / NHS;
    int k = r % NHS;
    const float* W = (m == 0) ? Wq : ((m == 1) ? Wk : Wv);
    g_wqkv_t[idx] = __float2bfloat16(W[h * ND * NHS + d * NHS + k]);
}

// ---------------- transpose + bf16 Wo/W1(swiglu-packed)/W2 ----------------
#define WO_N (ND * ND)
#define W1_N (ND * NFF)
#define W2_N (NHALF * ND)
__global__ void round_weights_kernel(const float* __restrict__ Wo,
                                     const float* __restrict__ W1,
                                     const float* __restrict__ W2)
{
    int idx = blockIdx.x * blockDim.x + threadIdx.x;
    if (idx < WO_N) {
        int n = idx / ND, k = idx % ND;
        g_wo_t[idx] = __float2bfloat16(Wo[k * ND + n]);
    }
    if (idx < W1_N) {
        int p = idx / ND, k = idx % ND;
        int base128 = p & ~127;
        int loc = p & 127;
        int u = loc >> 4;
        int v = loc & 15;
        int fbase = (base128 >> 1) + u * 8;
        int src = (v < 8) ? (fbase + v) : (NHALF + fbase + (v - 8));
        g_w1_t[idx] = __float2bfloat16(W1[k * NFF + src]);
    }
    if (idx < W2_N) {
        int n = idx / NHALF, k = idx % NHALF;
        g_w2_t[idx] = __float2bfloat16(W2[k * ND + n]);
    }
}

// ---------------- RMSNorm (bf16 output) ----------------
__device__ __forceinline__ void rms_body(const float* __restrict__ in,
                                         __nv_bfloat16* __restrict__ out,
                                         const float* __restrict__ g)
{
    int tid = threadIdx.x;
    float v0 = in[tid], v1 = in[tid + 256], v2 = in[tid + 512];
    float ss = v0*v0 + v1*v1 + v2*v2;
    #pragma unroll
    for (int o = 16; o; o >>= 1) ss += __shfl_xor_sync(0xffffffffu, ss, o);
    __shared__ float ws[8];
    __shared__ float s_inv;
    if ((tid & 31) == 0) ws[tid >> 5] = ss;
    __syncthreads();
    if (tid == 0) {
        float t = 0.f;
        #pragma unroll
        for (int i = 0; i < 8; i++) t += ws[i];
        float rms = sqrtf(t * (1.0f / (float)ND));
        s_inv = 1.0f / (rms + 1e-8f);
    }
    __syncthreads();
    float inv = s_inv;
    out[tid]       = __float2bfloat16(g[tid]       * v0 * inv);
    out[tid + 256] = __float2bfloat16(g[tid + 256] * v1 * inv);
    out[tid + 512] = __float2bfloat16(g[tid + 512] * v2 * inv);
}

__global__ __launch_bounds__(256) void rmsnorm1_kernel(const float* __restrict__ x,
                                                       const float* __restrict__ g)
{
    int row = blockIdx.x;
    rms_body(x + (size_t)row * ND, g_h + (size_t)row * ND, g);
}

__global__ __launch_bounds__(256) void rmsnorm2_kernel(const float* __restrict__ g)
{
    int row = blockIdx.x;
    rms_body(g_x1 + (size_t)row * ND, g_h + (size_t)row * ND, g);
}

// ---------------- BF16 GEMM: 128x128x64, 3-stage cp.async + ldmatrix ------
// Fragment double-buffering: k-step i+1 LDSMs issue before k-step i MMAs.
// MODE: 0 = fp32 out (+bias/res), 1 = bf16 out, 2 = fused-swiglu bf16 out
#define KC 64
#define STR32 36
#define STAGE32 (128 * STR32)
#define GEMM_SMEM (6 * STAGE32 * 4)   // 110592 B

template<int N, int K, bool BIAS, bool RES, int MODE, typename OutT>
__device__ __forceinline__ void bf16_gemm_body(const __nv_bfloat16* __restrict__ A,
                                               const __nv_bfloat16* __restrict__ Bt,
                                               OutT* __restrict__ C,
                                               const float* __restrict__ bias,
                                               const float* __restrict__ res)
{
    extern __shared__ __align__(16) uint32_t smu[];
    uint32_t* As = smu;                 // [3][128][36] b32
    uint32_t* Bs = smu + 3 * STAGE32;   // [3][128][36] b32

    const int tid  = threadIdx.x;
    const int warp = tid >> 5, lane = tid & 31;
    const int wm = (warp >> 1) * 32;
    const int wn = (warp & 1) * 64;
    const int bm = blockIdx.y * 128;
    const int bn = blockIdx.x * 128;

    const uint32_t s_smu = (uint32_t)__cvta_generic_to_shared(smu);

    const int lrow = tid >> 1;
    const int lch  = (tid & 1) * 4;

    const uint32_t a_off0 = (uint32_t)(wm + (lane & 15)) * 144u + ((lane >> 4) << 4);
    const uint32_t b_off0 = (uint32_t)(wn + (lane & 7) + ((lane >> 4) << 3)) * 144u
                          + (((lane >> 3) & 1) << 4);

    float acc[2][8][4];
    #pragma unroll
    for (int i = 0; i < 2; i++)
        #pragma unroll
        for (int j = 0; j < 8; j++)
            #pragma unroll
            for (int t = 0; t < 4; t++) acc[i][j][t] = 0.f;

    const int NCH = K / KC;

    #pragma unroll
    for (int s = 0; s < 2; s++) {
        uint32_t* as = As + s * STAGE32;
        uint32_t* bs = Bs + s * STAGE32;
        const int k0 = s * KC;
        #pragma unroll
        for (int i = 0; i < 4; i++) {
            int ch = lch + i;
            cp_async16(&as[lrow * STR32 + ch * 4],
                       A  + (size_t)(bm + lrow) * K + k0 + ch * 8);
            cp_async16(&bs[lrow * STR32 + ch * 4],
                       Bt + (size_t)(bn + lrow) * K + k0 + ch * 8);
        }
        CP_COMMIT();
    }

    int cur = 0;
    int nst = 2;
    #pragma unroll 1
    for (int chunk = 0; chunk < NCH; chunk++) {
        if (chunk == NCH - 1) { CP_WAIT0(); } else { CP_WAIT1(); }
        __syncthreads();

        if (chunk + 2 < NCH) {
            const int k0 = (chunk + 2) * KC;
            uint32_t* as = As + nst * STAGE32;
            uint32_t* bs = Bs + nst * STAGE32;
            #pragma unroll
            for (int i = 0; i < 4; i++) {
                int ch = lch + i;
                cp_async16(&as[lrow * STR32 + ch * 4],
                           A  + (size_t)(bm + lrow) * K + k0 + ch * 8);
                cp_async16(&bs[lrow * STR32 + ch * 4],
                           Bt + (size_t)(bn + lrow) * K + k0 + ch * 8);
            }
            CP_COMMIT();
        }

        const uint32_t as_b = s_smu + (uint32_t)(cur * STAGE32 * 4) + a_off0;
        const uint32_t bs_b = s_smu + (uint32_t)((3 + cur) * STAGE32 * 4) + b_off0;

        // fragment double buffer: preload k-step 0
        uint32_t aF[2][2][4], bF[2][8][2];
        #pragma unroll
        for (int mt = 0; mt < 2; mt++)
            ldsm_x4(aF[0][mt][0], aF[0][mt][1], aF[0][mt][2], aF[0][mt][3],
                    as_b + (uint32_t)(mt * 16 * 144));
        #pragma unroll
        for (int p = 0; p < 4; p++)
            ldsm_x4(bF[0][2*p][0], bF[0][2*p][1], bF[0][2*p+1][0], bF[0][2*p+1][1],
                    bs_b + (uint32_t)(p * 16 * 144));

        #pragma unroll
        for (int ki = 0; ki < 4; ki++) {
            const int pb = ki & 1;
            if (ki < 3) {
                const uint32_t ko = (uint32_t)((ki + 1) * 32);   // 16 cols * 2B
                #pragma unroll
                for (int mt = 0; mt < 2; mt++)
                    ldsm_x4(aF[pb^1][mt][0], aF[pb^1][mt][1],
                            aF[pb^1][mt][2], aF[pb^1][mt][3],
                            as_b + (uint32_t)(mt * 16 * 144) + ko);
                #pragma unroll
                for (int p = 0; p < 4; p++)
                    ldsm_x4(bF[pb^1][2*p][0], bF[pb^1][2*p][1],
                            bF[pb^1][2*p+1][0], bF[pb^1][2*p+1][1],
                            bs_b + (uint32_t)(p * 16 * 144) + ko);
            }
            #pragma unroll
            for (int mt = 0; mt < 2; mt++)
                #pragma unroll
                for (int nt = 0; nt < 8; nt++)
                    mma_bf16(acc[mt][nt], aF[pb][mt], bF[pb][nt]);
        }

        cur = (cur == 2) ? 0 : cur + 1;
        nst = (nst == 2) ? 0 : nst + 1;
    }

    if constexpr (MODE == 2) {
        #pragma unroll
        for (int mt = 0; mt < 2; mt++) {
            #pragma unroll
            for (int j = 0; j < 4; j++) {
                int row0 = bm + wm + mt * 16 + (lane >> 2);
                int f    = (bn >> 1) + (wn >> 1) + j * 8 + (lane & 3) * 2;
                float2 ba = *(const float2*)(bias + f);
                float2 bg = *(const float2*)(bias + NHALF + f);
                float a0 = acc[mt][2*j][0] + ba.x;
                float a1 = acc[mt][2*j][1] + ba.y;
                float a2 = acc[mt][2*j][2] + ba.x;
                float a3 = acc[mt][2*j][3] + ba.y;
                float z0 = acc[mt][2*j+1][0] + bg.x;
                float z1 = acc[mt][2*j+1][1] + bg.y;
                float z2 = acc[mt][2*j+1][2] + bg.x;
                float z3 = acc[mt][2*j+1][3] + bg.y;
                *(uint32_t*)((__nv_bfloat16*)C + (size_t)row0 * NHALF + f) =
                    packbf(siluf(z0) * a0, siluf(z1) * a1);
                *(uint32_t*)((__nv_bfloat16*)C + (size_t)(row0 + 8) * NHALF + f) =
                    packbf(siluf(z2) * a2, siluf(z3) * a3);
            }
        }
    } else {
        #pragma unroll
        for (int mt = 0; mt < 2; mt++) {
            #pragma unroll
            for (int nt = 0; nt < 8; nt++) {
                int row0 = bm + wm + mt * 16 + (lane >> 2);
                int col  = bn + wn + nt * 8 + (lane & 3) * 2;
                float2 v0 = make_float2(acc[mt][nt][0], acc[mt][nt][1]);
                float2 v1 = make_float2(acc[mt][nt][2], acc[mt][nt][3]);
                if constexpr (BIAS) {
                    float2 bb = *(const float2*)(bias + col);
                    v0.x += bb.x; v0.y += bb.y;
                    v1.x += bb.x; v1.y += bb.y;
                }
                if constexpr (RES) {
                    float2 r0 = *(const float2*)(res + (size_t)row0 * N + col);
                    float2 r1 = *(const float2*)(res + (size_t)(row0 + 8) * N + col);
                    v0.x += r0.x; v0.y += r0.y;
                    v1.x += r1.x; v1.y += r1.y;
                }
                if constexpr (MODE == 1) {
                    *(uint32_t*)(C + (size_t)row0 * N + col)       = packbf(v0.x, v0.y);
                    *(uint32_t*)(C + (size_t)(row0 + 8) * N + col) = packbf(v1.x, v1.y);
                } else {
                    *(float2*)(C + (size_t)row0 * N + col)       = v0;
                    *(float2*)(C + (size_t)(row0 + 8) * N + col) = v1;
                }
            }
        }
    }
}

__global__ __launch_bounds__(256, 2) void gemm_qkv_kernel()
{
    bf16_gemm_body<3 * ND, ND, false, false, 1, __nv_bfloat16>(g_h, g_wqkv_t, g_qkv,
                                                               nullptr, nullptr);
}
__global__ __launch_bounds__(256, 2) void gemm_o_kernel(const float* __restrict__ bo,
                                                        const float* __restrict__ x)
{
    bf16_gemm_body<ND, ND, true, true, 0, float>(g_attn, g_wo_t, g_x1, bo, x);
}
__global__ __launch_bounds__(256, 2) void gemm_ffn1_kernel(const float* __restrict__ b1)
{
    bf16_gemm_body<NFF, ND, false, false, 2, __nv_bfloat16>(g_h, g_w1_t, g_gl,
                                                            b1, nullptr);
}
__global__ __launch_bounds__(256, 2) void gemm_ffn2_kernel(const float* __restrict__ b2,
                                                           float* __restrict__ out)
{
    bf16_gemm_body<ND, NHALF, true, true, 0, float>(g_gl, g_w2_t, out, b2, g_x1);
}

// ---------------- Flash attention, full bf16 MMA (R10, passing) -----------
#define AT_STR 72
#define ATT_SMEM ((128 + 64 + 64) * AT_STR * 2)   // 36864 B

__global__ __launch_bounds__(256) void attn_mma_kernel()
{
    extern __shared__ __align__(16) __nv_bfloat16 smb[];
    __nv_bfloat16* Qs = smb;                     // [128][72]
    __nv_bfloat16* Ks = Qs + 128 * AT_STR;       // [64][72]
    __nv_bfloat16* Vs = Ks + 64 * AT_STR;        // [64][72]

    const int tid  = threadIdx.x;
    const int warp = tid >> 5, lane = tid & 31;
    const int qb = (int)gridDim.x - 1 - (int)blockIdx.x;
    const int h  = blockIdx.y;
    const int b  = blockIdx.z;
    const int row0 = qb * 128;
    const int wrow = warp * 16;

    const uint32_t sQ = (uint32_t)__cvta_generic_to_shared(Qs);
    const uint32_t sK = (uint32_t)__cvta_generic_to_shared(Ks);
    const uint32_t sV = (uint32_t)__cvta_generic_to_shared(Vs);

    {
        int row = tid >> 1;
        int chb = (tid & 1) * 4;
        const __nv_bfloat16* qp = g_qkv + (size_t)(b * NT + row0 + row) * (3 * ND)
                                  + h * NHS;
        #pragma unroll
        for (int i = 0; i < 4; i++) {
            int ch = chb + i;
            *(uint4*)&Qs[row * AT_STR + ch * 8] = *(const uint4*)(qp + ch * 8);
        }
    }

    float oacc[8][4];
    #pragma unroll
    for (int nt = 0; nt < 8; nt++)
        #pragma unroll
        for (int t = 0; t < 4; t++) oacc[nt][t] = 0.f;

    float m0 = -1e30f, m1 = -1e30f, l0 = 0.f, l1 = 0.f;
    const float scale = 0.03608439182435161f;   // 768^-0.5

    const int grow0 = row0 + wrow + (lane >> 2);
    const int grow1 = grow0 + 8;
    const int jb_max = 2 * qb + 1;

    const int kvrow = tid >> 2;
    const int kvch  = (tid & 3) * 2;

    uint4 kpre[2], vpre[2];
    {
        size_t base = (size_t)(b * NT + kvrow) * (3 * ND) + h * NHS;
        #pragma unroll
        for (int i = 0; i < 2; i++) {
            kpre[i] = *(const uint4*)(g_qkv + base + ND + (kvch + i) * 8);
            vpre[i] = *(const uint4*)(g_qkv + base + 2 * ND + (kvch + i) * 8);
        }
    }

    const uint32_t qa_off = (uint32_t)(wrow + (lane & 15)) * 144u + ((lane >> 4) << 4);
    const uint32_t kb_off = (uint32_t)((lane & 7) + ((lane >> 4) << 3)) * 144u
                          + (((lane >> 3) & 1) << 4);
    const uint32_t vb_off = (uint32_t)((lane & 7) + (((lane >> 3) & 1) << 3)) * 144u
                          + ((lane >> 4) << 4);

    for (int jb = 0; jb <= jb_max; jb++) {
        __syncthreads();
        #pragma unroll
        for (int i = 0; i < 2; i++) {
            *(uint4*)&Ks[kvrow * AT_STR + (kvch + i) * 8] = kpre[i];
            *(uint4*)&Vs[kvrow * AT_STR + (kvch + i) * 8] = vpre[i];
        }
        __syncthreads();

        if (jb < jb_max) {
            size_t base = (size_t)(b * NT + (jb + 1) * 64 + kvrow) * (3 * ND) + h * NHS;
            #pragma unroll
            for (int i = 0; i < 2; i++) {
                kpre[i] = *(const uint4*)(g_qkv + base + ND + (kvch + i) * 8);
                vpre[i] = *(const uint4*)(g_qkv + base + 2 * ND + (kvch + i) * 8);
            }
        }

        float sacc[8][4];
        #pragma unroll
        for (int nt = 0; nt < 8; nt++)
            #pragma unroll
            for (int t = 0; t < 4; t++) sacc[nt][t] = 0.f;

        #pragma unroll
        for (int kb = 0; kb < 64; kb += 16) {
            uint32_t aF[4], bF[8][2];
            ldsm_x4(aF[0], aF[1], aF[2], aF[3], sQ + qa_off + kb * 2);
            #pragma unroll
            for (int p = 0; p < 4; p++)
                ldsm_x4(bF[2*p][0], bF[2*p][1], bF[2*p+1][0], bF[2*p+1][1],
                        sK + kb_off + (uint32_t)(p * 16 * 144) + (uint32_t)(kb * 2));
            #pragma unroll
            for (int nt = 0; nt < 8; nt++)
                mma_bf16(sacc[nt], aF, bF[nt]);
        }

        #pragma unroll
        for (int nt = 0; nt < 8; nt++) {
            int gcol = jb * 64 + nt * 8 + (lane & 3) * 2;
            float v0 = sacc[nt][0] * scale;
            float v1 = sacc[nt][1] * scale;
            float v2 = sacc[nt][2] * scale;
            float v3 = sacc[nt][3] * scale;
            if (gcol     > grow0) v0 = -1e30f;
            if (gcol + 1 > grow0) v1 = -1e30f;
            if (gcol     > grow1) v2 = -1e30f;
            if (gcol + 1 > grow1) v3 = -1e30f;
            sacc[nt][0] = v0; sacc[nt][1] = v1;
            sacc[nt][2] = v2; sacc[nt][3] = v3;
        }

        float mx0 = -1e30f, mx1 = -1e30f;
        #pragma unroll
        for (int nt = 0; nt < 8; nt++) {
            mx0 = fmaxf(mx0, fmaxf(sacc[nt][0], sacc[nt][1]));
            mx1 = fmaxf(mx1, fmaxf(sacc[nt][2], sacc[nt][3]));
        }
        mx0 = fmaxf(mx0, __shfl_xor_sync(0xffffffffu, mx0, 1));
        mx0 = fmaxf(mx0, __shfl_xor_sync(0xffffffffu, mx0, 2));
        mx1 = fmaxf(mx1, __shfl_xor_sync(0xffffffffu, mx1, 1));
        mx1 = fmaxf(mx1, __shfl_xor_sync(0xffffffffu, mx1, 2));

        float mn0 = fmaxf(m0, mx0);
        float mn1 = fmaxf(m1, mx1);

        float s0 = 0.f, s1 = 0.f;
        #pragma unroll
        for (int nt = 0; nt < 8; nt++) {
            float p0 = __expf(sacc[nt][0] - mn0);
            float p1 = __expf(sacc[nt][1] - mn0);
            float p2 = __expf(sacc[nt][2] - mn1);
            float p3 = __expf(sacc[nt][3] - mn1);
            sacc[nt][0] = p0; sacc[nt][1] = p1;
            sacc[nt][2] = p2; sacc[nt][3] = p3;
            s0 += p0 + p1;
            s1 += p2 + p3;
        }
        s0 += __shfl_xor_sync(0xffffffffu, s0, 1);
        s0 += __shfl_xor_sync(0xffffffffu, s0, 2);
        s1 += __shfl_xor_sync(0xffffffffu, s1, 1);
        s1 += __shfl_xor_sync(0xffffffffu, s1, 2);

        float al0 = __expf(m0 - mn0);
        float al1 = __expf(m1 - mn1);
        l0 = l0 * al0 + s0;
        l1 = l1 * al1 + s1;
        m0 = mn0; m1 = mn1;

        #pragma unroll
        for (int nt = 0; nt < 8; nt++) {
            oacc[nt][0] *= al0; oacc[nt][1] *= al0;
            oacc[nt][2] *= al1; oacc[nt][3] *= al1;
        }

        uint32_t aP[4][4];
        #pragma unroll
        for (int j = 0; j < 4; j++) {
            aP[j][0] = packbf(sacc[2*j][0],   sacc[2*j][1]);
            aP[j][1] = packbf(sacc[2*j][2],   sacc[2*j][3]);
            aP[j][2] = packbf(sacc[2*j+1][0], sacc[2*j+1][1]);
            aP[j][3] = packbf(sacc[2*j+1][2], sacc[2*j+1][3]);
        }

        #pragma unroll
        for (int j = 0; j < 4; j++) {
            uint32_t bV[8][2];
            #pragma unroll
            for (int p = 0; p < 4; p++)
                ldsm_x4_t(bV[2*p][0], bV[2*p][1], bV[2*p+1][0], bV[2*p+1][1],
                          sV + vb_off + (uint32_t)(j * 16 * 144) + (uint32_t)(p * 32));
            #pragma unroll
            for (int nt = 0; nt < 8; nt++)
                mma_bf16(oacc[nt], aP[j], bV[nt]);
        }
    }

    float li0 = 1.0f / l0, li1 = 1.0f / l1;
    {
        int r_g0 = b * NT + grow0;
        int r_g1 = b * NT + grow1;
        #pragma unroll
        for (int nt = 0; nt < 8; nt++) {
            int c = h * NHS + nt * 8 + (lane & 3) * 2;
            *(uint32_t*)&g_attn[(size_t)r_g0 * ND + c] =
                packbf(oacc[nt][0] * li0, oacc[nt][1] * li0);
            *(uint32_t*)&g_attn[(size_t)r_g1 * ND + c] =
                packbf(oacc[nt][2] * li1, oacc[nt][3] * li1);
        }
    }
}

// ---------------- launch ----------------
extern "C" void kernel_launch(void* const* d_in, const int* in_sizes, int n_in,
                              void* d_out, int out_size)
{
    const float* x  = (const float*)d_in[0];
    const float* Wq = (const float*)d_in[1];
    const float* Wk = (const float*)d_in[2];
    const float* Wv = (const float*)d_in[3];
    const float* Wo = (const float*)d_in[4];
    const float* bo = (const float*)d_in[5];
    const float* W1 = (const float*)d_in[6];
    const float* b1 = (const float*)d_in[7];
    const float* W2 = (const float*)d_in[8];
    const float* b2 = (const float*)d_in[9];
    const float* g1 = (const float*)d_in[10];
    const float* g2 = (const float*)d_in[11];
    float* out = (float*)d_out;

    cudaFuncSetAttribute(attn_mma_kernel, cudaFuncAttributeMaxDynamicSharedMemorySize, ATT_SMEM);
    cudaFuncSetAttribute(gemm_qkv_kernel,  cudaFuncAttributeMaxDynamicSharedMemorySize, GEMM_SMEM);
    cudaFuncSetAttribute(gemm_o_kernel,    cudaFuncAttributeMaxDynamicSharedMemorySize, GEMM_SMEM);
    cudaFuncSetAttribute(gemm_ffn1_kernel, cudaFuncAttributeMaxDynamicSharedMemorySize, GEMM_SMEM);
    cudaFuncSetAttribute(gemm_ffn2_kernel, cudaFuncAttributeMaxDynamicSharedMemorySize, GEMM_SMEM);

    pack_wqkv_kernel<<<(3 * ND * ND + 255) / 256, 256>>>(Wq, Wk, Wv);
    round_weights_kernel<<<(W1_N + 255) / 256, 256>>>(Wo, W1, W2);
    rmsnorm1_kernel<<<NBT, 256>>>(x, g1);
    gemm_qkv_kernel<<<dim3(3 * ND / 128, NBT / 128), 256, GEMM_SMEM>>>();
    attn_mma_kernel<<<dim3(NT / 128, NH, NB), 256, ATT_SMEM>>>();
    gemm_o_kernel<<<dim3(ND / 128, NBT / 128), 256, GEMM_SMEM>>>(bo, x);
    rmsnorm2_kernel<<<NBT, 256>>>(g2);
    gemm_ffn1_kernel<<<dim3(NFF / 128, NBT / 128), 256, GEMM_SMEM>>>(b1);
    gemm_ffn2_kernel<<<dim3(ND / 128, NBT / 128), 256, GEMM_SMEM>>>(b2, out);
}